// round 1
// baseline (speedup 1.0000x reference)
#include <cuda_runtime.h>
#include <math.h>
#include <stdint.h>

// Problem constants
#define BB   2
#define HH   128
#define WW   256
#define CCH  768
#define KWV  65          // kept W frequencies: 0..64
#define NB   8
#define BS   96
#define NPOS (BB*HH*KWV) // 16640 positions in the truncated slab
#define SLABN (NPOS*CCH) // 12,779,520 elements

// ---------------- scratch (device globals; no allocation) ----------------
__device__ float2 g_A[SLABN];   // ~102 MB
__device__ float2 g_B[SLABN];   // ~102 MB
__device__ float2 g_tw256[256];
__device__ float2 g_tw768[768];
__device__ float2 g_tw128[128];
__device__ float  g_W1p[NB*BS*BS], g_W1m[NB*BS*BS];
__device__ float  g_W2p[NB*BS*BS], g_W2m[NB*BS*BS];
__device__ float  g_b1k[NB*BS], g_b1n[NB*BS], g_b2k[NB*BS], g_b2n[NB*BS];

__device__ __forceinline__ void cmadd(float2& acc, float2 z, float2 t) {
    acc.x = fmaf(z.x, t.x, fmaf(-z.y, t.y, acc.x));
    acc.y = fmaf(z.x, t.y, fmaf( z.y, t.x, acc.y));
}

// ---------------- prep: twiddles + combined weights ----------------
__global__ void kPrep(const float* __restrict__ w1, const float* __restrict__ b1,
                      const float* __restrict__ w2, const float* __restrict__ b2)
{
    int t = blockIdx.x * blockDim.x + threadIdx.x;
    int stride = gridDim.x * blockDim.x;
    const double TWO_PI = 6.283185307179586476925286766559;
    for (int j = t; j < 768; j += stride) {
        double s, c;
        sincos(-TWO_PI * (double)j / 768.0, &s, &c);
        g_tw768[j] = make_float2((float)c, (float)s);
        if (j < 256) {
            sincos(-TWO_PI * (double)j / 256.0, &s, &c);
            g_tw256[j] = make_float2((float)c, (float)s);
        }
        if (j < 128) {
            sincos(-TWO_PI * (double)j / 128.0, &s, &c);
            g_tw128[j] = make_float2((float)c, (float)s);
        }
    }
    for (int i = t; i < NB*BS*BS; i += stride) {
        float a0 = w1[i], a1 = w1[NB*BS*BS + i];
        g_W1p[i] = a0 + a1; g_W1m[i] = a0 - a1;
        float c0 = w2[i], c1 = w2[NB*BS*BS + i];
        g_W2p[i] = c0 + c1; g_W2m[i] = c0 - c1;
    }
    for (int i = t; i < NB*BS; i += stride) {
        g_b1k[i] = b1[i]; g_b1n[i] = b1[NB*BS + i];
        g_b2k[i] = b2[i]; g_b2n[i] = b2[NB*BS + i];
    }
}

// ---------------- forward W-FFT (256 = 16x16), pruned to kw<65 ----------------
// x[b][h][w][c] -> g_A[b][h][kw][c]
__global__ void kF1(const float* __restrict__ x)
{
    __shared__ float  Xs[256][16];
    __shared__ float2 Ys[256][16];   // [(k1<<4)+n2][c]
    int bh = blockIdx.x;
    int c0 = blockIdx.y * 16;
    const float* xp = x + (size_t)bh * (WW*CCH) + c0;
    for (int e = threadIdx.x; e < 256*16; e += 256) {
        int w = e >> 4, c = e & 15;
        Xs[w][c] = xp[(size_t)w * CCH + c];
    }
    __syncthreads();
    // step 1: Y[k1][n2] = sum_{n1} x[16n1+n2] * e^{-2pi i k1(16n1+n2)/256}
    for (int e = threadIdx.x; e < 4096; e += 256) {
        int c = e & 15, n2 = (e >> 4) & 15, k1 = e >> 8;
        float re = 0.f, im = 0.f;
        int idx = (k1 * n2) & 255;
        int step = (k1 * 16) & 255;
        int w = n2;
        #pragma unroll
        for (int n1 = 0; n1 < 16; n1++) {
            float2 tw = __ldg(&g_tw256[idx]);
            float v = Xs[w][c];
            re = fmaf(v, tw.x, re);
            im = fmaf(v, tw.y, im);
            w += 16; idx = (idx + step) & 255;
        }
        Ys[(k1<<4) + n2][c] = make_float2(re, im);
    }
    __syncthreads();
    // step 2: X[k1+16k2] = sum_{n2} Y[k1][n2] * e^{-2pi i n2 k2/16}, keep k<65
    for (int e = threadIdx.x; e < KWV*16; e += 256) {
        int c = e & 15, kw = e >> 4;
        int k1 = kw & 15, k2 = kw >> 4;
        float2 acc = make_float2(0.f, 0.f);
        int idx = 0, step = (k2 * 16) & 255;
        #pragma unroll
        for (int n2 = 0; n2 < 16; n2++) {
            float2 tw = __ldg(&g_tw256[idx]);
            cmadd(acc, Ys[(k1<<4) + n2][c], tw);
            idx = (idx + step) & 255;
        }
        g_A[((size_t)bh*KWV + kw)*CCH + c0 + c] = acc;
    }
}

// ---------------- C-FFT (768 = 32x24) on slab: A (cplx or real) -> B ----------------
template<int RIN>
__global__ void kFC()
{
    __shared__ float2 Zs[768];
    __shared__ float2 Ys[768];   // [k1*24+n2]
    size_t row = blockIdx.x;
    if (RIN) {
        const float* sp = (const float*)g_A;
        for (int e = threadIdx.x; e < 768; e += 256)
            Zs[e] = make_float2(sp[row*768 + e], 0.f);
    } else {
        for (int e = threadIdx.x; e < 768; e += 256)
            Zs[e] = g_A[row*768 + e];
    }
    __syncthreads();
    for (int e = threadIdx.x; e < 768; e += 256) {
        int k1 = e / 24, n2 = e - 24*k1;
        float2 acc = make_float2(0.f, 0.f);
        int idx = k1 * n2;        // < 768
        int step = k1 * 24;       // < 768
        #pragma unroll 8
        for (int n1 = 0; n1 < 32; n1++) {
            float2 tw = __ldg(&g_tw768[idx]);
            cmadd(acc, Zs[24*n1 + n2], tw);
            idx += step; if (idx >= 768) idx -= 768;
        }
        Ys[e] = acc;
    }
    __syncthreads();
    for (int e = threadIdx.x; e < 768; e += 256) {
        int k1 = e & 31, k2 = e >> 5;
        float2 acc = make_float2(0.f, 0.f);
        int idx = 0, step = 32 * k2;   // < 768
        #pragma unroll 8
        for (int n2 = 0; n2 < 24; n2++) {
            float2 tw = __ldg(&g_tw768[idx]);
            cmadd(acc, Ys[k1*24 + n2], tw);
            idx += step; if (idx >= 768) idx -= 768;
        }
        g_B[row*768 + e] = acc;
    }
}

// ---------------- H-FFT (128 = 16x8) + B-FFT (length 2) : B -> A ----------------
__global__ void kFHB()
{
    __shared__ float2 Zs[2][128][8];
    __shared__ float2 Ys[2][128][8];  // [bb][(k1<<3)+n2][c]
    int kw = blockIdx.x;
    int c0 = blockIdx.y * 8;
    for (int e = threadIdx.x; e < 2048; e += 256) {
        int c = e & 7, h = (e >> 3) & 127, b = e >> 10;
        Zs[b][h][c] = g_B[(((size_t)b*HH + h)*KWV + kw)*CCH + c0 + c];
    }
    __syncthreads();
    for (int e = threadIdx.x; e < 2048; e += 256) {
        int c = e & 7, n2 = (e >> 3) & 7, k1 = (e >> 6) & 15, bb = e >> 10;
        float2 acc = make_float2(0.f, 0.f);
        int idx = (k1 * n2) & 127, step = (k1 * 8) & 127;
        #pragma unroll
        for (int n1 = 0; n1 < 16; n1++) {
            int h = (n1 << 3) + n2;
            float2 z0 = Zs[0][h][c], z1 = Zs[1][h][c];
            float2 u = bb ? make_float2(z0.x - z1.x, z0.y - z1.y)
                          : make_float2(z0.x + z1.x, z0.y + z1.y);
            float2 tw = __ldg(&g_tw128[idx]);
            cmadd(acc, u, tw);
            idx = (idx + step) & 127;
        }
        Ys[bb][(k1<<3) + n2][c] = acc;
    }
    __syncthreads();
    for (int e = threadIdx.x; e < 2048; e += 256) {
        int c = e & 7, k = (e >> 3) & 127, bb = e >> 10;
        int k1 = k & 15, k2 = k >> 4;
        float2 acc = make_float2(0.f, 0.f);
        int idx = 0, step = (k2 * 16) & 127;
        #pragma unroll
        for (int n2 = 0; n2 < 8; n2++) {
            float2 tw = __ldg(&g_tw128[idx]);
            cmadd(acc, Ys[bb][(k1<<3) + n2][c], tw);
            idx = (idx + step) & 127;
        }
        g_A[(((size_t)bb*HH + k)*KWV + kw)*CCH + c0 + c] = acc;
    }
}

// ---------------- MLP layer 1: A (spectral slab) + x (gather) -> o1k/o1n in B ----------------
__global__ void kMLP1(const float* __restrict__ x)
{
    __shared__ float av [32][96];
    __shared__ float anv[32][96];
    int pt = blockIdx.x, n = blockIdx.y;
    int o = threadIdx.x;      // 0..95
    int p0 = pt * 32;
    for (int p = 0; p < 32; p++) {
        int pg = p0 + p;
        int b  = pg / (HH*KWV);
        int r  = pg - b*(HH*KWV);
        int h  = r / KWV;
        int kw = r - h*KWV;
        float2 z = g_A[(size_t)pg*CCH + n*BS + o];
        av[p][o] = z.x + z.y;                       // DHT = Re + Im
        int hn = (HH - h) & (HH - 1);
        int wn = (WW - kw) & (WW - 1);
        anv[p][o] = x[(((size_t)b*HH + hn)*WW + wn)*CCH + n*BS + o];
    }
    __syncthreads();
    float accK[32], accN[32];
    #pragma unroll
    for (int p = 0; p < 32; p++) { accK[p] = 0.f; accN[p] = 0.f; }
    const float* Wp = g_W1p + n*BS*BS + o;
    const float* Wm = g_W1m + n*BS*BS + o;
    for (int i = 0; i < 96; i++) {
        float wp = __ldg(Wp + i*BS);
        float wm = __ldg(Wm + i*BS);
        #pragma unroll
        for (int p = 0; p < 32; p++) {
            float a = av[p][i], an = anv[p][i];
            accK[p] = fmaf(a,  wp, fmaf(an, wm, accK[p]));
            accN[p] = fmaf(an, wp, fmaf(a,  wm, accN[p]));
        }
    }
    float bk = g_b1k[n*BS + o], bn = g_b1n[n*BS + o];
    float* o1k = (float*)g_B;
    float* o1n = o1k + (size_t)SLABN;
    for (int p = 0; p < 32; p++) {
        size_t a = (size_t)(p0 + p)*CCH + n*BS + o;
        o1k[a] = fmaxf(fmaf(0.5f, accK[p], bk), 0.f);
        o1n[a] = fmaxf(fmaf(0.5f, accN[p], bn), 0.f);
    }
}

// ---------------- MLP layer 2 + soft-threshold: B -> s (real) in A ----------------
__global__ void kMLP2()
{
    __shared__ float uk[32][96];
    __shared__ float un[32][96];
    __shared__ float ok[32][96];
    int pt = blockIdx.x, n = blockIdx.y;
    int o = threadIdx.x;
    int p0 = pt * 32;
    const float* o1k = (const float*)g_B;
    const float* o1n = o1k + (size_t)SLABN;
    for (int p = 0; p < 32; p++) {
        size_t a = (size_t)(p0 + p)*CCH + n*BS + o;
        uk[p][o] = o1k[a];
        un[p][o] = o1n[a];
    }
    __syncthreads();
    const float* Wp = g_W2p + n*BS*BS + o;
    const float* Wm = g_W2m + n*BS*BS + o;
    float acc[32];
    #pragma unroll
    for (int p = 0; p < 32; p++) acc[p] = 0.f;
    for (int i = 0; i < 96; i++) {
        float wp = __ldg(Wp + i*BS);
        float wm = __ldg(Wm + i*BS);
        #pragma unroll
        for (int p = 0; p < 32; p++)
            acc[p] = fmaf(uk[p][i], wp, fmaf(un[p][i], wm, acc[p]));
    }
    float b2k = g_b2k[n*BS + o];
    #pragma unroll
    for (int p = 0; p < 32; p++) ok[p][o] = fmaf(0.5f, acc[p], b2k);
    __syncthreads();
    #pragma unroll
    for (int p = 0; p < 32; p++) acc[p] = 0.f;
    for (int i = 0; i < 96; i++) {
        float wp = __ldg(Wp + i*BS);
        float wm = __ldg(Wm + i*BS);
        #pragma unroll
        for (int p = 0; p < 32; p++)
            acc[p] = fmaf(un[p][i], wp, fmaf(ok[p][i], wm, acc[p]));  // o2_nk uses o2_k!
    }
    float b2n = g_b2n[n*BS + o];
    float* sb = (float*)g_A;
    for (int p = 0; p < 32; p++) {
        float o2n = fmaf(0.5f, acc[p], b2n);
        float t = ok[p][o] + o2n;
        float s = copysignf(fmaxf(fabsf(t) - 0.01f, 0.f), t);
        sb[(size_t)(p0 + p)*CCH + n*BS + o] = s;
    }
}

// ---------------- inverse W-FFT (65 nonzero inputs -> 256 outputs) + scale + residual ----------------
__global__ void kIW(const float* __restrict__ x, float* __restrict__ out)
{
    __shared__ float2 Ys[16][16][16];   // [k1][n2][c]
    int bh = blockIdx.x;
    int c0 = blockIdx.y * 16;
    const float2* zp = g_A + (size_t)bh*KWV*CCH + c0;
    for (int e = threadIdx.x; e < 4096; e += 256) {
        int c = e & 15, n2 = (e >> 4) & 15, k1 = e >> 8;
        float2 acc = make_float2(0.f, 0.f);
        int idx = (k1 * n2) & 255, step = (k1 * 16) & 255;
        int nmax = (n2 == 0) ? 5 : 4;    // w = 16*n1 + n2 must be < 65
        for (int n1 = 0; n1 < nmax; n1++) {
            int w = (n1 << 4) + n2;
            float2 z = __ldg(&zp[(size_t)w*CCH + c]);
            float2 tw = __ldg(&g_tw256[idx]);
            cmadd(acc, z, tw);
            idx = (idx + step) & 255;
        }
        Ys[k1][n2][c] = acc;
    }
    __syncthreads();
    const float invN = 1.0f / 50331648.0f;
    for (int e = threadIdx.x; e < 4096; e += 256) {
        int c = e & 15, k = e >> 4;
        int k1 = k & 15, k2 = k >> 4;
        float2 acc = make_float2(0.f, 0.f);
        int idx = 0, step = (k2 * 16) & 255;
        #pragma unroll
        for (int n2 = 0; n2 < 16; n2++) {
            float2 tw = __ldg(&g_tw256[idx]);
            cmadd(acc, Ys[k1][n2][c], tw);
            idx = (idx + step) & 255;
        }
        size_t a = ((size_t)bh*WW + k)*CCH + c0 + c;
        out[a] = fmaf(acc.x + acc.y, invN, x[a]);
    }
}

// ---------------- launch ----------------
extern "C" void kernel_launch(void* const* d_in, const int* in_sizes, int n_in,
                              void* d_out, int out_size)
{
    const float* x  = (const float*)d_in[0];
    const float* w1 = (const float*)d_in[1];
    const float* b1 = (const float*)d_in[2];
    const float* w2 = (const float*)d_in[3];
    const float* b2 = (const float*)d_in[4];
    float* out = (float*)d_out;

    kPrep<<<96, 256>>>(w1, b1, w2, b2);
    kF1 <<<dim3(BB*HH, CCH/16), 256>>>(x);        // W-FFT (pruned) : x -> A
    kFC<0><<<NPOS, 256>>>();                      // C-FFT          : A -> B
    kFHB<<<dim3(KWV, CCH/8), 256>>>();            // H+B FFT        : B -> A
    kMLP1<<<dim3(NPOS/32, NB), 96>>>(x);          // layer1         : A,x -> B
    kMLP2<<<dim3(NPOS/32, NB), 96>>>();           // layer2+thresh  : B -> A (real s)
    kFC<1><<<NPOS, 256>>>();                      // C-FFT (real in): A -> B
    kFHB<<<dim3(KWV, CCH/8), 256>>>();            // H+B FFT        : B -> A
    kIW <<<dim3(BB*HH, CCH/16), 256>>>(x, out);   // W-FFT + scale + residual
}

// round 2
// speedup vs baseline: 1.0009x; 1.0009x over previous
#include <cuda_runtime.h>
#include <math.h>
#include <stdint.h>

// Problem constants
#define BB   2
#define HH   128
#define WW   256
#define CCH  768
#define KWV  65          // kept W frequencies: 0..64
#define NB   8
#define BS   96
#define NPOS (BB*HH*KWV) // 16640 positions in the truncated slab
#define SLABN (NPOS*CCH) // 12,779,520 elements

// ---------------- scratch (device globals; no allocation) ----------------
__device__ float2 g_A[SLABN];   // ~102 MB
__device__ float2 g_B[SLABN];   // ~102 MB
__device__ float2 g_tw256[256];
__device__ float2 g_tw768[768];
__device__ float2 g_tw128[128];
__device__ float  g_W1p[NB*BS*BS], g_W1m[NB*BS*BS];
__device__ float  g_W2p[NB*BS*BS], g_W2m[NB*BS*BS];
__device__ float  g_b1k[NB*BS], g_b1n[NB*BS], g_b2k[NB*BS], g_b2n[NB*BS];

__device__ __forceinline__ void cmadd(float2& acc, float2 z, float2 t) {
    acc.x = fmaf(z.x, t.x, fmaf(-z.y, t.y, acc.x));
    acc.y = fmaf(z.x, t.y, fmaf( z.y, t.x, acc.y));
}

// ---------------- prep: twiddles + combined weights ----------------
__global__ void kPrep(const float* __restrict__ w1, const float* __restrict__ b1,
                      const float* __restrict__ w2, const float* __restrict__ b2)
{
    int t = blockIdx.x * blockDim.x + threadIdx.x;
    int stride = gridDim.x * blockDim.x;
    const double TWO_PI = 6.283185307179586476925286766559;
    for (int j = t; j < 768; j += stride) {
        double s, c;
        sincos(-TWO_PI * (double)j / 768.0, &s, &c);
        g_tw768[j] = make_float2((float)c, (float)s);
        if (j < 256) {
            sincos(-TWO_PI * (double)j / 256.0, &s, &c);
            g_tw256[j] = make_float2((float)c, (float)s);
        }
        if (j < 128) {
            sincos(-TWO_PI * (double)j / 128.0, &s, &c);
            g_tw128[j] = make_float2((float)c, (float)s);
        }
    }
    for (int i = t; i < NB*BS*BS; i += stride) {
        float a0 = w1[i], a1 = w1[NB*BS*BS + i];
        g_W1p[i] = a0 + a1; g_W1m[i] = a0 - a1;
        float c0 = w2[i], c1 = w2[NB*BS*BS + i];
        g_W2p[i] = c0 + c1; g_W2m[i] = c0 - c1;
    }
    for (int i = t; i < NB*BS; i += stride) {
        g_b1k[i] = b1[i]; g_b1n[i] = b1[NB*BS + i];
        g_b2k[i] = b2[i]; g_b2n[i] = b2[NB*BS + i];
    }
}

// ---------------- forward W-FFT (256 = 16x16), pruned to kw<65 ----------------
// x[b][h][w][c] -> g_A[b][h][kw][c]
__global__ void kF1(const float* __restrict__ x)
{
    __shared__ float  Xs[256][16];
    __shared__ float2 Ys[256][16];   // [(k1<<4)+n2][c]
    int bh = blockIdx.x;
    int c0 = blockIdx.y * 16;
    const float* xp = x + (size_t)bh * (WW*CCH) + c0;
    for (int e = threadIdx.x; e < 256*16; e += 256) {
        int w = e >> 4, c = e & 15;
        Xs[w][c] = xp[(size_t)w * CCH + c];
    }
    __syncthreads();
    // step 1: Y[k1][n2] = sum_{n1} x[16n1+n2] * e^{-2pi i k1(16n1+n2)/256}
    for (int e = threadIdx.x; e < 4096; e += 256) {
        int c = e & 15, n2 = (e >> 4) & 15, k1 = e >> 8;
        float re = 0.f, im = 0.f;
        int idx = (k1 * n2) & 255;
        int step = (k1 * 16) & 255;
        int w = n2;
        #pragma unroll
        for (int n1 = 0; n1 < 16; n1++) {
            float2 tw = __ldg(&g_tw256[idx]);
            float v = Xs[w][c];
            re = fmaf(v, tw.x, re);
            im = fmaf(v, tw.y, im);
            w += 16; idx = (idx + step) & 255;
        }
        Ys[(k1<<4) + n2][c] = make_float2(re, im);
    }
    __syncthreads();
    // step 2: X[k1+16k2] = sum_{n2} Y[k1][n2] * e^{-2pi i n2 k2/16}, keep k<65
    for (int e = threadIdx.x; e < KWV*16; e += 256) {
        int c = e & 15, kw = e >> 4;
        int k1 = kw & 15, k2 = kw >> 4;
        float2 acc = make_float2(0.f, 0.f);
        int idx = 0, step = (k2 * 16) & 255;
        #pragma unroll
        for (int n2 = 0; n2 < 16; n2++) {
            float2 tw = __ldg(&g_tw256[idx]);
            cmadd(acc, Ys[(k1<<4) + n2][c], tw);
            idx = (idx + step) & 255;
        }
        g_A[((size_t)bh*KWV + kw)*CCH + c0 + c] = acc;
    }
}

// ---------------- C-FFT (768 = 32x24) on slab: A (cplx or real) -> B ----------------
template<int RIN>
__global__ void kFC()
{
    __shared__ float2 Zs[768];
    __shared__ float2 Ys[768];   // [k1*24+n2]
    size_t row = blockIdx.x;
    if (RIN) {
        const float* sp = (const float*)g_A;
        for (int e = threadIdx.x; e < 768; e += 256)
            Zs[e] = make_float2(sp[row*768 + e], 0.f);
    } else {
        for (int e = threadIdx.x; e < 768; e += 256)
            Zs[e] = g_A[row*768 + e];
    }
    __syncthreads();
    for (int e = threadIdx.x; e < 768; e += 256) {
        int k1 = e / 24, n2 = e - 24*k1;
        float2 acc = make_float2(0.f, 0.f);
        int idx = k1 * n2;        // < 768
        int step = k1 * 24;       // < 768
        #pragma unroll 8
        for (int n1 = 0; n1 < 32; n1++) {
            float2 tw = __ldg(&g_tw768[idx]);
            cmadd(acc, Zs[24*n1 + n2], tw);
            idx += step; if (idx >= 768) idx -= 768;
        }
        Ys[e] = acc;
    }
    __syncthreads();
    for (int e = threadIdx.x; e < 768; e += 256) {
        int k1 = e & 31, k2 = e >> 5;
        float2 acc = make_float2(0.f, 0.f);
        int idx = 0, step = 32 * k2;   // < 768
        #pragma unroll 8
        for (int n2 = 0; n2 < 24; n2++) {
            float2 tw = __ldg(&g_tw768[idx]);
            cmadd(acc, Ys[k1*24 + n2], tw);
            idx += step; if (idx >= 768) idx -= 768;
        }
        g_B[row*768 + e] = acc;
    }
}

// ---------------- H-FFT (128 = 16x8) + B-FFT (length 2) : B -> A ----------------
__global__ void kFHB()
{
    __shared__ float2 Zs[2][128][8];
    __shared__ float2 Ys[2][128][8];  // [bb][(k1<<3)+n2][c]
    int kw = blockIdx.x;
    int c0 = blockIdx.y * 8;
    for (int e = threadIdx.x; e < 2048; e += 256) {
        int c = e & 7, h = (e >> 3) & 127, b = e >> 10;
        Zs[b][h][c] = g_B[(((size_t)b*HH + h)*KWV + kw)*CCH + c0 + c];
    }
    __syncthreads();
    for (int e = threadIdx.x; e < 2048; e += 256) {
        int c = e & 7, n2 = (e >> 3) & 7, k1 = (e >> 6) & 15, bb = e >> 10;
        float2 acc = make_float2(0.f, 0.f);
        int idx = (k1 * n2) & 127, step = (k1 * 8) & 127;
        #pragma unroll
        for (int n1 = 0; n1 < 16; n1++) {
            int h = (n1 << 3) + n2;
            float2 z0 = Zs[0][h][c], z1 = Zs[1][h][c];
            float2 u = bb ? make_float2(z0.x - z1.x, z0.y - z1.y)
                          : make_float2(z0.x + z1.x, z0.y + z1.y);
            float2 tw = __ldg(&g_tw128[idx]);
            cmadd(acc, u, tw);
            idx = (idx + step) & 127;
        }
        Ys[bb][(k1<<3) + n2][c] = acc;
    }
    __syncthreads();
    for (int e = threadIdx.x; e < 2048; e += 256) {
        int c = e & 7, k = (e >> 3) & 127, bb = e >> 10;
        int k1 = k & 15, k2 = k >> 4;
        float2 acc = make_float2(0.f, 0.f);
        int idx = 0, step = (k2 * 16) & 127;
        #pragma unroll
        for (int n2 = 0; n2 < 8; n2++) {
            float2 tw = __ldg(&g_tw128[idx]);
            cmadd(acc, Ys[bb][(k1<<3) + n2][c], tw);
            idx = (idx + step) & 127;
        }
        g_A[(((size_t)bb*HH + k)*KWV + kw)*CCH + c0 + c] = acc;
    }
}

// ---------------- MLP layer 1: A (spectral slab) + x (gather) -> o1k/o1n in B ----------------
__global__ void kMLP1(const float* __restrict__ x)
{
    __shared__ float av [32][96];
    __shared__ float anv[32][96];
    int pt = blockIdx.x, n = blockIdx.y;
    int o = threadIdx.x;      // 0..95
    int p0 = pt * 32;
    for (int p = 0; p < 32; p++) {
        int pg = p0 + p;
        int b  = pg / (HH*KWV);
        int r  = pg - b*(HH*KWV);
        int h  = r / KWV;
        int kw = r - h*KWV;
        float2 z = g_A[(size_t)pg*CCH + n*BS + o];
        av[p][o] = z.x + z.y;                       // DHT = Re + Im
        int hn = (HH - h) & (HH - 1);
        int wn = (WW - kw) & (WW - 1);
        anv[p][o] = x[(((size_t)b*HH + hn)*WW + wn)*CCH + n*BS + o];
    }
    __syncthreads();
    float accK[32], accN[32];
    #pragma unroll
    for (int p = 0; p < 32; p++) { accK[p] = 0.f; accN[p] = 0.f; }
    const float* Wp = g_W1p + n*BS*BS + o;
    const float* Wm = g_W1m + n*BS*BS + o;
    for (int i = 0; i < 96; i++) {
        float wp = __ldg(Wp + i*BS);
        float wm = __ldg(Wm + i*BS);
        #pragma unroll
        for (int p = 0; p < 32; p++) {
            float a = av[p][i], an = anv[p][i];
            accK[p] = fmaf(a,  wp, fmaf(an, wm, accK[p]));
            accN[p] = fmaf(an, wp, fmaf(a,  wm, accN[p]));
        }
    }
    float bk = g_b1k[n*BS + o], bn = g_b1n[n*BS + o];
    float* o1k = (float*)g_B;
    float* o1n = o1k + (size_t)SLABN;
    for (int p = 0; p < 32; p++) {
        size_t a = (size_t)(p0 + p)*CCH + n*BS + o;
        o1k[a] = fmaxf(fmaf(0.5f, accK[p], bk), 0.f);
        o1n[a] = fmaxf(fmaf(0.5f, accN[p], bn), 0.f);
    }
}

// ---------------- MLP layer 2 + soft-threshold: B -> s (real) in A ----------------
__global__ void kMLP2()
{
    __shared__ float uk[32][96];
    __shared__ float un[32][96];
    __shared__ float ok[32][96];
    int pt = blockIdx.x, n = blockIdx.y;
    int o = threadIdx.x;
    int p0 = pt * 32;
    const float* o1k = (const float*)g_B;
    const float* o1n = o1k + (size_t)SLABN;
    for (int p = 0; p < 32; p++) {
        size_t a = (size_t)(p0 + p)*CCH + n*BS + o;
        uk[p][o] = o1k[a];
        un[p][o] = o1n[a];
    }
    __syncthreads();
    const float* Wp = g_W2p + n*BS*BS + o;
    const float* Wm = g_W2m + n*BS*BS + o;
    float acc[32];
    #pragma unroll
    for (int p = 0; p < 32; p++) acc[p] = 0.f;
    for (int i = 0; i < 96; i++) {
        float wp = __ldg(Wp + i*BS);
        float wm = __ldg(Wm + i*BS);
        #pragma unroll
        for (int p = 0; p < 32; p++)
            acc[p] = fmaf(uk[p][i], wp, fmaf(un[p][i], wm, acc[p]));
    }
    float b2k = g_b2k[n*BS + o];
    #pragma unroll
    for (int p = 0; p < 32; p++) ok[p][o] = fmaf(0.5f, acc[p], b2k);
    __syncthreads();
    #pragma unroll
    for (int p = 0; p < 32; p++) acc[p] = 0.f;
    for (int i = 0; i < 96; i++) {
        float wp = __ldg(Wp + i*BS);
        float wm = __ldg(Wm + i*BS);
        #pragma unroll
        for (int p = 0; p < 32; p++)
            acc[p] = fmaf(un[p][i], wp, fmaf(ok[p][i], wm, acc[p]));  // o2_nk uses o2_k!
    }
    float b2n = g_b2n[n*BS + o];
    float* sb = (float*)g_A;
    for (int p = 0; p < 32; p++) {
        float o2n = fmaf(0.5f, acc[p], b2n);
        float t = ok[p][o] + o2n;
        float s = copysignf(fmaxf(fabsf(t) - 0.01f, 0.f), t);
        sb[(size_t)(p0 + p)*CCH + n*BS + o] = s;
    }
}

// ---------------- inverse W-FFT (65 nonzero inputs -> 256 outputs) + scale + residual ----------------
__global__ void kIW(const float* __restrict__ x, float* __restrict__ out)
{
    __shared__ float2 Ys[16][16][16];   // [k1][n2][c]
    int bh = blockIdx.x;
    int c0 = blockIdx.y * 16;
    const float2* zp = g_A + (size_t)bh*KWV*CCH + c0;
    for (int e = threadIdx.x; e < 4096; e += 256) {
        int c = e & 15, n2 = (e >> 4) & 15, k1 = e >> 8;
        float2 acc = make_float2(0.f, 0.f);
        int idx = (k1 * n2) & 255, step = (k1 * 16) & 255;
        int nmax = (n2 == 0) ? 5 : 4;    // w = 16*n1 + n2 must be < 65
        for (int n1 = 0; n1 < nmax; n1++) {
            int w = (n1 << 4) + n2;
            float2 z = __ldg(&zp[(size_t)w*CCH + c]);
            float2 tw = __ldg(&g_tw256[idx]);
            cmadd(acc, z, tw);
            idx = (idx + step) & 255;
        }
        Ys[k1][n2][c] = acc;
    }
    __syncthreads();
    const float invN = 1.0f / 50331648.0f;
    for (int e = threadIdx.x; e < 4096; e += 256) {
        int c = e & 15, k = e >> 4;
        int k1 = k & 15, k2 = k >> 4;
        float2 acc = make_float2(0.f, 0.f);
        int idx = 0, step = (k2 * 16) & 255;
        #pragma unroll
        for (int n2 = 0; n2 < 16; n2++) {
            float2 tw = __ldg(&g_tw256[idx]);
            cmadd(acc, Ys[k1][n2][c], tw);
            idx = (idx + step) & 255;
        }
        size_t a = ((size_t)bh*WW + k)*CCH + c0 + c;
        out[a] = fmaf(acc.x + acc.y, invN, x[a]);
    }
}

// ---------------- launch ----------------
extern "C" void kernel_launch(void* const* d_in, const int* in_sizes, int n_in,
                              void* d_out, int out_size)
{
    const float* x  = (const float*)d_in[0];
    const float* w1 = (const float*)d_in[1];
    const float* b1 = (const float*)d_in[2];
    const float* w2 = (const float*)d_in[3];
    const float* b2 = (const float*)d_in[4];
    float* out = (float*)d_out;

    kPrep<<<96, 256>>>(w1, b1, w2, b2);
    kF1 <<<dim3(BB*HH, CCH/16), 256>>>(x);        // W-FFT (pruned) : x -> A
    kFC<0><<<NPOS, 256>>>();                      // C-FFT          : A -> B
    kFHB<<<dim3(KWV, CCH/8), 256>>>();            // H+B FFT        : B -> A
    kMLP1<<<dim3(NPOS/32, NB), 96>>>(x);          // layer1         : A,x -> B
    kMLP2<<<dim3(NPOS/32, NB), 96>>>();           // layer2+thresh  : B -> A (real s)
    kFC<1><<<NPOS, 256>>>();                      // C-FFT (real in): A -> B
    kFHB<<<dim3(KWV, CCH/8), 256>>>();            // H+B FFT        : B -> A
    kIW <<<dim3(BB*HH, CCH/16), 256>>>(x, out);   // W-FFT + scale + residual
}

// round 3
// speedup vs baseline: 1.1978x; 1.1967x over previous
#include <cuda_runtime.h>
#include <math.h>
#include <stdint.h>

#define BB 2
#define HH 128
#define WW 256
#define CCH 768
#define KWV 65
#define NB 8
#define BS 96
#define NPOS (BB*HH*KWV)
#define SLABN (NPOS*CCH)

__device__ float2 g_A[SLABN];
__device__ float2 g_B[SLABN];
__device__ float2 g_tw256[256];
__device__ float2 g_tw768[768];
__device__ float2 g_tw128[128];

__device__ constexpr float W16C[16] = {
  1.0f, 0.92387953251128674f, 0.70710678118654752f, 0.38268343236508977f,
  0.0f,-0.38268343236508977f,-0.70710678118654752f,-0.92387953251128674f,
 -1.0f,-0.92387953251128674f,-0.70710678118654752f,-0.38268343236508977f,
  0.0f, 0.38268343236508977f, 0.70710678118654752f, 0.92387953251128674f};
__device__ constexpr float W16S[16] = {
  0.0f,-0.38268343236508977f,-0.70710678118654752f,-0.92387953251128674f,
 -1.0f,-0.92387953251128674f,-0.70710678118654752f,-0.38268343236508977f,
  0.0f, 0.38268343236508977f, 0.70710678118654752f, 0.92387953251128674f,
  1.0f, 0.92387953251128674f, 0.70710678118654752f, 0.38268343236508977f};

__device__ __forceinline__ void cmadd(float2& acc, float2 z, float2 t) {
    acc.x = fmaf(z.x, t.x, fmaf(-z.y, t.y, acc.x));
    acc.y = fmaf(z.x, t.y, fmaf( z.y, t.x, acc.y));
}
__device__ __forceinline__ void cmaddc(float2& acc, float2 z, float C, float S) {
    acc.x = fmaf(z.x, C, fmaf(-z.y, S, acc.x));
    acc.y = fmaf(z.x, S, fmaf( z.y, C, acc.y));
}
__device__ __forceinline__ float2 cmul(float2 a, float2 b) {
    return make_float2(a.x*b.x - a.y*b.y, a.x*b.y + a.y*b.x);
}

__global__ void kPrep()
{
    int t = blockIdx.x * blockDim.x + threadIdx.x;
    const double TP = 6.283185307179586476925286766559;
    if (t < 768) {
        double s, c;
        sincos(-TP * (double)t / 768.0, &s, &c);
        g_tw768[t] = make_float2((float)c, (float)s);
        if (t < 256) { sincos(-TP*(double)t/256.0, &s, &c); g_tw256[t] = make_float2((float)c,(float)s); }
        if (t < 128) { sincos(-TP*(double)t/128.0, &s, &c); g_tw128[t] = make_float2((float)c,(float)s); }
    }
}

// ---------------- forward W-FFT (256=16x16) pruned to kw<65 : x -> g_A ----------------
__global__ void kF1(const float* __restrict__ x)
{
    __shared__ float  Xs[256][16];
    __shared__ float2 Ys[256][16];
    int bh = blockIdx.x, c0 = blockIdx.y * 16;
    const float* xp = x + (size_t)bh * (WW*CCH) + c0;
    for (int e = threadIdx.x; e < 4096; e += 256)
        Xs[e >> 4][e & 15] = xp[(size_t)(e >> 4) * CCH + (e & 15)];
    __syncthreads();
    for (int e = threadIdx.x; e < 4096; e += 256) {
        int c = e & 15, n2 = (e >> 4) & 15, k1 = e >> 8;
        float re = 0.f, im = 0.f;
        int idx = (k1 * n2) & 255, step = (k1 * 16) & 255, w = n2;
        #pragma unroll
        for (int n1 = 0; n1 < 16; n1++) {
            float2 tw = __ldg(&g_tw256[idx]);
            float v = Xs[w][c];
            re = fmaf(v, tw.x, re); im = fmaf(v, tw.y, im);
            w += 16; idx = (idx + step) & 255;
        }
        Ys[(k1<<4) + n2][c] = make_float2(re, im);
    }
    __syncthreads();
    for (int e = threadIdx.x; e < KWV*16; e += 256) {
        int c = e & 15, kw = e >> 4;
        int k1 = kw & 15, k2 = kw >> 4;
        float2 acc = make_float2(0.f, 0.f);
        int idx = 0, step = (k2 * 16) & 255;
        #pragma unroll
        for (int n2 = 0; n2 < 16; n2++) {
            float2 tw = __ldg(&g_tw256[idx]);
            cmadd(acc, Ys[(k1<<4) + n2][c], tw);
            idx = (idx + step) & 255;
        }
        g_A[((size_t)bh*KWV + kw)*CCH + c0 + c] = acc;
    }
}

// ---------------- C-FFT (768=32x24). RIN=0: cplx g_A->g_B; RIN=1: real g_B->g_A ----------------
template<int RIN>
__global__ void kFC()
{
    __shared__ float2 Zs[768];
    __shared__ float2 Ys[768];
    size_t row = blockIdx.x;
    if (RIN) {
        const float* sp = (const float*)g_B;
        for (int e = threadIdx.x; e < 768; e += 256)
            Zs[e] = make_float2(sp[row*768 + e], 0.f);
    } else {
        for (int e = threadIdx.x; e < 768; e += 256)
            Zs[e] = g_A[row*768 + e];
    }
    __syncthreads();
    for (int e = threadIdx.x; e < 768; e += 256) {
        int k1 = e / 24, n2 = e - 24*k1;
        float2 acc = make_float2(0.f, 0.f);
        int idx = k1 * n2, step = k1 * 24;
        #pragma unroll 8
        for (int n1 = 0; n1 < 32; n1++) {
            float2 tw = __ldg(&g_tw768[idx]);
            cmadd(acc, Zs[24*n1 + n2], tw);
            idx += step; if (idx >= 768) idx -= 768;
        }
        Ys[e] = acc;
    }
    __syncthreads();
    float2* dst = RIN ? g_A : g_B;
    for (int e = threadIdx.x; e < 768; e += 256) {
        int k1 = e & 31, k2 = e >> 5;
        float2 acc = make_float2(0.f, 0.f);
        int idx = 0, step = 32 * k2;
        #pragma unroll 8
        for (int n2 = 0; n2 < 24; n2++) {
            float2 tw = __ldg(&g_tw768[idx]);
            cmadd(acc, Ys[k1*24 + n2], tw);
            idx += step; if (idx >= 768) idx -= 768;
        }
        dst[row*768 + e] = acc;
    }
}

// ---------------- H-FFT (128=16x8, const twiddles) + length-2 B-FFT ----------------
// SWAP=0: g_B -> g_A ;  SWAP=1: g_A -> g_B
template<int SWAP>
__global__ __launch_bounds__(128) void kFHB()
{
    __shared__ float2 Zs[2][128][8];
    __shared__ float2 Ys[2][16][8][8];   // [bb][k1][n2][c]
    __shared__ float2 stw[128];
    const float2* src = SWAP ? g_A : g_B;
    float2* dst = SWAP ? g_B : g_A;
    int kw = blockIdx.x, c0 = blockIdx.y * 8, tid = threadIdx.x;
    if (tid < 128) stw[tid] = g_tw128[tid];
    for (int e = tid; e < 2048; e += 128) {
        int c = e & 7, h = (e >> 3) & 127, b = e >> 10;
        Zs[b][h][c] = src[(((size_t)b*HH + h)*KWV + kw)*CCH + c0 + c];
    }
    __syncthreads();
    {   // stage1: one (bb,n2,c) per thread, DFT-16 over n1 with const twiddles
        int c = tid & 7, n2 = (tid >> 3) & 7, bb = tid >> 6;
        float2 u[16];
        #pragma unroll
        for (int n1 = 0; n1 < 16; n1++) {
            float2 a = Zs[0][8*n1 + n2][c], b = Zs[1][8*n1 + n2][c];
            u[n1] = bb ? make_float2(a.x - b.x, a.y - b.y)
                       : make_float2(a.x + b.x, a.y + b.y);
        }
        #pragma unroll
        for (int k1 = 0; k1 < 16; k1++) {
            float2 acc = make_float2(0.f, 0.f);
            #pragma unroll
            for (int n1 = 0; n1 < 16; n1++)
                cmaddc(acc, u[n1], W16C[(k1*n1)&15], W16S[(k1*n1)&15]);
            Ys[bb][k1][n2][c] = cmul(acc, stw[k1*n2]);
        }
    }
    __syncthreads();
    #pragma unroll
    for (int r = 0; r < 2; r++) {   // stage2: (bb,k1,c), DFT-8 over n2
        int t = tid + 128*r;
        int c = t & 7, k1 = (t >> 3) & 15, bb = t >> 7;
        float2 v[8];
        #pragma unroll
        for (int n2 = 0; n2 < 8; n2++) v[n2] = Ys[bb][k1][n2][c];
        #pragma unroll
        for (int k2 = 0; k2 < 8; k2++) {
            float2 acc = make_float2(0.f, 0.f);
            #pragma unroll
            for (int n2 = 0; n2 < 8; n2++)
                cmaddc(acc, v[n2], W16C[(2*k2*n2)&15], W16S[(2*k2*n2)&15]);
            dst[(((size_t)bb*HH + k1 + 16*k2)*KWV + kw)*CCH + c0 + c] = acc;
        }
    }
}

// ---------------- fused MLP (Karatsuba): g_A,x -> s (float) in g_B ----------------
__device__ __forceinline__ void gemv6(const float* sS, const float* sD,
                                      const float* sW0, const float* sW1,
                                      int pb, int ob, float aU[4][6], float aV[4][6])
{
    #pragma unroll
    for (int i = 0; i < 4; i++)
        #pragma unroll
        for (int j = 0; j < 6; j++) { aU[i][j] = 0.f; aV[i][j] = 0.f; }
    for (int k = 0; k < 96; k++) {
        float s4[4], d4[4];
        #pragma unroll
        for (int i = 0; i < 4; i++) { s4[i] = sS[k*65 + pb + i]; d4[i] = sD[k*65 + pb + i]; }
        float w0[6], w1r[6];
        #pragma unroll
        for (int j = 0; j < 3; j++) {
            float2 a = *(const float2*)(sW0 + k*96 + ob + 2*j);
            float2 b = *(const float2*)(sW1 + k*96 + ob + 2*j);
            w0[2*j] = a.x; w0[2*j+1] = a.y; w1r[2*j] = b.x; w1r[2*j+1] = b.y;
        }
        #pragma unroll
        for (int i = 0; i < 4; i++)
            #pragma unroll
            for (int j = 0; j < 6; j++) {
                aU[i][j] = fmaf(s4[i], w0[j],  aU[i][j]);
                aV[i][j] = fmaf(d4[i], w1r[j], aV[i][j]);
            }
    }
}

__global__ __launch_bounds__(256) void kMLP(const float* __restrict__ x,
    const float* __restrict__ w1, const float* __restrict__ b1,
    const float* __restrict__ w2, const float* __restrict__ b2)
{
    extern __shared__ float smp[];
    float* sW0 = smp;            // 96*96
    float* sW1 = smp + 9216;     // 96*96
    float* sS  = smp + 18432;    // 96*65
    float* sD  = smp + 24672;    // 96*65
    const int n = blockIdx.y, p0 = blockIdx.x * 64, tid = threadIdx.x;
    const int og = tid & 15, pg = tid >> 4, ob = og*6, pb = pg*4;

    const float4* W10 = (const float4*)(w1 + (size_t)n*9216);
    const float4* W11 = (const float4*)(w1 + (size_t)(NB+n)*9216);
    for (int e = tid; e < 2304; e += 256) {
        ((float4*)sW0)[e] = W10[e];
        ((float4*)sW1)[e] = W11[e];
    }
    for (int e = tid; e < 6144; e += 256) {
        int p = e / 96, c = e - 96*p;
        int pgl = p0 + p;
        int b = (pgl >= HH*KWV) ? 1 : 0;
        int r = pgl - b*(HH*KWV);
        int h = r / KWV, kw = r - h*KWV;
        float2 z = g_A[(size_t)pgl*CCH + n*BS + c];
        float av = z.x + z.y;
        int hn = (HH - h) & (HH-1), wn = (WW - kw) & (WW-1);
        float an = x[(((size_t)b*HH + hn)*WW + wn)*CCH + n*BS + c];
        sS[c*65 + p] = av + an;
        sD[c*65 + p] = av - an;
    }
    __syncthreads();

    float aU[4][6], aV[4][6], keep[4][6];
    gemv6(sS, sD, sW0, sW1, pb, ob, aU, aV);
    float bk[6], bn[6];
    #pragma unroll
    for (int j = 0; j < 6; j++) { bk[j] = b1[n*BS + ob + j]; bn[j] = b1[(NB+n)*BS + ob + j]; }
    __syncthreads();
    #pragma unroll
    for (int i = 0; i < 4; i++)
        #pragma unroll
        for (int j = 0; j < 6; j++) {
            float U = aU[i][j], V = aV[i][j];
            float o1k = fmaxf(fmaf(0.5f, U + V, bk[j]), 0.f);
            float o1n = fmaxf(fmaf(0.5f, U - V, bn[j]), 0.f);
            keep[i][j] = o1n;
            sS[(ob+j)*65 + pb + i] = o1k + o1n;
            sD[(ob+j)*65 + pb + i] = o1k - o1n;
        }
    const float4* W20 = (const float4*)(w2 + (size_t)n*9216);
    const float4* W21 = (const float4*)(w2 + (size_t)(NB+n)*9216);
    for (int e = tid; e < 2304; e += 256) {
        ((float4*)sW0)[e] = W20[e];
        ((float4*)sW1)[e] = W21[e];
    }
    __syncthreads();

    gemv6(sS, sD, sW0, sW1, pb, ob, aU, aV);
    #pragma unroll
    for (int j = 0; j < 6; j++) { bk[j] = b2[n*BS + ob + j]; bn[j] = b2[(NB+n)*BS + ob + j]; }
    __syncthreads();
    #pragma unroll
    for (int i = 0; i < 4; i++)
        #pragma unroll
        for (int j = 0; j < 6; j++) {
            float ok = fmaf(0.5f, aU[i][j] + aV[i][j], bk[j]);
            float un = keep[i][j];
            sS[(ob+j)*65 + pb + i] = un + ok;
            sD[(ob+j)*65 + pb + i] = un - ok;   // o2_nk uses o2_k (reference quirk)
            keep[i][j] = ok;
        }
    __syncthreads();

    gemv6(sS, sD, sW0, sW1, pb, ob, aU, aV);
    float* outp = (float*)g_B;
    #pragma unroll
    for (int i = 0; i < 4; i++)
        #pragma unroll
        for (int j = 0; j < 6; j++) {
            float o2n = fmaf(0.5f, aU[i][j] + aV[i][j], bn[j]);
            float t = keep[i][j] + o2n;
            float s = copysignf(fmaxf(fabsf(t) - 0.01f, 0.f), t);
            outp[(size_t)(p0 + pb + i)*CCH + n*BS + ob + j] = s;
        }
}

// ---------------- inverse W-FFT (65 inputs -> 256 outs) + scale + residual : g_B -> out ----------------
__global__ void kIW(const float* __restrict__ x, float* __restrict__ out)
{
    __shared__ float2 Ys[16][16][16];
    int bh = blockIdx.x, c0 = blockIdx.y * 16;
    const float2* zp = g_B + (size_t)bh*KWV*CCH + c0;
    for (int e = threadIdx.x; e < 4096; e += 256) {
        int c = e & 15, n2 = (e >> 4) & 15, k1 = e >> 8;
        float2 acc = make_float2(0.f, 0.f);
        int idx = (k1 * n2) & 255, step = (k1 * 16) & 255;
        int nmax = (n2 == 0) ? 5 : 4;
        for (int n1 = 0; n1 < nmax; n1++) {
            int w = (n1 << 4) + n2;
            float2 z = __ldg(&zp[(size_t)w*CCH + c]);
            float2 tw = __ldg(&g_tw256[idx]);
            cmadd(acc, z, tw);
            idx = (idx + step) & 255;
        }
        Ys[k1][n2][c] = acc;
    }
    __syncthreads();
    const float invN = 1.0f / 50331648.0f;
    for (int e = threadIdx.x; e < 4096; e += 256) {
        int c = e & 15, k = e >> 4;
        int k1 = k & 15, k2 = k >> 4;
        float2 acc = make_float2(0.f, 0.f);
        int idx = 0, step = (k2 * 16) & 255;
        #pragma unroll
        for (int n2 = 0; n2 < 16; n2++) {
            float2 tw = __ldg(&g_tw256[idx]);
            cmadd(acc, Ys[k1][n2][c], tw);
            idx = (idx + step) & 255;
        }
        size_t a = ((size_t)bh*WW + k)*CCH + c0 + c;
        out[a] = fmaf(acc.x + acc.y, invN, x[a]);
    }
}

extern "C" void kernel_launch(void* const* d_in, const int* in_sizes, int n_in,
                              void* d_out, int out_size)
{
    const float* x  = (const float*)d_in[0];
    const float* w1 = (const float*)d_in[1];
    const float* b1 = (const float*)d_in[2];
    const float* w2 = (const float*)d_in[3];
    const float* b2 = (const float*)d_in[4];
    float* out = (float*)d_out;

    cudaFuncSetAttribute(kMLP, cudaFuncAttributeMaxDynamicSharedMemorySize, 30912*4);

    kPrep<<<3, 256>>>();
    kF1 <<<dim3(BB*HH, CCH/16), 256>>>(x);     // x -> A
    kFC<0><<<NPOS, 256>>>();                   // A -> B
    kFHB<0><<<dim3(KWV, CCH/8), 128>>>();      // B -> A
    kMLP<<<dim3(NPOS/64, NB), 256, 30912*4>>>(x, w1, b1, w2, b2);  // A,x -> s in B
    kFC<1><<<NPOS, 256>>>();                   // B(real) -> A
    kFHB<1><<<dim3(KWV, CCH/8), 128>>>();      // A -> B
    kIW <<<dim3(BB*HH, CCH/16), 256>>>(x, out);// B -> out
}

// round 4
// speedup vs baseline: 2.4556x; 2.0500x over previous
#include <cuda_runtime.h>
#include <math.h>
#include <stdint.h>

#define BB 2
#define HH 128
#define WW 256
#define CCH 768
#define KWV 65
#define NB 8
#define BS 96
#define NPOS (BB*HH*KWV)
#define SLABN (NPOS*CCH)

__device__ float2 g_A[SLABN];
__device__ float2 g_B[SLABN];
__device__ float2 g_tw256[256];
__device__ float2 g_tw768[768];
__device__ float2 g_tw128[128];

__device__ constexpr float W16C[16] = {
  1.0f, 0.92387953251128674f, 0.70710678118654752f, 0.38268343236508977f,
  0.0f,-0.38268343236508977f,-0.70710678118654752f,-0.92387953251128674f,
 -1.0f,-0.92387953251128674f,-0.70710678118654752f,-0.38268343236508977f,
  0.0f, 0.38268343236508977f, 0.70710678118654752f, 0.92387953251128674f};
__device__ constexpr float W16S[16] = {
  0.0f,-0.38268343236508977f,-0.70710678118654752f,-0.92387953251128674f,
 -1.0f,-0.92387953251128674f,-0.70710678118654752f,-0.38268343236508977f,
  0.0f, 0.38268343236508977f, 0.70710678118654752f, 0.92387953251128674f,
  1.0f, 0.92387953251128674f, 0.70710678118654752f, 0.38268343236508977f};

__device__ __forceinline__ void cmadd(float2& acc, float2 z, float2 t) {
    acc.x = fmaf(z.x, t.x, fmaf(-z.y, t.y, acc.x));
    acc.y = fmaf(z.x, t.y, fmaf( z.y, t.x, acc.y));
}
__device__ __forceinline__ void cmaddc(float2& acc, float2 z, float C, float S) {
    acc.x = fmaf(z.x, C, fmaf(-z.y, S, acc.x));
    acc.y = fmaf(z.x, S, fmaf( z.y, C, acc.y));
}
__device__ __forceinline__ float2 cmul(float2 a, float2 b) {
    return make_float2(a.x*b.x - a.y*b.y, a.x*b.y + a.y*b.x);
}

__global__ void kPrep()
{
    int t = blockIdx.x * blockDim.x + threadIdx.x;
    const double TP = 6.283185307179586476925286766559;
    if (t < 768) {
        double s, c;
        sincos(-TP * (double)t / 768.0, &s, &c);
        g_tw768[t] = make_float2((float)c, (float)s);
        if (t < 256) { sincos(-TP*(double)t/256.0, &s, &c); g_tw256[t] = make_float2((float)c,(float)s); }
        if (t < 128) { sincos(-TP*(double)t/128.0, &s, &c); g_tw128[t] = make_float2((float)c,(float)s); }
    }
}

// ---------------- forward W-FFT (256=16x16, const-twiddle) pruned kw<65 : x -> g_A ----------------
__global__ __launch_bounds__(256) void kF1(const float* __restrict__ x)
{
    extern __shared__ float smF1[];
    float*  Xs  = smF1;                             // 256*17 floats
    float2* Ys  = (float2*)(smF1 + 4352);           // 256*17 float2
    float2* stw = Ys + 4352;                        // 256 float2
    const int bh = blockIdx.x, c0 = blockIdx.y * 16, tid = threadIdx.x;
    if (tid < 256) stw[tid] = g_tw256[tid];
    const float* xp = x + (size_t)bh * (WW*CCH) + c0;
    for (int e = tid; e < 4096; e += 256)
        Xs[(e >> 4)*17 + (e & 15)] = xp[(size_t)(e >> 4) * CCH + (e & 15)];
    __syncthreads();
    {   // stage1: thread = (n2,c). real DFT-16 over n1 (const) then x tw256[n2*k1]
        const int n2 = tid >> 4, c = tid & 15;
        float u[16];
        #pragma unroll
        for (int n1 = 0; n1 < 16; n1++) u[n1] = Xs[(16*n1 + n2)*17 + c];
        #pragma unroll
        for (int k1 = 0; k1 < 16; k1++) {
            float re = 0.f, im = 0.f;
            #pragma unroll
            for (int n1 = 0; n1 < 16; n1++) {
                re = fmaf(u[n1], W16C[(k1*n1)&15], re);
                im = fmaf(u[n1], W16S[(k1*n1)&15], im);
            }
            Ys[(k1*16 + n2)*17 + c] = cmul(make_float2(re, im), stw[n2*k1]);
        }
    }
    __syncthreads();
    {   // stage2: thread = (k1,c). const DFT-16 over n2, keep kw<65
        const int k1 = tid >> 4, c = tid & 15;
        float2 v[16];
        #pragma unroll
        for (int n2 = 0; n2 < 16; n2++) v[n2] = Ys[(k1*16 + n2)*17 + c];
        float2* dst = g_A + ((size_t)bh*KWV)*CCH + c0 + c;
        #pragma unroll
        for (int k2 = 0; k2 < 4; k2++) {
            float2 acc = make_float2(0.f, 0.f);
            #pragma unroll
            for (int n2 = 0; n2 < 16; n2++)
                cmaddc(acc, v[n2], W16C[(k2*n2)&15], W16S[(k2*n2)&15]);
            dst[(size_t)(k1 + 16*k2)*CCH] = acc;
        }
        if (k1 == 0) {   // kw = 64
            float2 acc = make_float2(0.f, 0.f);
            #pragma unroll
            for (int n2 = 0; n2 < 16; n2++)
                cmaddc(acc, v[n2], W16C[(4*n2)&15], W16S[(4*n2)&15]);
            dst[(size_t)64*CCH] = acc;
        }
    }
}

// ---------------- C-FFT 768 = 16x16x3, const twiddles. RIN=0: g_A->g_B; RIN=1: real g_B->g_A ----------------
template<int RIN>
__global__ __launch_bounds__(256) void kFC()
{
    extern __shared__ float2 smC[];
    float2* zb = smC;            // 4*768
    float2* Ab = smC + 3072;     // 4*768
    float2* stw256 = smC + 6144; // 256
    float2* stw768 = smC + 6400; // 512
    const int tid = threadIdx.x, r = tid >> 6, l = tid & 63;
    const size_t row = (size_t)blockIdx.x * 4 + r;
    if (tid < 256) stw256[tid] = g_tw256[tid];
    for (int e = tid; e < 512; e += 256) stw768[e] = g_tw768[e];
    if (RIN) {
        const float* sp = (const float*)g_B;
        #pragma unroll
        for (int q = 0; q < 12; q++)
            zb[r*768 + l + 64*q] = make_float2(sp[row*768 + l + 64*q], 0.f);
    } else {
        #pragma unroll
        for (int q = 0; q < 12; q++)
            zb[r*768 + l + 64*q] = g_A[row*768 + l + 64*q];
    }
    __syncthreads();
    if (l < 48) {   // stage1: (n3,n2): DFT-16 over n1 (const), then x tw256[n2*k1]
        const int n3 = l >> 4, n2 = l & 15;
        if (RIN) {
            float u[16];
            #pragma unroll
            for (int n1 = 0; n1 < 16; n1++) u[n1] = zb[r*768 + n3 + 3*n2 + 48*n1].x;
            #pragma unroll
            for (int k1 = 0; k1 < 16; k1++) {
                float re = 0.f, im = 0.f;
                #pragma unroll
                for (int n1 = 0; n1 < 16; n1++) {
                    re = fmaf(u[n1], W16C[(k1*n1)&15], re);
                    im = fmaf(u[n1], W16S[(k1*n1)&15], im);
                }
                Ab[r*768 + (n3*16 + k1)*16 + n2] = cmul(make_float2(re, im), stw256[n2*k1]);
            }
        } else {
            float2 u[16];
            #pragma unroll
            for (int n1 = 0; n1 < 16; n1++) u[n1] = zb[r*768 + n3 + 3*n2 + 48*n1];
            #pragma unroll
            for (int k1 = 0; k1 < 16; k1++) {
                float2 acc = make_float2(0.f, 0.f);
                #pragma unroll
                for (int n1 = 0; n1 < 16; n1++)
                    cmaddc(acc, u[n1], W16C[(k1*n1)&15], W16S[(k1*n1)&15]);
                Ab[r*768 + (n3*16 + k1)*16 + n2] = cmul(acc, stw256[n2*k1]);
            }
        }
    }
    __syncthreads();
    if (l < 48) {   // stage2: (n3,k1): const DFT-16 over n2
        const int n3 = l >> 4, k1 = l & 15;
        float2 v[16];
        #pragma unroll
        for (int n2 = 0; n2 < 16; n2++) v[n2] = Ab[r*768 + (n3*16 + k1)*16 + n2];
        #pragma unroll
        for (int k2 = 0; k2 < 16; k2++) {
            float2 acc = make_float2(0.f, 0.f);
            #pragma unroll
            for (int n2 = 0; n2 < 16; n2++)
                cmaddc(acc, v[n2], W16C[(k2*n2)&15], W16S[(k2*n2)&15]);
            zb[r*768 + (n3*16 + k1)*16 + k2] = acc;
        }
    }
    __syncthreads();
    {   // stage3: radix-3 combine, m = k1+16k2
        float2* dst = RIN ? g_A : g_B;
        const float s3 = 0.86602540378443865f;
        #pragma unroll
        for (int q = 0; q < 4; q++) {
            const int m = l + 64*q;
            const int k1 = m & 15, k2 = m >> 4;
            float2 b0 = zb[r*768 +       k1*16 + k2];
            float2 b1 = cmul(zb[r*768 + 256 + k1*16 + k2], stw768[m]);
            float2 b2 = cmul(zb[r*768 + 512 + k1*16 + k2], stw768[2*m]);
            float2 t1 = make_float2(b1.x + b2.x, b1.y + b2.y);
            float2 t2 = make_float2(b1.x - b2.x, b1.y - b2.y);
            dst[row*768 + m] = make_float2(b0.x + t1.x, b0.y + t1.y);
            float xr = fmaf(-0.5f, t1.x, b0.x);
            float xi = fmaf(-0.5f, t1.y, b0.y);
            dst[row*768 + m + 256] = make_float2(fmaf( s3, t2.y, xr), fmaf(-s3, t2.x, xi));
            dst[row*768 + m + 512] = make_float2(fmaf(-s3, t2.y, xr), fmaf( s3, t2.x, xi));
        }
    }
}

// ---------------- H-FFT (128=16x8, const twiddles) + length-2 B-FFT ----------------
template<int SWAP>
__global__ __launch_bounds__(128) void kFHB()
{
    __shared__ float2 Zs[2][128][8];
    __shared__ float2 Ys[2][16][8][8];
    __shared__ float2 stw[128];
    const float2* src = SWAP ? g_A : g_B;
    float2* dst = SWAP ? g_B : g_A;
    int kw = blockIdx.x, c0 = blockIdx.y * 8, tid = threadIdx.x;
    if (tid < 128) stw[tid] = g_tw128[tid];
    for (int e = tid; e < 2048; e += 128) {
        int c = e & 7, h = (e >> 3) & 127, b = e >> 10;
        Zs[b][h][c] = src[(((size_t)b*HH + h)*KWV + kw)*CCH + c0 + c];
    }
    __syncthreads();
    {
        int c = tid & 7, n2 = (tid >> 3) & 7, bb = tid >> 6;
        float2 u[16];
        #pragma unroll
        for (int n1 = 0; n1 < 16; n1++) {
            float2 a = Zs[0][8*n1 + n2][c], b = Zs[1][8*n1 + n2][c];
            u[n1] = bb ? make_float2(a.x - b.x, a.y - b.y)
                       : make_float2(a.x + b.x, a.y + b.y);
        }
        #pragma unroll
        for (int k1 = 0; k1 < 16; k1++) {
            float2 acc = make_float2(0.f, 0.f);
            #pragma unroll
            for (int n1 = 0; n1 < 16; n1++)
                cmaddc(acc, u[n1], W16C[(k1*n1)&15], W16S[(k1*n1)&15]);
            Ys[bb][k1][n2][c] = cmul(acc, stw[k1*n2]);
        }
    }
    __syncthreads();
    #pragma unroll
    for (int r = 0; r < 2; r++) {
        int t = tid + 128*r;
        int c = t & 7, k1 = (t >> 3) & 15, bb = t >> 7;
        float2 v[8];
        #pragma unroll
        for (int n2 = 0; n2 < 8; n2++) v[n2] = Ys[bb][k1][n2][c];
        #pragma unroll
        for (int k2 = 0; k2 < 8; k2++) {
            float2 acc = make_float2(0.f, 0.f);
            #pragma unroll
            for (int n2 = 0; n2 < 8; n2++)
                cmaddc(acc, v[n2], W16C[(2*k2*n2)&15], W16S[(2*k2*n2)&15]);
            dst[(((size_t)bb*HH + k1 + 16*k2)*KWV + kw)*CCH + c0 + c] = acc;
        }
    }
}

// ---------------- fused MLP (Karatsuba): g_A,x -> s (float) in g_B ----------------
__device__ __forceinline__ void gemv6(const float* sS, const float* sD,
                                      const float* sW0, const float* sW1,
                                      int pb, int ob, float aU[4][6], float aV[4][6])
{
    #pragma unroll
    for (int i = 0; i < 4; i++)
        #pragma unroll
        for (int j = 0; j < 6; j++) { aU[i][j] = 0.f; aV[i][j] = 0.f; }
    for (int k = 0; k < 96; k++) {
        float s4[4], d4[4];
        #pragma unroll
        for (int i = 0; i < 4; i++) { s4[i] = sS[k*65 + pb + i]; d4[i] = sD[k*65 + pb + i]; }
        float w0[6], w1r[6];
        #pragma unroll
        for (int j = 0; j < 3; j++) {
            float2 a = *(const float2*)(sW0 + k*96 + ob + 2*j);
            float2 b = *(const float2*)(sW1 + k*96 + ob + 2*j);
            w0[2*j] = a.x; w0[2*j+1] = a.y; w1r[2*j] = b.x; w1r[2*j+1] = b.y;
        }
        #pragma unroll
        for (int i = 0; i < 4; i++)
            #pragma unroll
            for (int j = 0; j < 6; j++) {
                aU[i][j] = fmaf(s4[i], w0[j],  aU[i][j]);
                aV[i][j] = fmaf(d4[i], w1r[j], aV[i][j]);
            }
    }
}

__global__ __launch_bounds__(256) void kMLP(const float* __restrict__ x,
    const float* __restrict__ w1, const float* __restrict__ b1,
    const float* __restrict__ w2, const float* __restrict__ b2)
{
    extern __shared__ float smp[];
    float* sW0 = smp;
    float* sW1 = smp + 9216;
    float* sS  = smp + 18432;
    float* sD  = smp + 24672;
    const int n = blockIdx.y, p0 = blockIdx.x * 64, tid = threadIdx.x;
    const int og = tid & 15, pg = tid >> 4, ob = og*6, pb = pg*4;

    const float4* W10 = (const float4*)(w1 + (size_t)n*9216);
    const float4* W11 = (const float4*)(w1 + (size_t)(NB+n)*9216);
    for (int e = tid; e < 2304; e += 256) {
        ((float4*)sW0)[e] = W10[e];
        ((float4*)sW1)[e] = W11[e];
    }
    for (int e = tid; e < 6144; e += 256) {
        int p = e / 96, c = e - 96*p;
        int pgl = p0 + p;
        int b = (pgl >= HH*KWV) ? 1 : 0;
        int r = pgl - b*(HH*KWV);
        int h = r / KWV, kw = r - h*KWV;
        float2 z = g_A[(size_t)pgl*CCH + n*BS + c];
        float av = z.x + z.y;
        int hn = (HH - h) & (HH-1), wn = (WW - kw) & (WW-1);
        float an = x[(((size_t)b*HH + hn)*WW + wn)*CCH + n*BS + c];
        sS[c*65 + p] = av + an;
        sD[c*65 + p] = av - an;
    }
    __syncthreads();

    float aU[4][6], aV[4][6], keep[4][6];
    gemv6(sS, sD, sW0, sW1, pb, ob, aU, aV);
    float bk[6], bn[6];
    #pragma unroll
    for (int j = 0; j < 6; j++) { bk[j] = b1[n*BS + ob + j]; bn[j] = b1[(NB+n)*BS + ob + j]; }
    __syncthreads();
    #pragma unroll
    for (int i = 0; i < 4; i++)
        #pragma unroll
        for (int j = 0; j < 6; j++) {
            float U = aU[i][j], V = aV[i][j];
            float o1k = fmaxf(fmaf(0.5f, U + V, bk[j]), 0.f);
            float o1n = fmaxf(fmaf(0.5f, U - V, bn[j]), 0.f);
            keep[i][j] = o1n;
            sS[(ob+j)*65 + pb + i] = o1k + o1n;
            sD[(ob+j)*65 + pb + i] = o1k - o1n;
        }
    const float4* W20 = (const float4*)(w2 + (size_t)n*9216);
    const float4* W21 = (const float4*)(w2 + (size_t)(NB+n)*9216);
    for (int e = tid; e < 2304; e += 256) {
        ((float4*)sW0)[e] = W20[e];
        ((float4*)sW1)[e] = W21[e];
    }
    __syncthreads();

    gemv6(sS, sD, sW0, sW1, pb, ob, aU, aV);
    #pragma unroll
    for (int j = 0; j < 6; j++) { bk[j] = b2[n*BS + ob + j]; bn[j] = b2[(NB+n)*BS + ob + j]; }
    __syncthreads();
    #pragma unroll
    for (int i = 0; i < 4; i++)
        #pragma unroll
        for (int j = 0; j < 6; j++) {
            float ok = fmaf(0.5f, aU[i][j] + aV[i][j], bk[j]);
            float un = keep[i][j];
            sS[(ob+j)*65 + pb + i] = un + ok;
            sD[(ob+j)*65 + pb + i] = un - ok;
            keep[i][j] = ok;
        }
    __syncthreads();

    gemv6(sS, sD, sW0, sW1, pb, ob, aU, aV);
    float* outp = (float*)g_B;
    #pragma unroll
    for (int i = 0; i < 4; i++)
        #pragma unroll
        for (int j = 0; j < 6; j++) {
            float o2n = fmaf(0.5f, aU[i][j] + aV[i][j], bn[j]);
            float t = keep[i][j] + o2n;
            float s = copysignf(fmaxf(fabsf(t) - 0.01f, 0.f), t);
            outp[(size_t)(p0 + pb + i)*CCH + n*BS + ob + j] = s;
        }
}

// ---------------- inverse W-FFT (65 -> 256) + scale + residual : g_B -> out ----------------
__global__ __launch_bounds__(256) void kIW(const float* __restrict__ x, float* __restrict__ out)
{
    __shared__ float2 Ys[256*17];
    __shared__ float2 stw[256];
    const int bh = blockIdx.x, c0 = blockIdx.y * 16, tid = threadIdx.x;
    if (tid < 256) stw[tid] = g_tw256[tid];
    __syncthreads();
    const float2* zp = g_B + (size_t)bh*KWV*CCH + c0;
    for (int e = tid; e < 4096; e += 256) {
        int c = e & 15, n2 = (e >> 4) & 15, k1 = e >> 8;
        float2 acc = make_float2(0.f, 0.f);
        int idx = (k1 * n2) & 255, step = (k1 * 16) & 255;
        int nmax = (n2 == 0) ? 5 : 4;
        for (int n1 = 0; n1 < nmax; n1++) {
            int w = (n1 << 4) + n2;
            float2 z = __ldg(&zp[(size_t)w*CCH + c]);
            cmadd(acc, z, stw[idx]);
            idx = (idx + step) & 255;
        }
        Ys[(k1*16 + n2)*17 + c] = acc;
    }
    __syncthreads();
    const float invN = 1.0f / 50331648.0f;
    {
        const int k1 = tid >> 4, c = tid & 15;
        float2 v[16];
        #pragma unroll
        for (int n2 = 0; n2 < 16; n2++) v[n2] = Ys[(k1*16 + n2)*17 + c];
        #pragma unroll
        for (int k2 = 0; k2 < 16; k2++) {
            float2 acc = make_float2(0.f, 0.f);
            #pragma unroll
            for (int n2 = 0; n2 < 16; n2++)
                cmaddc(acc, v[n2], W16C[(k2*n2)&15], W16S[(k2*n2)&15]);
            size_t a = ((size_t)bh*WW + k1 + 16*k2)*CCH + c0 + c;
            out[a] = fmaf(acc.x + acc.y, invN, x[a]);
        }
    }
}

extern "C" void kernel_launch(void* const* d_in, const int* in_sizes, int n_in,
                              void* d_out, int out_size)
{
    const float* x  = (const float*)d_in[0];
    const float* w1 = (const float*)d_in[1];
    const float* b1 = (const float*)d_in[2];
    const float* w2 = (const float*)d_in[3];
    const float* b2 = (const float*)d_in[4];
    float* out = (float*)d_out;

    cudaFuncSetAttribute(kMLP,  cudaFuncAttributeMaxDynamicSharedMemorySize, 30912*4);
    cudaFuncSetAttribute(kF1,   cudaFuncAttributeMaxDynamicSharedMemorySize, 54272);
    cudaFuncSetAttribute(kFC<0>, cudaFuncAttributeMaxDynamicSharedMemorySize, 55296);
    cudaFuncSetAttribute(kFC<1>, cudaFuncAttributeMaxDynamicSharedMemorySize, 55296);

    kPrep<<<3, 256>>>();
    kF1 <<<dim3(BB*HH, CCH/16), 256, 54272>>>(x);   // x -> A
    kFC<0><<<NPOS/4, 256, 55296>>>();               // A -> B
    kFHB<0><<<dim3(KWV, CCH/8), 128>>>();           // B -> A
    kMLP<<<dim3(NPOS/64, NB), 256, 30912*4>>>(x, w1, b1, w2, b2);  // A,x -> s in B
    kFC<1><<<NPOS/4, 256, 55296>>>();               // B(real) -> A
    kFHB<1><<<dim3(KWV, CCH/8), 128>>>();           // A -> B
    kIW <<<dim3(BB*HH, CCH/16), 256>>>(x, out);     // B -> out
}

// round 5
// speedup vs baseline: 2.7535x; 1.1213x over previous
#include <cuda_runtime.h>
#include <math.h>
#include <stdint.h>

#define BB 2
#define HH 128
#define WW 256
#define CCH 768
#define KWV 65
#define NB 8
#define BS 96
#define NPOS (BB*HH*KWV)
#define SLABN (NPOS*CCH)

typedef unsigned long long u64;

__device__ float2 g_A[SLABN];
__device__ float2 g_B[SLABN];
__device__ float2 g_tw256[256];
__device__ float2 g_tw768[768];
__device__ float2 g_tw128[128];

__device__ constexpr float W16C[16] = {
  1.0f, 0.92387953251128674f, 0.70710678118654752f, 0.38268343236508977f,
  0.0f,-0.38268343236508977f,-0.70710678118654752f,-0.92387953251128674f,
 -1.0f,-0.92387953251128674f,-0.70710678118654752f,-0.38268343236508977f,
  0.0f, 0.38268343236508977f, 0.70710678118654752f, 0.92387953251128674f};
__device__ constexpr float W16S[16] = {
  0.0f,-0.38268343236508977f,-0.70710678118654752f,-0.92387953251128674f,
 -1.0f,-0.92387953251128674f,-0.70710678118654752f,-0.38268343236508977f,
  0.0f, 0.38268343236508977f, 0.70710678118654752f, 0.92387953251128674f,
  1.0f, 0.92387953251128674f, 0.70710678118654752f, 0.38268343236508977f};

__device__ __forceinline__ void cmadd(float2& acc, float2 z, float2 t) {
    acc.x = fmaf(z.x, t.x, fmaf(-z.y, t.y, acc.x));
    acc.y = fmaf(z.x, t.y, fmaf( z.y, t.x, acc.y));
}
__device__ __forceinline__ void cmaddc(float2& acc, float2 z, float C, float S) {
    acc.x = fmaf(z.x, C, fmaf(-z.y, S, acc.x));
    acc.y = fmaf(z.x, S, fmaf( z.y, C, acc.y));
}
__device__ __forceinline__ float2 cmul(float2 a, float2 b) {
    return make_float2(a.x*b.x - a.y*b.y, a.x*b.y + a.y*b.x);
}
// packed f32x2 helpers
__device__ __forceinline__ u64 pk2(float v) {
    u64 r; asm("mov.b64 %0, {%1, %1};" : "=l"(r) : "f"(v)); return r;
}
__device__ __forceinline__ void f2fma(u64& acc, u64 a, u64 b) {
    asm("fma.rn.f32x2 %0, %1, %2, %0;" : "+l"(acc) : "l"(a), "l"(b));
}
__device__ __forceinline__ float2 up2(u64 a) {
    float2 f; asm("mov.b64 {%0, %1}, %2;" : "=f"(f.x), "=f"(f.y) : "l"(a)); return f;
}

__global__ void kPrep()
{
    int t = blockIdx.x * blockDim.x + threadIdx.x;
    const double TP = 6.283185307179586476925286766559;
    if (t < 768) {
        double s, c;
        sincos(-TP * (double)t / 768.0, &s, &c);
        g_tw768[t] = make_float2((float)c, (float)s);
        if (t < 256) { sincos(-TP*(double)t/256.0, &s, &c); g_tw256[t] = make_float2((float)c,(float)s); }
        if (t < 128) { sincos(-TP*(double)t/128.0, &s, &c); g_tw128[t] = make_float2((float)c,(float)s); }
    }
}

// ---------------- forward W-FFT (256=16x16, const-twiddle) pruned kw<65 : x -> g_A ----------------
__global__ __launch_bounds__(256) void kF1(const float* __restrict__ x)
{
    extern __shared__ float smF1[];
    float*  Xs  = smF1;
    float2* Ys  = (float2*)(smF1 + 4352);
    float2* stw = Ys + 4352;
    const int bh = blockIdx.x, c0 = blockIdx.y * 16, tid = threadIdx.x;
    if (tid < 256) stw[tid] = g_tw256[tid];
    const float* xp = x + (size_t)bh * (WW*CCH) + c0;
    for (int e = tid; e < 4096; e += 256)
        Xs[(e >> 4)*17 + (e & 15)] = xp[(size_t)(e >> 4) * CCH + (e & 15)];
    __syncthreads();
    {
        const int n2 = tid >> 4, c = tid & 15;
        float u[16];
        #pragma unroll
        for (int n1 = 0; n1 < 16; n1++) u[n1] = Xs[(16*n1 + n2)*17 + c];
        #pragma unroll
        for (int k1 = 0; k1 < 16; k1++) {
            float re = 0.f, im = 0.f;
            #pragma unroll
            for (int n1 = 0; n1 < 16; n1++) {
                re = fmaf(u[n1], W16C[(k1*n1)&15], re);
                im = fmaf(u[n1], W16S[(k1*n1)&15], im);
            }
            Ys[(k1*16 + n2)*17 + c] = cmul(make_float2(re, im), stw[n2*k1]);
        }
    }
    __syncthreads();
    {
        const int k1 = tid >> 4, c = tid & 15;
        float2 v[16];
        #pragma unroll
        for (int n2 = 0; n2 < 16; n2++) v[n2] = Ys[(k1*16 + n2)*17 + c];
        float2* dst = g_A + ((size_t)bh*KWV)*CCH + c0 + c;
        #pragma unroll
        for (int k2 = 0; k2 < 4; k2++) {
            float2 acc = make_float2(0.f, 0.f);
            #pragma unroll
            for (int n2 = 0; n2 < 16; n2++)
                cmaddc(acc, v[n2], W16C[(k2*n2)&15], W16S[(k2*n2)&15]);
            dst[(size_t)(k1 + 16*k2)*CCH] = acc;
        }
        if (k1 == 0) {
            float2 acc = make_float2(0.f, 0.f);
            #pragma unroll
            for (int n2 = 0; n2 < 16; n2++)
                cmaddc(acc, v[n2], W16C[(4*n2)&15], W16S[(4*n2)&15]);
            dst[(size_t)64*CCH] = acc;
        }
    }
}

// ---------------- C-FFT 768 = 16x16x3, const twiddles. RIN=0: g_A->g_B; RIN=1: real g_B->g_A ----------------
template<int RIN>
__global__ __launch_bounds__(256) void kFC()
{
    extern __shared__ float2 smC[];
    float2* zb = smC;
    float2* Ab = smC + 3072;
    float2* stw256 = smC + 6144;
    float2* stw768 = smC + 6400;
    const int tid = threadIdx.x, r = tid >> 6, l = tid & 63;
    const size_t row = (size_t)blockIdx.x * 4 + r;
    if (tid < 256) stw256[tid] = g_tw256[tid];
    for (int e = tid; e < 512; e += 256) stw768[e] = g_tw768[e];
    if (RIN) {
        const float* sp = (const float*)g_B;
        #pragma unroll
        for (int q = 0; q < 12; q++)
            zb[r*768 + l + 64*q] = make_float2(sp[row*768 + l + 64*q], 0.f);
    } else {
        #pragma unroll
        for (int q = 0; q < 12; q++)
            zb[r*768 + l + 64*q] = g_A[row*768 + l + 64*q];
    }
    __syncthreads();
    if (l < 48) {
        const int n3 = l >> 4, n2 = l & 15;
        if (RIN) {
            float u[16];
            #pragma unroll
            for (int n1 = 0; n1 < 16; n1++) u[n1] = zb[r*768 + n3 + 3*n2 + 48*n1].x;
            #pragma unroll
            for (int k1 = 0; k1 < 16; k1++) {
                float re = 0.f, im = 0.f;
                #pragma unroll
                for (int n1 = 0; n1 < 16; n1++) {
                    re = fmaf(u[n1], W16C[(k1*n1)&15], re);
                    im = fmaf(u[n1], W16S[(k1*n1)&15], im);
                }
                Ab[r*768 + (n3*16 + k1)*16 + n2] = cmul(make_float2(re, im), stw256[n2*k1]);
            }
        } else {
            float2 u[16];
            #pragma unroll
            for (int n1 = 0; n1 < 16; n1++) u[n1] = zb[r*768 + n3 + 3*n2 + 48*n1];
            #pragma unroll
            for (int k1 = 0; k1 < 16; k1++) {
                float2 acc = make_float2(0.f, 0.f);
                #pragma unroll
                for (int n1 = 0; n1 < 16; n1++)
                    cmaddc(acc, u[n1], W16C[(k1*n1)&15], W16S[(k1*n1)&15]);
                Ab[r*768 + (n3*16 + k1)*16 + n2] = cmul(acc, stw256[n2*k1]);
            }
        }
    }
    __syncthreads();
    if (l < 48) {
        const int n3 = l >> 4, k1 = l & 15;
        float2 v[16];
        #pragma unroll
        for (int n2 = 0; n2 < 16; n2++) v[n2] = Ab[r*768 + (n3*16 + k1)*16 + n2];
        #pragma unroll
        for (int k2 = 0; k2 < 16; k2++) {
            float2 acc = make_float2(0.f, 0.f);
            #pragma unroll
            for (int n2 = 0; n2 < 16; n2++)
                cmaddc(acc, v[n2], W16C[(k2*n2)&15], W16S[(k2*n2)&15]);
            zb[r*768 + (n3*16 + k1)*16 + k2] = acc;
        }
    }
    __syncthreads();
    {
        float2* dst = RIN ? g_A : g_B;
        const float s3 = 0.86602540378443865f;
        #pragma unroll
        for (int q = 0; q < 4; q++) {
            const int m = l + 64*q;
            const int k1 = m & 15, k2 = m >> 4;
            float2 b0 = zb[r*768 +       k1*16 + k2];
            float2 b1 = cmul(zb[r*768 + 256 + k1*16 + k2], stw768[m]);
            float2 b2 = cmul(zb[r*768 + 512 + k1*16 + k2], stw768[2*m]);
            float2 t1 = make_float2(b1.x + b2.x, b1.y + b2.y);
            float2 t2 = make_float2(b1.x - b2.x, b1.y - b2.y);
            dst[row*768 + m] = make_float2(b0.x + t1.x, b0.y + t1.y);
            float xr = fmaf(-0.5f, t1.x, b0.x);
            float xi = fmaf(-0.5f, t1.y, b0.y);
            dst[row*768 + m + 256] = make_float2(fmaf( s3, t2.y, xr), fmaf(-s3, t2.x, xi));
            dst[row*768 + m + 512] = make_float2(fmaf(-s3, t2.y, xr), fmaf( s3, t2.x, xi));
        }
    }
}

// ---------------- H-FFT (128=16x8, const twiddles) + length-2 B-FFT, direct-load ----------------
template<int SWAP>
__global__ __launch_bounds__(128) void kFHB()
{
    __shared__ float2 Ys[2][16][8][8];   // [bb][k1][n2][c]
    __shared__ float2 stw[128];
    const float2* src = SWAP ? g_A : g_B;
    float2* dst = SWAP ? g_B : g_A;
    const int kw = blockIdx.x, c0 = blockIdx.y * 8, tid = threadIdx.x;
    stw[tid] = g_tw128[tid];
    {   // stage1: thread = (bb,n2,c); load both batches directly, DFT-16 over n1
        const int c = tid & 7, n2 = (tid >> 3) & 7, bb = tid >> 6;
        float2 u[16];
        #pragma unroll
        for (int n1 = 0; n1 < 16; n1++) {
            size_t h = (size_t)(8*n1 + n2);
            float2 a = src[(h*KWV + kw)*CCH + c0 + c];
            float2 b = src[(((size_t)HH + h)*KWV + kw)*CCH + c0 + c];
            u[n1] = bb ? make_float2(a.x - b.x, a.y - b.y)
                       : make_float2(a.x + b.x, a.y + b.y);
        }
        __syncthreads();   // stw visible
        #pragma unroll
        for (int k1 = 0; k1 < 16; k1++) {
            float2 acc = make_float2(0.f, 0.f);
            #pragma unroll
            for (int n1 = 0; n1 < 16; n1++)
                cmaddc(acc, u[n1], W16C[(k1*n1)&15], W16S[(k1*n1)&15]);
            Ys[bb][k1][n2][c] = cmul(acc, stw[k1*n2]);
        }
    }
    __syncthreads();
    #pragma unroll
    for (int r = 0; r < 2; r++) {
        int t = tid + 128*r;
        int c = t & 7, k1 = (t >> 3) & 15, bb = t >> 7;
        float2 v[8];
        #pragma unroll
        for (int n2 = 0; n2 < 8; n2++) v[n2] = Ys[bb][k1][n2][c];
        #pragma unroll
        for (int k2 = 0; k2 < 8; k2++) {
            float2 acc = make_float2(0.f, 0.f);
            #pragma unroll
            for (int n2 = 0; n2 < 8; n2++)
                cmaddc(acc, v[n2], W16C[(2*k2*n2)&15], W16S[(2*k2*n2)&15]);
            dst[(((size_t)bb*HH + k1 + 16*k2)*KWV + kw)*CCH + c0 + c] = acc;
        }
    }
}

// ---------------- fused MLP (Karatsuba + f32x2): g_A,x -> s (float) in g_B ----------------
// thread map: og = tid>>4 (output group, ob=og*6), pg = tid&15 (position group, pb=pg*4)
#define SST 68   // activation row stride (floats): even*? 68*4=272 = 16*17 -> 16B-aligned rows

__device__ __forceinline__ void gemv6p(const float* sS, const float* sD,
                                       const float* sW0, const float* sW1,
                                       int pb, int ob, u64 aU[2][6], u64 aV[2][6])
{
    #pragma unroll
    for (int i = 0; i < 2; i++)
        #pragma unroll
        for (int j = 0; j < 6; j++) { aU[i][j] = 0ull; aV[i][j] = 0ull; }
    for (int k = 0; k < 96; k++) {
        ulonglong2 sv = *(const ulonglong2*)(sS + k*SST + pb);
        ulonglong2 dv = *(const ulonglong2*)(sD + k*SST + pb);
        float2 wa = *(const float2*)(sW0 + k*96 + ob);
        float2 wb = *(const float2*)(sW0 + k*96 + ob + 2);
        float2 wc = *(const float2*)(sW0 + k*96 + ob + 4);
        float2 va = *(const float2*)(sW1 + k*96 + ob);
        float2 vb = *(const float2*)(sW1 + k*96 + ob + 2);
        float2 vc = *(const float2*)(sW1 + k*96 + ob + 4);
        u64 w0d[6], w1d[6];
        w0d[0]=pk2(wa.x); w0d[1]=pk2(wa.y); w0d[2]=pk2(wb.x);
        w0d[3]=pk2(wb.y); w0d[4]=pk2(wc.x); w0d[5]=pk2(wc.y);
        w1d[0]=pk2(va.x); w1d[1]=pk2(va.y); w1d[2]=pk2(vb.x);
        w1d[3]=pk2(vb.y); w1d[4]=pk2(vc.x); w1d[5]=pk2(vc.y);
        #pragma unroll
        for (int j = 0; j < 6; j++) {
            f2fma(aU[0][j], sv.x, w0d[j]);
            f2fma(aU[1][j], sv.y, w0d[j]);
            f2fma(aV[0][j], dv.x, w1d[j]);
            f2fma(aV[1][j], dv.y, w1d[j]);
        }
    }
}
__device__ __forceinline__ void unpack46(u64 a2[2][6], float o[4][6])
{
    #pragma unroll
    for (int j = 0; j < 6; j++) {
        float2 t0 = up2(a2[0][j]), t1 = up2(a2[1][j]);
        o[0][j] = t0.x; o[1][j] = t0.y; o[2][j] = t1.x; o[3][j] = t1.y;
    }
}

__global__ __launch_bounds__(256) void kMLP(const float* __restrict__ x,
    const float* __restrict__ w1, const float* __restrict__ b1,
    const float* __restrict__ w2, const float* __restrict__ b2)
{
    extern __shared__ float smp[];
    float* sW0 = smp;             // 9216
    float* sW1 = smp + 9216;      // 9216
    float* sS  = smp + 18432;     // 96*SST = 6528
    float* sD  = smp + 24960;     // 6528
    const int n = blockIdx.y, p0 = blockIdx.x * 64, tid = threadIdx.x;
    const int og = tid >> 4, pg = tid & 15, ob = og*6, pb = pg*4;

    const float4* W10 = (const float4*)(w1 + (size_t)n*9216);
    const float4* W11 = (const float4*)(w1 + (size_t)(NB+n)*9216);
    for (int e = tid; e < 2304; e += 256) {
        ((float4*)sW0)[e] = W10[e];
        ((float4*)sW1)[e] = W11[e];
    }
    for (int e = tid; e < 6144; e += 256) {
        int p = e / 96, c = e - 96*p;
        int pgl = p0 + p;
        int b = (pgl >= HH*KWV) ? 1 : 0;
        int r = pgl - b*(HH*KWV);
        int h = r / KWV, kw = r - h*KWV;
        float2 z = g_A[(size_t)pgl*CCH + n*BS + c];
        float av = z.x + z.y;
        int hn = (HH - h) & (HH-1), wn = (WW - kw) & (WW-1);
        float an = x[(((size_t)b*HH + hn)*WW + wn)*CCH + n*BS + c];
        sS[c*SST + p] = av + an;
        sD[c*SST + p] = av - an;
    }
    __syncthreads();

    u64 aU2[2][6], aV2[2][6];
    float U[4][6], V[4][6], keep[4][6];
    gemv6p(sS, sD, sW0, sW1, pb, ob, aU2, aV2);
    unpack46(aU2, U); unpack46(aV2, V);
    float bk[6], bn[6];
    #pragma unroll
    for (int j = 0; j < 6; j++) { bk[j] = b1[n*BS + ob + j]; bn[j] = b1[(NB+n)*BS + ob + j]; }
    __syncthreads();
    #pragma unroll
    for (int i = 0; i < 4; i++)
        #pragma unroll
        for (int j = 0; j < 6; j++) {
            float o1k = fmaxf(fmaf(0.5f, U[i][j] + V[i][j], bk[j]), 0.f);
            float o1n = fmaxf(fmaf(0.5f, U[i][j] - V[i][j], bn[j]), 0.f);
            keep[i][j] = o1n;
            sS[(ob+j)*SST + pb + i] = o1k + o1n;
            sD[(ob+j)*SST + pb + i] = o1k - o1n;
        }
    const float4* W20 = (const float4*)(w2 + (size_t)n*9216);
    const float4* W21 = (const float4*)(w2 + (size_t)(NB+n)*9216);
    for (int e = tid; e < 2304; e += 256) {
        ((float4*)sW0)[e] = W20[e];
        ((float4*)sW1)[e] = W21[e];
    }
    __syncthreads();

    gemv6p(sS, sD, sW0, sW1, pb, ob, aU2, aV2);
    unpack46(aU2, U); unpack46(aV2, V);
    #pragma unroll
    for (int j = 0; j < 6; j++) { bk[j] = b2[n*BS + ob + j]; bn[j] = b2[(NB+n)*BS + ob + j]; }
    __syncthreads();
    #pragma unroll
    for (int i = 0; i < 4; i++)
        #pragma unroll
        for (int j = 0; j < 6; j++) {
            float ok = fmaf(0.5f, U[i][j] + V[i][j], bk[j]);
            float un = keep[i][j];
            sS[(ob+j)*SST + pb + i] = un + ok;
            sD[(ob+j)*SST + pb + i] = un - ok;   // o2_nk uses o2_k (reference quirk)
            keep[i][j] = ok;
        }
    __syncthreads();

    gemv6p(sS, sD, sW0, sW1, pb, ob, aU2, aV2);
    unpack46(aU2, U); unpack46(aV2, V);
    __syncthreads();   // done reading sW0 (weights) before reuse as staging
    #pragma unroll
    for (int i = 0; i < 4; i++)
        #pragma unroll
        for (int j = 0; j < 6; j++) {
            float o2n = fmaf(0.5f, U[i][j] + V[i][j], bn[j]);
            float t = keep[i][j] + o2n;
            sW0[(ob+j)*SST + pb + i] = copysignf(fmaxf(fabsf(t) - 0.01f, 0.f), t);
        }
    __syncthreads();
    float* outp = (float*)g_B;
    for (int e = tid; e < 6144; e += 256) {
        int p = e / 96, c = e - 96*p;
        outp[(size_t)(p0 + p)*CCH + n*BS + c] = sW0[c*SST + p];
    }
}

// ---------------- inverse W-FFT (65 -> 256) + scale + residual : g_B -> out ----------------
__global__ __launch_bounds__(256) void kIW(const float* __restrict__ x, float* __restrict__ out)
{
    __shared__ float2 Ys[256*17];
    __shared__ float2 stw[256];
    const int bh = blockIdx.x, c0 = blockIdx.y * 16, tid = threadIdx.x;
    if (tid < 256) stw[tid] = g_tw256[tid];
    __syncthreads();
    const float2* zp = g_B + (size_t)bh*KWV*CCH + c0;
    for (int e = tid; e < 4096; e += 256) {
        int c = e & 15, n2 = (e >> 4) & 15, k1 = e >> 8;
        float2 acc = make_float2(0.f, 0.f);
        int idx = (k1 * n2) & 255, step = (k1 * 16) & 255;
        int nmax = (n2 == 0) ? 5 : 4;
        for (int n1 = 0; n1 < nmax; n1++) {
            int w = (n1 << 4) + n2;
            float2 z = __ldg(&zp[(size_t)w*CCH + c]);
            cmadd(acc, z, stw[idx]);
            idx = (idx + step) & 255;
        }
        Ys[(k1*16 + n2)*17 + c] = acc;
    }
    __syncthreads();
    const float invN = 1.0f / 50331648.0f;
    {
        const int k1 = tid >> 4, c = tid & 15;
        float2 v[16];
        #pragma unroll
        for (int n2 = 0; n2 < 16; n2++) v[n2] = Ys[(k1*16 + n2)*17 + c];
        #pragma unroll
        for (int k2 = 0; k2 < 16; k2++) {
            float2 acc = make_float2(0.f, 0.f);
            #pragma unroll
            for (int n2 = 0; n2 < 16; n2++)
                cmaddc(acc, v[n2], W16C[(k2*n2)&15], W16S[(k2*n2)&15]);
            size_t a = ((size_t)bh*WW + k1 + 16*k2)*CCH + c0 + c;
            out[a] = fmaf(acc.x + acc.y, invN, x[a]);
        }
    }
}

extern "C" void kernel_launch(void* const* d_in, const int* in_sizes, int n_in,
                              void* d_out, int out_size)
{
    const float* x  = (const float*)d_in[0];
    const float* w1 = (const float*)d_in[1];
    const float* b1 = (const float*)d_in[2];
    const float* w2 = (const float*)d_in[3];
    const float* b2 = (const float*)d_in[4];
    float* out = (float*)d_out;

    cudaFuncSetAttribute(kMLP,   cudaFuncAttributeMaxDynamicSharedMemorySize, 31488*4);
    cudaFuncSetAttribute(kF1,    cudaFuncAttributeMaxDynamicSharedMemorySize, 54272);
    cudaFuncSetAttribute(kFC<0>, cudaFuncAttributeMaxDynamicSharedMemorySize, 55296);
    cudaFuncSetAttribute(kFC<1>, cudaFuncAttributeMaxDynamicSharedMemorySize, 55296);

    kPrep<<<3, 256>>>();
    kF1 <<<dim3(BB*HH, CCH/16), 256, 54272>>>(x);   // x -> A
    kFC<0><<<NPOS/4, 256, 55296>>>();               // A -> B
    kFHB<0><<<dim3(KWV, CCH/8), 128>>>();           // B -> A
    kMLP<<<dim3(NPOS/64, NB), 256, 31488*4>>>(x, w1, b1, w2, b2);  // A,x -> s in B
    kFC<1><<<NPOS/4, 256, 55296>>>();               // B(real) -> A
    kFHB<1><<<dim3(KWV, CCH/8), 128>>>();           // A -> B
    kIW <<<dim3(BB*HH, CCH/16), 256>>>(x, out);     // B -> out
}

// round 7
// speedup vs baseline: 2.8476x; 1.0342x over previous
#include <cuda_runtime.h>
#include <math.h>
#include <stdint.h>

#define BB 2
#define HH 128
#define WW 256
#define CCH 768
#define KWV 65
#define NB 8
#define BS 96
#define NPOS (BB*HH*KWV)
#define SLABN (NPOS*CCH)

typedef unsigned long long u64;

__device__ float2 g_A[SLABN];
__device__ float2 g_B[SLABN];
__device__ float2 g_tw256[256];
__device__ float2 g_tw768[768];
__device__ float2 g_tw128[128];

__device__ constexpr float W16C[16] = {
  1.0f, 0.92387953251128674f, 0.70710678118654752f, 0.38268343236508977f,
  0.0f,-0.38268343236508977f,-0.70710678118654752f,-0.92387953251128674f,
 -1.0f,-0.92387953251128674f,-0.70710678118654752f,-0.38268343236508977f,
  0.0f, 0.38268343236508977f, 0.70710678118654752f, 0.92387953251128674f};
__device__ constexpr float W16S[16] = {
  0.0f,-0.38268343236508977f,-0.70710678118654752f,-0.92387953251128674f,
 -1.0f,-0.92387953251128674f,-0.70710678118654752f,-0.38268343236508977f,
  0.0f, 0.38268343236508977f, 0.70710678118654752f, 0.92387953251128674f,
  1.0f, 0.92387953251128674f, 0.70710678118654752f, 0.38268343236508977f};

__device__ __forceinline__ void cmadd(float2& acc, float2 z, float2 t) {
    acc.x = fmaf(z.x, t.x, fmaf(-z.y, t.y, acc.x));
    acc.y = fmaf(z.x, t.y, fmaf( z.y, t.x, acc.y));
}
__device__ __forceinline__ void cmaddc(float2& acc, float2 z, float C, float S) {
    acc.x = fmaf(z.x, C, fmaf(-z.y, S, acc.x));
    acc.y = fmaf(z.x, S, fmaf( z.y, C, acc.y));
}
__device__ __forceinline__ float2 cmul(float2 a, float2 b) {
    return make_float2(a.x*b.x - a.y*b.y, a.x*b.y + a.y*b.x);
}
// packed f32x2 helpers
__device__ __forceinline__ u64 pk2(float v) {
    u64 r; asm("mov.b64 %0, {%1, %1};" : "=l"(r) : "f"(v)); return r;
}
__device__ __forceinline__ void f2fma(u64& acc, u64 a, u64 b) {
    asm("fma.rn.f32x2 %0, %1, %2, %0;" : "+l"(acc) : "l"(a), "l"(b));
}
__device__ __forceinline__ float2 up2(u64 a) {
    float2 f; asm("mov.b64 {%0, %1}, %2;" : "=f"(f.x), "=f"(f.y) : "l"(a)); return f;
}

__global__ void kPrep()
{
    int t = blockIdx.x * blockDim.x + threadIdx.x;
    const double TP = 6.283185307179586476925286766559;
    if (t < 768) {
        double s, c;
        sincos(-TP * (double)t / 768.0, &s, &c);
        g_tw768[t] = make_float2((float)c, (float)s);
        if (t < 256) { sincos(-TP*(double)t/256.0, &s, &c); g_tw256[t] = make_float2((float)c,(float)s); }
        if (t < 128) { sincos(-TP*(double)t/128.0, &s, &c); g_tw128[t] = make_float2((float)c,(float)s); }
    }
}

// ---------------- forward W-FFT (256=16x16, const-twiddle) pruned kw<65 : x -> g_A ----------------
__global__ __launch_bounds__(256) void kF1(const float* __restrict__ x)
{
    extern __shared__ float smF1[];
    float*  Xs  = smF1;
    float2* Ys  = (float2*)(smF1 + 4352);
    float2* stw = Ys + 4352;
    const int bh = blockIdx.x, c0 = blockIdx.y * 16, tid = threadIdx.x;
    if (tid < 256) stw[tid] = g_tw256[tid];
    const float* xp = x + (size_t)bh * (WW*CCH) + c0;
    for (int e = tid; e < 4096; e += 256)
        Xs[(e >> 4)*17 + (e & 15)] = xp[(size_t)(e >> 4) * CCH + (e & 15)];
    __syncthreads();
    {
        const int n2 = tid >> 4, c = tid & 15;
        float u[16];
        #pragma unroll
        for (int n1 = 0; n1 < 16; n1++) u[n1] = Xs[(16*n1 + n2)*17 + c];
        #pragma unroll
        for (int k1 = 0; k1 < 16; k1++) {
            float re = 0.f, im = 0.f;
            #pragma unroll
            for (int n1 = 0; n1 < 16; n1++) {
                re = fmaf(u[n1], W16C[(k1*n1)&15], re);
                im = fmaf(u[n1], W16S[(k1*n1)&15], im);
            }
            Ys[(k1*16 + n2)*17 + c] = cmul(make_float2(re, im), stw[n2*k1]);
        }
    }
    __syncthreads();
    {
        const int k1 = tid >> 4, c = tid & 15;
        float2 v[16];
        #pragma unroll
        for (int n2 = 0; n2 < 16; n2++) v[n2] = Ys[(k1*16 + n2)*17 + c];
        float2* dst = g_A + ((size_t)bh*KWV)*CCH + c0 + c;
        #pragma unroll
        for (int k2 = 0; k2 < 4; k2++) {
            float2 acc = make_float2(0.f, 0.f);
            #pragma unroll
            for (int n2 = 0; n2 < 16; n2++)
                cmaddc(acc, v[n2], W16C[(k2*n2)&15], W16S[(k2*n2)&15]);
            dst[(size_t)(k1 + 16*k2)*CCH] = acc;
        }
        if (k1 == 0) {
            float2 acc = make_float2(0.f, 0.f);
            #pragma unroll
            for (int n2 = 0; n2 < 16; n2++)
                cmaddc(acc, v[n2], W16C[(4*n2)&15], W16S[(4*n2)&15]);
            dst[(size_t)64*CCH] = acc;
        }
    }
}

// ---------------- C-FFT 768 = 16x16x3, const twiddles, 192 threads (no idle lanes) ----------------
template<int RIN>
__global__ __launch_bounds__(192) void kFC()
{
    extern __shared__ float2 smC[];
    float2* zb = smC;            // 4*768
    float2* Ab = smC + 3072;     // 4*768
    float2* stw256 = smC + 6144; // 256
    float2* stw768 = smC + 6400; // 512
    const int tid = threadIdx.x;
    const int r = tid / 48, l = tid - r*48;
    const size_t row0 = (size_t)blockIdx.x * 4;
    for (int e = tid; e < 256; e += 192) stw256[e] = g_tw256[e];
    for (int e = tid; e < 512; e += 192) stw768[e] = g_tw768[e];
    if (RIN) {
        const float* sp = (const float*)g_B;
        for (int e = tid; e < 3072; e += 192)
            zb[e] = make_float2(sp[row0*768 + e], 0.f);
    } else {
        for (int e = tid; e < 3072; e += 192)
            zb[e] = g_A[row0*768 + e];
    }
    __syncthreads();
    {   // stage1: (r, n3, n2): DFT-16 over n1 (const), then x tw256[n2*k1]
        const int n3 = l >> 4, n2 = l & 15;
        if (RIN) {
            float u[16];
            #pragma unroll
            for (int n1 = 0; n1 < 16; n1++) u[n1] = zb[r*768 + n3 + 3*n2 + 48*n1].x;
            #pragma unroll
            for (int k1 = 0; k1 < 16; k1++) {
                float re = 0.f, im = 0.f;
                #pragma unroll
                for (int n1 = 0; n1 < 16; n1++) {
                    re = fmaf(u[n1], W16C[(k1*n1)&15], re);
                    im = fmaf(u[n1], W16S[(k1*n1)&15], im);
                }
                Ab[r*768 + (n3*16 + k1)*16 + n2] = cmul(make_float2(re, im), stw256[n2*k1]);
            }
        } else {
            float2 u[16];
            #pragma unroll
            for (int n1 = 0; n1 < 16; n1++) u[n1] = zb[r*768 + n3 + 3*n2 + 48*n1];
            #pragma unroll
            for (int k1 = 0; k1 < 16; k1++) {
                float2 acc = make_float2(0.f, 0.f);
                #pragma unroll
                for (int n1 = 0; n1 < 16; n1++)
                    cmaddc(acc, u[n1], W16C[(k1*n1)&15], W16S[(k1*n1)&15]);
                Ab[r*768 + (n3*16 + k1)*16 + n2] = cmul(acc, stw256[n2*k1]);
            }
        }
    }
    __syncthreads();
    {   // stage2: (r, n3, k1): const DFT-16 over n2
        const int n3 = l >> 4, k1 = l & 15;
        float2 v[16];
        #pragma unroll
        for (int n2 = 0; n2 < 16; n2++) v[n2] = Ab[r*768 + (n3*16 + k1)*16 + n2];
        #pragma unroll
        for (int k2 = 0; k2 < 16; k2++) {
            float2 acc = make_float2(0.f, 0.f);
            #pragma unroll
            for (int n2 = 0; n2 < 16; n2++)
                cmaddc(acc, v[n2], W16C[(k2*n2)&15], W16S[(k2*n2)&15]);
            zb[r*768 + (n3*16 + k1)*16 + k2] = acc;
        }
    }
    __syncthreads();
    {   // stage3: radix-3 combine
        float2* dst = RIN ? g_A : g_B;
        const float s3 = 0.86602540378443865f;
        for (int e = tid; e < 1024; e += 192) {
            const int rr = e >> 8, m = e & 255;
            const int k1 = m & 15, k2 = m >> 4;
            float2 b0 = zb[rr*768 +       k1*16 + k2];
            float2 b1 = cmul(zb[rr*768 + 256 + k1*16 + k2], stw768[m]);
            float2 b2 = cmul(zb[rr*768 + 512 + k1*16 + k2], stw768[2*m]);
            float2 t1 = make_float2(b1.x + b2.x, b1.y + b2.y);
            float2 t2 = make_float2(b1.x - b2.x, b1.y - b2.y);
            dst[(row0+rr)*768 + m] = make_float2(b0.x + t1.x, b0.y + t1.y);
            float xr = fmaf(-0.5f, t1.x, b0.x);
            float xi = fmaf(-0.5f, t1.y, b0.y);
            dst[(row0+rr)*768 + m + 256] = make_float2(fmaf( s3, t2.y, xr), fmaf(-s3, t2.x, xi));
            dst[(row0+rr)*768 + m + 512] = make_float2(fmaf(-s3, t2.y, xr), fmaf( s3, t2.x, xi));
        }
    }
}

// ---------------- H-FFT (128=16x8, const twiddles) + length-2 B-FFT, direct-load ----------------
template<int SWAP>
__global__ __launch_bounds__(128) void kFHB()
{
    __shared__ float2 Ys[2][16][8][8];
    __shared__ float2 stw[128];
    const float2* src = SWAP ? g_A : g_B;
    float2* dst = SWAP ? g_B : g_A;
    const int kw = blockIdx.x, c0 = blockIdx.y * 8, tid = threadIdx.x;
    stw[tid] = g_tw128[tid];
    {
        const int c = tid & 7, n2 = (tid >> 3) & 7, bb = tid >> 6;
        float2 u[16];
        #pragma unroll
        for (int n1 = 0; n1 < 16; n1++) {
            size_t h = (size_t)(8*n1 + n2);
            float2 a = src[(h*KWV + kw)*CCH + c0 + c];
            float2 b = src[(((size_t)HH + h)*KWV + kw)*CCH + c0 + c];
            u[n1] = bb ? make_float2(a.x - b.x, a.y - b.y)
                       : make_float2(a.x + b.x, a.y + b.y);
        }
        __syncthreads();
        #pragma unroll
        for (int k1 = 0; k1 < 16; k1++) {
            float2 acc = make_float2(0.f, 0.f);
            #pragma unroll
            for (int n1 = 0; n1 < 16; n1++)
                cmaddc(acc, u[n1], W16C[(k1*n1)&15], W16S[(k1*n1)&15]);
            Ys[bb][k1][n2][c] = cmul(acc, stw[k1*n2]);
        }
    }
    __syncthreads();
    #pragma unroll
    for (int r = 0; r < 2; r++) {
        int t = tid + 128*r;
        int c = t & 7, k1 = (t >> 3) & 15, bb = t >> 7;
        float2 v[8];
        #pragma unroll
        for (int n2 = 0; n2 < 8; n2++) v[n2] = Ys[bb][k1][n2][c];
        #pragma unroll
        for (int k2 = 0; k2 < 8; k2++) {
            float2 acc = make_float2(0.f, 0.f);
            #pragma unroll
            for (int n2 = 0; n2 < 8; n2++)
                cmaddc(acc, v[n2], W16C[(2*k2*n2)&15], W16S[(2*k2*n2)&15]);
            dst[(((size_t)bb*HH + k1 + 16*k2)*KWV + kw)*CCH + c0 + c] = acc;
        }
    }
}

// ---------------- fused MLP (Karatsuba + f32x2, 4pos x 12out tiles): g_A,x -> s in g_B ----------------
#define SST 132   // 128 positions + 4 pad floats; 528B rows, 16B-aligned
#define MP  128   // positions per block

__device__ __forceinline__ void gemv12(const float* __restrict__ sS, const float* __restrict__ sD,
                                       const float* __restrict__ sW0, const float* __restrict__ sW1,
                                       int pb, int ob, u64 aU[4][6], u64 aV[4][6])
{
    #pragma unroll
    for (int i = 0; i < 4; i++)
        #pragma unroll
        for (int j = 0; j < 6; j++) { aU[i][j] = 0ull; aV[i][j] = 0ull; }
    for (int k = 0; k < 96; k++) {
        float4 s4 = *(const float4*)(sS + k*SST + pb);
        float4 d4 = *(const float4*)(sD + k*SST + pb);
        ulonglong2 wA = *(const ulonglong2*)(sW0 + k*96 + ob);
        ulonglong2 wB = *(const ulonglong2*)(sW0 + k*96 + ob + 4);
        ulonglong2 wC = *(const ulonglong2*)(sW0 + k*96 + ob + 8);
        ulonglong2 vA = *(const ulonglong2*)(sW1 + k*96 + ob);
        ulonglong2 vB = *(const ulonglong2*)(sW1 + k*96 + ob + 4);
        ulonglong2 vC = *(const ulonglong2*)(sW1 + k*96 + ob + 8);
        u64 w0[6] = {wA.x, wA.y, wB.x, wB.y, wC.x, wC.y};
        u64 w1v[6] = {vA.x, vA.y, vB.x, vB.y, vC.x, vC.y};
        u64 sp[4] = {pk2(s4.x), pk2(s4.y), pk2(s4.z), pk2(s4.w)};
        u64 dp[4] = {pk2(d4.x), pk2(d4.y), pk2(d4.z), pk2(d4.w)};
        #pragma unroll
        for (int i = 0; i < 4; i++)
            #pragma unroll
            for (int j = 0; j < 6; j++) {
                f2fma(aU[i][j], sp[i], w0[j]);
                f2fma(aV[i][j], dp[i], w1v[j]);
            }
    }
}

__global__ __launch_bounds__(256) void kMLP(const float* __restrict__ x,
    const float* __restrict__ w1, const float* __restrict__ b1,
    const float* __restrict__ w2, const float* __restrict__ b2)
{
    extern __shared__ float smp[];
    float* sW0 = smp;              // 9216
    float* sW1 = smp + 9216;       // 9216
    float* sS  = smp + 18432;      // 96*SST = 12672
    float* sD  = smp + 31104;      // 12672 -> total 43776 floats = 175104 B
    const int n = blockIdx.y, p0 = blockIdx.x * MP, tid = threadIdx.x;
    const int og = tid >> 5, pg = tid & 31;      // og warp-uniform -> weight broadcast
    const int ob = og * 12, pb = pg * 4;

    const float4* W10 = (const float4*)(w1 + (size_t)n*9216);
    const float4* W11 = (const float4*)(w1 + (size_t)(NB+n)*9216);
    for (int e = tid; e < 2304; e += 256) {
        ((float4*)sW0)[e] = W10[e];
        ((float4*)sW1)[e] = W11[e];
    }
    for (int e = tid; e < MP*96; e += 256) {
        int p = e / 96, c = e - 96*p;
        int pgl = p0 + p;
        int b = (pgl >= HH*KWV) ? 1 : 0;
        int r = pgl - b*(HH*KWV);
        int h = r / KWV, kw = r - h*KWV;
        float2 z = g_A[(size_t)pgl*CCH + n*BS + c];
        float av = z.x + z.y;
        int hn = (HH - h) & (HH-1), wn = (WW - kw) & (WW-1);
        float an = x[(((size_t)b*HH + hn)*WW + wn)*CCH + n*BS + c];
        sS[c*SST + p] = av + an;
        sD[c*SST + p] = av - an;
    }
    __syncthreads();

    u64 aU[4][6], aV[4][6];
    float keep[4][12];
    float bk[12], bn[12];

    // =============== layer 1 ===============
    gemv12(sS, sD, sW0, sW1, pb, ob, aU, aV);
    #pragma unroll
    for (int j = 0; j < 12; j++) { bk[j] = b1[n*BS + ob + j]; bn[j] = b1[(NB+n)*BS + ob + j]; }
    __syncthreads();
    #pragma unroll
    for (int jp = 0; jp < 6; jp++) {
        float4 vs0, vd0, vs1, vd1;
        #pragma unroll
        for (int i = 0; i < 4; i++) {
            float2 u = up2(aU[i][jp]), v = up2(aV[i][jp]);
            float k0 = fmaxf(fmaf(0.5f, u.x + v.x, bk[2*jp]),   0.f);
            float n0 = fmaxf(fmaf(0.5f, u.x - v.x, bn[2*jp]),   0.f);
            float k1 = fmaxf(fmaf(0.5f, u.y + v.y, bk[2*jp+1]), 0.f);
            float n1 = fmaxf(fmaf(0.5f, u.y - v.y, bn[2*jp+1]), 0.f);
            keep[i][2*jp] = n0; keep[i][2*jp+1] = n1;
            ((float*)&vs0)[i] = k0 + n0; ((float*)&vd0)[i] = k0 - n0;
            ((float*)&vs1)[i] = k1 + n1; ((float*)&vd1)[i] = k1 - n1;
        }
        *(float4*)(sS + (ob+2*jp  )*SST + pb) = vs0;
        *(float4*)(sD + (ob+2*jp  )*SST + pb) = vd0;
        *(float4*)(sS + (ob+2*jp+1)*SST + pb) = vs1;
        *(float4*)(sD + (ob+2*jp+1)*SST + pb) = vd1;
    }
    const float4* W20 = (const float4*)(w2 + (size_t)n*9216);
    const float4* W21 = (const float4*)(w2 + (size_t)(NB+n)*9216);
    for (int e = tid; e < 2304; e += 256) {
        ((float4*)sW0)[e] = W20[e];
        ((float4*)sW1)[e] = W21[e];
    }
    __syncthreads();

    // =============== layer 2 (o2_k) ===============
    gemv12(sS, sD, sW0, sW1, pb, ob, aU, aV);
    #pragma unroll
    for (int j = 0; j < 12; j++) { bk[j] = b2[n*BS + ob + j]; bn[j] = b2[(NB+n)*BS + ob + j]; }
    __syncthreads();
    #pragma unroll
    for (int jp = 0; jp < 6; jp++) {
        float4 vs0, vd0, vs1, vd1;
        #pragma unroll
        for (int i = 0; i < 4; i++) {
            float2 u = up2(aU[i][jp]), v = up2(aV[i][jp]);
            float ok0 = fmaf(0.5f, u.x + v.x, bk[2*jp]);
            float ok1 = fmaf(0.5f, u.y + v.y, bk[2*jp+1]);
            float un0 = keep[i][2*jp], un1 = keep[i][2*jp+1];
            keep[i][2*jp] = ok0; keep[i][2*jp+1] = ok1;
            ((float*)&vs0)[i] = un0 + ok0; ((float*)&vd0)[i] = un0 - ok0;  // o2_nk uses o2_k
            ((float*)&vs1)[i] = un1 + ok1; ((float*)&vd1)[i] = un1 - ok1;
        }
        *(float4*)(sS + (ob+2*jp  )*SST + pb) = vs0;
        *(float4*)(sD + (ob+2*jp  )*SST + pb) = vd0;
        *(float4*)(sS + (ob+2*jp+1)*SST + pb) = vs1;
        *(float4*)(sD + (ob+2*jp+1)*SST + pb) = vd1;
    }
    __syncthreads();

    // =============== layer 2 (o2_nk) + soft-threshold ===============
    gemv12(sS, sD, sW0, sW1, pb, ob, aU, aV);
    __syncthreads();
    #pragma unroll
    for (int jp = 0; jp < 6; jp++) {
        float4 vs0, vs1;
        #pragma unroll
        for (int i = 0; i < 4; i++) {
            float2 u = up2(aU[i][jp]), v = up2(aV[i][jp]);
            float o2n0 = fmaf(0.5f, u.x + v.x, bn[2*jp]);
            float o2n1 = fmaf(0.5f, u.y + v.y, bn[2*jp+1]);
            float t0 = keep[i][2*jp]   + o2n0;
            float t1 = keep[i][2*jp+1] + o2n1;
            ((float*)&vs0)[i] = copysignf(fmaxf(fabsf(t0) - 0.01f, 0.f), t0);
            ((float*)&vs1)[i] = copysignf(fmaxf(fabsf(t1) - 0.01f, 0.f), t1);
        }
        *(float4*)(sS + (ob+2*jp  )*SST + pb) = vs0;
        *(float4*)(sS + (ob+2*jp+1)*SST + pb) = vs1;
    }
    __syncthreads();
    float* outp = (float*)g_B;
    for (int e = tid; e < MP*96; e += 256) {
        int p = e / 96, c = e - 96*p;
        outp[(size_t)(p0 + p)*CCH + n*BS + c] = sS[c*SST + p];
    }
}

// ---------------- inverse W-FFT (65 -> 256) + scale + residual : g_B -> out ----------------
__global__ __launch_bounds__(256) void kIW(const float* __restrict__ x, float* __restrict__ out)
{
    __shared__ float2 Ys[256*17];
    __shared__ float2 stw[256];
    const int bh = blockIdx.x, c0 = blockIdx.y * 16, tid = threadIdx.x;
    if (tid < 256) stw[tid] = g_tw256[tid];
    __syncthreads();
    const float2* zp = g_B + (size_t)bh*KWV*CCH + c0;
    for (int e = tid; e < 4096; e += 256) {
        int c = e & 15, n2 = (e >> 4) & 15, k1 = e >> 8;
        float2 acc = make_float2(0.f, 0.f);
        int idx = (k1 * n2) & 255, step = (k1 * 16) & 255;
        int nmax = (n2 == 0) ? 5 : 4;
        for (int n1 = 0; n1 < nmax; n1++) {
            int w = (n1 << 4) + n2;
            float2 z = __ldg(&zp[(size_t)w*CCH + c]);
            cmadd(acc, z, stw[idx]);
            idx = (idx + step) & 255;
        }
        Ys[(k1*16 + n2)*17 + c] = acc;
    }
    __syncthreads();
    const float invN = 1.0f / 50331648.0f;
    {
        const int k1 = tid >> 4, c = tid & 15;
        float2 v[16];
        #pragma unroll
        for (int n2 = 0; n2 < 16; n2++) v[n2] = Ys[(k1*16 + n2)*17 + c];
        #pragma unroll
        for (int k2 = 0; k2 < 16; k2++) {
            float2 acc = make_float2(0.f, 0.f);
            #pragma unroll
            for (int n2 = 0; n2 < 16; n2++)
                cmaddc(acc, v[n2], W16C[(k2*n2)&15], W16S[(k2*n2)&15]);
            size_t a = ((size_t)bh*WW + k1 + 16*k2)*CCH + c0 + c;
            out[a] = fmaf(acc.x + acc.y, invN, x[a]);
        }
    }
}

extern "C" void kernel_launch(void* const* d_in, const int* in_sizes, int n_in,
                              void* d_out, int out_size)
{
    const float* x  = (const float*)d_in[0];
    const float* w1 = (const float*)d_in[1];
    const float* b1 = (const float*)d_in[2];
    const float* w2 = (const float*)d_in[3];
    const float* b2 = (const float*)d_in[4];
    float* out = (float*)d_out;

    cudaFuncSetAttribute(kMLP,   cudaFuncAttributeMaxDynamicSharedMemorySize, 175104);
    cudaFuncSetAttribute(kF1,    cudaFuncAttributeMaxDynamicSharedMemorySize, 54272);
    cudaFuncSetAttribute(kFC<0>, cudaFuncAttributeMaxDynamicSharedMemorySize, 55296);
    cudaFuncSetAttribute(kFC<1>, cudaFuncAttributeMaxDynamicSharedMemorySize, 55296);

    kPrep<<<3, 256>>>();
    kF1 <<<dim3(BB*HH, CCH/16), 256, 54272>>>(x);   // x -> A
    kFC<0><<<NPOS/4, 192, 55296>>>();               // A -> B
    kFHB<0><<<dim3(KWV, CCH/8), 128>>>();           // B -> A
    kMLP<<<dim3(NPOS/MP, NB), 256, 175104>>>(x, w1, b1, w2, b2);  // A,x -> s in B
    kFC<1><<<NPOS/4, 192, 55296>>>();               // B(real) -> A
    kFHB<1><<<dim3(KWV, CCH/8), 128>>>();           // A -> B
    kIW <<<dim3(BB*HH, CCH/16), 256>>>(x, out);     // B -> out
}

// round 8
// speedup vs baseline: 2.9942x; 1.0515x over previous
#include <cuda_runtime.h>
#include <math.h>
#include <stdint.h>

#define BB 2
#define HH 128
#define WW 256
#define CCH 768
#define KWV 65
#define NB 8
#define BS 96
#define NPOS (BB*HH*KWV)
#define SLABN (NPOS*CCH)

typedef unsigned long long u64;

__device__ float2 g_A[SLABN];
__device__ float2 g_B[SLABN];
__device__ float2 g_tw256[256];
__device__ float2 g_tw768[768];
__device__ float2 g_tw128[128];

__device__ __forceinline__ void cmadd(float2& acc, float2 z, float2 t) {
    acc.x = fmaf(z.x, t.x, fmaf(-z.y, t.y, acc.x));
    acc.y = fmaf(z.x, t.y, fmaf( z.y, t.x, acc.y));
}
__device__ __forceinline__ float2 cmul(float2 a, float2 b) {
    return make_float2(a.x*b.x - a.y*b.y, a.x*b.y + a.y*b.x);
}
// packed f32x2 helpers
__device__ __forceinline__ u64 pk2(float v) {
    u64 r; asm("mov.b64 %0, {%1, %1};" : "=l"(r) : "f"(v)); return r;
}
__device__ __forceinline__ void f2fma(u64& acc, u64 a, u64 b) {
    asm("fma.rn.f32x2 %0, %1, %2, %0;" : "+l"(acc) : "l"(a), "l"(b));
}
__device__ __forceinline__ float2 up2(u64 a) {
    float2 f; asm("mov.b64 {%0, %1}, %2;" : "=f"(f.x), "=f"(f.y) : "l"(a)); return f;
}

// ---------------- register FFT primitives ----------------
#define FC1 0.92387953251128674f
#define FS1 0.38268343236508977f
#define FR  0.70710678118654752f

__device__ __forceinline__ float2 cadd2(float2 a, float2 b) {
    return make_float2(fmaf(b.x, 1.0f, a.x), fmaf(b.y, 1.0f, a.y));
}
__device__ __forceinline__ float2 csub2(float2 a, float2 b) {
    return make_float2(fmaf(b.x, -1.0f, a.x), fmaf(b.y, -1.0f, a.y));
}
__device__ __forceinline__ float2 cmulK(float2 z, float C, float S) {
    return make_float2(fmaf(z.x, C, -z.y*S), fmaf(z.y, C, z.x*S));
}
__device__ __forceinline__ void dft4(float2& a, float2& b, float2& c, float2& d) {
    float2 apc = cadd2(a, c), amc = csub2(a, c);
    float2 bpd = cadd2(b, d), bmd = csub2(b, d);
    float2 jb = make_float2(bmd.y, -bmd.x);   // -i * (b-d)
    a = cadd2(apc, bpd);
    b = cadd2(amc, jb);
    c = csub2(apc, bpd);
    d = csub2(amc, jb);
}
// 16-point FFT (W16 = e^{-2pi i/16}); output X[k] at v[FFI(k)]
#define FFI(k) (4*((k)&3) + ((k)>>2))
__device__ __forceinline__ void fft16r(float2 v[16]) {
    dft4(v[0], v[4], v[8],  v[12]);
    dft4(v[1], v[5], v[9],  v[13]);
    dft4(v[2], v[6], v[10], v[14]);
    dft4(v[3], v[7], v[11], v[15]);
    v[5]  = cmulK(v[5],  FC1, -FS1);
    v[6]  = cmulK(v[6],  FR,  -FR );
    v[7]  = cmulK(v[7],  FS1, -FC1);
    v[9]  = cmulK(v[9],  FR,  -FR );
    v[10] = make_float2(v[10].y, -v[10].x);
    v[11] = cmulK(v[11], -FR,  -FR );
    v[13] = cmulK(v[13], FS1, -FC1);
    v[14] = cmulK(v[14], -FR,  -FR );
    v[15] = cmulK(v[15], -FC1,  FS1);
    dft4(v[0],  v[1],  v[2],  v[3]);
    dft4(v[4],  v[5],  v[6],  v[7]);
    dft4(v[8],  v[9],  v[10], v[11]);
    dft4(v[12], v[13], v[14], v[15]);
}
// 8-point FFT, natural-order output
__device__ __forceinline__ void fft8r(float2 v[8]) {
    float2 a0 = cadd2(v[0], v[4]), a1 = cadd2(v[1], v[5]);
    float2 a2 = cadd2(v[2], v[6]), a3 = cadd2(v[3], v[7]);
    float2 b0 = csub2(v[0], v[4]);
    float2 t1 = csub2(v[1], v[5]);
    float2 t2 = csub2(v[2], v[6]);
    float2 t3 = csub2(v[3], v[7]);
    float2 b1 = cmulK(t1, FR, -FR);
    float2 b2 = make_float2(t2.y, -t2.x);
    float2 b3 = cmulK(t3, -FR, -FR);
    dft4(a0, a1, a2, a3);
    dft4(b0, b1, b2, b3);
    v[0] = a0; v[2] = a1; v[4] = a2; v[6] = a3;
    v[1] = b0; v[3] = b1; v[5] = b2; v[7] = b3;
}

__global__ void kPrep()
{
    int t = blockIdx.x * blockDim.x + threadIdx.x;
    const double TP = 6.283185307179586476925286766559;
    if (t < 768) {
        double s, c;
        sincos(-TP * (double)t / 768.0, &s, &c);
        g_tw768[t] = make_float2((float)c, (float)s);
        if (t < 256) { sincos(-TP*(double)t/256.0, &s, &c); g_tw256[t] = make_float2((float)c,(float)s); }
        if (t < 128) { sincos(-TP*(double)t/128.0, &s, &c); g_tw128[t] = make_float2((float)c,(float)s); }
    }
}

// ---------------- forward W-FFT (256=16x16) pruned kw<65 : x -> g_A ----------------
__global__ __launch_bounds__(256) void kF1(const float* __restrict__ x)
{
    extern __shared__ float smF1[];
    float*  Xs  = smF1;
    float2* Ys  = (float2*)(smF1 + 4352);
    float2* stw = Ys + 4352;
    const int bh = blockIdx.x, c0 = blockIdx.y * 16, tid = threadIdx.x;
    if (tid < 256) stw[tid] = g_tw256[tid];
    const float* xp = x + (size_t)bh * (WW*CCH) + c0;
    for (int e = tid; e < 4096; e += 256)
        Xs[(e >> 4)*17 + (e & 15)] = xp[(size_t)(e >> 4) * CCH + (e & 15)];
    __syncthreads();
    {
        const int n2 = tid >> 4, c = tid & 15;
        float2 u[16];
        #pragma unroll
        for (int n1 = 0; n1 < 16; n1++) u[n1] = make_float2(Xs[(16*n1 + n2)*17 + c], 0.f);
        fft16r(u);
        #pragma unroll
        for (int k1 = 0; k1 < 16; k1++)
            Ys[(k1*16 + n2)*17 + c] = cmul(u[FFI(k1)], stw[n2*k1]);
    }
    __syncthreads();
    {
        const int k1 = tid >> 4, c = tid & 15;
        float2 v[16];
        #pragma unroll
        for (int n2 = 0; n2 < 16; n2++) v[n2] = Ys[(k1*16 + n2)*17 + c];
        fft16r(v);
        float2* dst = g_A + ((size_t)bh*KWV)*CCH + c0 + c;
        #pragma unroll
        for (int k2 = 0; k2 < 4; k2++)
            dst[(size_t)(k1 + 16*k2)*CCH] = v[FFI(k2)];
        if (k1 == 0)
            dst[(size_t)64*CCH] = v[FFI(4)];
    }
}

// ---------------- C-FFT 768 = 16x16x3 : RIN=0: g_A->g_B; RIN=1: real g_B->g_A ----------------
template<int RIN>
__global__ __launch_bounds__(192) void kFC()
{
    extern __shared__ float2 smC[];
    float2* zb = smC;            // 4*768
    float2* Ab = smC + 3072;     // 4*768
    float2* stw256 = smC + 6144; // 256
    float2* stw768 = smC + 6400; // 512
    const int tid = threadIdx.x;
    const int r = tid / 48, l = tid - r*48;
    const size_t row0 = (size_t)blockIdx.x * 4;
    for (int e = tid; e < 256; e += 192) stw256[e] = g_tw256[e];
    for (int e = tid; e < 512; e += 192) stw768[e] = g_tw768[e];
    if (RIN) {
        const float* sp = (const float*)g_B;
        for (int e = tid; e < 3072; e += 192)
            zb[e] = make_float2(sp[row0*768 + e], 0.f);
    } else {
        for (int e = tid; e < 3072; e += 192)
            zb[e] = g_A[row0*768 + e];
    }
    __syncthreads();
    {   // stage1: (r, n3, n2): FFT-16 over n1, then x tw256[n2*k1]
        const int n3 = l >> 4, n2 = l & 15;
        float2 u[16];
        #pragma unroll
        for (int n1 = 0; n1 < 16; n1++) u[n1] = zb[r*768 + n3 + 3*n2 + 48*n1];
        fft16r(u);
        #pragma unroll
        for (int k1 = 0; k1 < 16; k1++)
            Ab[r*768 + (n3*16 + k1)*16 + n2] = cmul(u[FFI(k1)], stw256[n2*k1]);
    }
    __syncthreads();
    {   // stage2: (r, n3, k1): FFT-16 over n2
        const int n3 = l >> 4, k1 = l & 15;
        float2 v[16];
        #pragma unroll
        for (int n2 = 0; n2 < 16; n2++) v[n2] = Ab[r*768 + (n3*16 + k1)*16 + n2];
        fft16r(v);
        #pragma unroll
        for (int k2 = 0; k2 < 16; k2++)
            zb[r*768 + (n3*16 + k1)*16 + k2] = v[FFI(k2)];
    }
    __syncthreads();
    {   // stage3: radix-3 combine
        float2* dst = RIN ? g_A : g_B;
        const float s3 = 0.86602540378443865f;
        for (int e = tid; e < 1024; e += 192) {
            const int rr = e >> 8, m = e & 255;
            const int k1 = m & 15, k2 = m >> 4;
            float2 b0 = zb[rr*768 +       k1*16 + k2];
            float2 b1 = cmul(zb[rr*768 + 256 + k1*16 + k2], stw768[m]);
            float2 b2 = cmul(zb[rr*768 + 512 + k1*16 + k2], stw768[2*m]);
            float2 t1 = make_float2(b1.x + b2.x, b1.y + b2.y);
            float2 t2 = make_float2(b1.x - b2.x, b1.y - b2.y);
            dst[(row0+rr)*768 + m] = make_float2(b0.x + t1.x, b0.y + t1.y);
            float xr = fmaf(-0.5f, t1.x, b0.x);
            float xi = fmaf(-0.5f, t1.y, b0.y);
            dst[(row0+rr)*768 + m + 256] = make_float2(fmaf( s3, t2.y, xr), fmaf(-s3, t2.x, xi));
            dst[(row0+rr)*768 + m + 512] = make_float2(fmaf(-s3, t2.y, xr), fmaf( s3, t2.x, xi));
        }
    }
}

// ---------------- H-FFT (128=16x8) + length-2 B-FFT, direct-load ----------------
template<int SWAP>
__global__ __launch_bounds__(128) void kFHB()
{
    __shared__ float2 Ys[2][16][8][8];
    __shared__ float2 stw[128];
    const float2* src = SWAP ? g_A : g_B;
    float2* dst = SWAP ? g_B : g_A;
    const int kw = blockIdx.x, c0 = blockIdx.y * 8, tid = threadIdx.x;
    stw[tid] = g_tw128[tid];
    {
        const int c = tid & 7, n2 = (tid >> 3) & 7, bb = tid >> 6;
        float2 u[16];
        #pragma unroll
        for (int n1 = 0; n1 < 16; n1++) {
            size_t h = (size_t)(8*n1 + n2);
            float2 a = src[(h*KWV + kw)*CCH + c0 + c];
            float2 b = src[(((size_t)HH + h)*KWV + kw)*CCH + c0 + c];
            u[n1] = bb ? make_float2(a.x - b.x, a.y - b.y)
                       : make_float2(a.x + b.x, a.y + b.y);
        }
        __syncthreads();
        fft16r(u);
        #pragma unroll
        for (int k1 = 0; k1 < 16; k1++)
            Ys[bb][k1][n2][c] = cmul(u[FFI(k1)], stw[k1*n2]);
    }
    __syncthreads();
    #pragma unroll
    for (int r = 0; r < 2; r++) {
        int t = tid + 128*r;
        int c = t & 7, k1 = (t >> 3) & 15, bb = t >> 7;
        float2 v[8];
        #pragma unroll
        for (int n2 = 0; n2 < 8; n2++) v[n2] = Ys[bb][k1][n2][c];
        fft8r(v);
        #pragma unroll
        for (int k2 = 0; k2 < 8; k2++)
            dst[(((size_t)bb*HH + k1 + 16*k2)*KWV + kw)*CCH + c0 + c] = v[k2];
    }
}

// ---------------- fused MLP (Karatsuba + f32x2, 4pos x 12out tiles): g_A,x -> s in g_B ----------------
#define SST 132
#define MP  128

__device__ __forceinline__ void gemv12(const float* __restrict__ sS, const float* __restrict__ sD,
                                       const float* __restrict__ sW0, const float* __restrict__ sW1,
                                       int pb, int ob, u64 aU[4][6], u64 aV[4][6])
{
    #pragma unroll
    for (int i = 0; i < 4; i++)
        #pragma unroll
        for (int j = 0; j < 6; j++) { aU[i][j] = 0ull; aV[i][j] = 0ull; }
    for (int k = 0; k < 96; k++) {
        float4 s4 = *(const float4*)(sS + k*SST + pb);
        float4 d4 = *(const float4*)(sD + k*SST + pb);
        ulonglong2 wA = *(const ulonglong2*)(sW0 + k*96 + ob);
        ulonglong2 wB = *(const ulonglong2*)(sW0 + k*96 + ob + 4);
        ulonglong2 wC = *(const ulonglong2*)(sW0 + k*96 + ob + 8);
        ulonglong2 vA = *(const ulonglong2*)(sW1 + k*96 + ob);
        ulonglong2 vB = *(const ulonglong2*)(sW1 + k*96 + ob + 4);
        ulonglong2 vC = *(const ulonglong2*)(sW1 + k*96 + ob + 8);
        u64 w0[6] = {wA.x, wA.y, wB.x, wB.y, wC.x, wC.y};
        u64 w1v[6] = {vA.x, vA.y, vB.x, vB.y, vC.x, vC.y};
        u64 sp[4] = {pk2(s4.x), pk2(s4.y), pk2(s4.z), pk2(s4.w)};
        u64 dp[4] = {pk2(d4.x), pk2(d4.y), pk2(d4.z), pk2(d4.w)};
        #pragma unroll
        for (int i = 0; i < 4; i++)
            #pragma unroll
            for (int j = 0; j < 6; j++) {
                f2fma(aU[i][j], sp[i], w0[j]);
                f2fma(aV[i][j], dp[i], w1v[j]);
            }
    }
}

__global__ __launch_bounds__(256) void kMLP(const float* __restrict__ x,
    const float* __restrict__ w1, const float* __restrict__ b1,
    const float* __restrict__ w2, const float* __restrict__ b2)
{
    extern __shared__ float smp[];
    float* sW0 = smp;
    float* sW1 = smp + 9216;
    float* sS  = smp + 18432;
    float* sD  = smp + 31104;
    const int n = blockIdx.y, p0 = blockIdx.x * MP, tid = threadIdx.x;
    const int og = tid >> 5, pg = tid & 31;
    const int ob = og * 12, pb = pg * 4;

    const float4* W10 = (const float4*)(w1 + (size_t)n*9216);
    const float4* W11 = (const float4*)(w1 + (size_t)(NB+n)*9216);
    for (int e = tid; e < 2304; e += 256) {
        ((float4*)sW0)[e] = W10[e];
        ((float4*)sW1)[e] = W11[e];
    }
    for (int e = tid; e < MP*96; e += 256) {
        int p = e / 96, c = e - 96*p;
        int pgl = p0 + p;
        int b = (pgl >= HH*KWV) ? 1 : 0;
        int r = pgl - b*(HH*KWV);
        int h = r / KWV, kw = r - h*KWV;
        float2 z = g_A[(size_t)pgl*CCH + n*BS + c];
        float av = z.x + z.y;
        int hn = (HH - h) & (HH-1), wn = (WW - kw) & (WW-1);
        float an = x[(((size_t)b*HH + hn)*WW + wn)*CCH + n*BS + c];
        sS[c*SST + p] = av + an;
        sD[c*SST + p] = av - an;
    }
    __syncthreads();

    u64 aU[4][6], aV[4][6];
    float keep[4][12];
    float bk[12], bn[12];

    gemv12(sS, sD, sW0, sW1, pb, ob, aU, aV);
    #pragma unroll
    for (int j = 0; j < 12; j++) { bk[j] = b1[n*BS + ob + j]; bn[j] = b1[(NB+n)*BS + ob + j]; }
    __syncthreads();
    #pragma unroll
    for (int jp = 0; jp < 6; jp++) {
        float4 vs0, vd0, vs1, vd1;
        #pragma unroll
        for (int i = 0; i < 4; i++) {
            float2 u = up2(aU[i][jp]), v = up2(aV[i][jp]);
            float k0 = fmaxf(fmaf(0.5f, u.x + v.x, bk[2*jp]),   0.f);
            float n0 = fmaxf(fmaf(0.5f, u.x - v.x, bn[2*jp]),   0.f);
            float k1 = fmaxf(fmaf(0.5f, u.y + v.y, bk[2*jp+1]), 0.f);
            float n1 = fmaxf(fmaf(0.5f, u.y - v.y, bn[2*jp+1]), 0.f);
            keep[i][2*jp] = n0; keep[i][2*jp+1] = n1;
            ((float*)&vs0)[i] = k0 + n0; ((float*)&vd0)[i] = k0 - n0;
            ((float*)&vs1)[i] = k1 + n1; ((float*)&vd1)[i] = k1 - n1;
        }
        *(float4*)(sS + (ob+2*jp  )*SST + pb) = vs0;
        *(float4*)(sD + (ob+2*jp  )*SST + pb) = vd0;
        *(float4*)(sS + (ob+2*jp+1)*SST + pb) = vs1;
        *(float4*)(sD + (ob+2*jp+1)*SST + pb) = vd1;
    }
    const float4* W20 = (const float4*)(w2 + (size_t)n*9216);
    const float4* W21 = (const float4*)(w2 + (size_t)(NB+n)*9216);
    for (int e = tid; e < 2304; e += 256) {
        ((float4*)sW0)[e] = W20[e];
        ((float4*)sW1)[e] = W21[e];
    }
    __syncthreads();

    gemv12(sS, sD, sW0, sW1, pb, ob, aU, aV);
    #pragma unroll
    for (int j = 0; j < 12; j++) { bk[j] = b2[n*BS + ob + j]; bn[j] = b2[(NB+n)*BS + ob + j]; }
    __syncthreads();
    #pragma unroll
    for (int jp = 0; jp < 6; jp++) {
        float4 vs0, vd0, vs1, vd1;
        #pragma unroll
        for (int i = 0; i < 4; i++) {
            float2 u = up2(aU[i][jp]), v = up2(aV[i][jp]);
            float ok0 = fmaf(0.5f, u.x + v.x, bk[2*jp]);
            float ok1 = fmaf(0.5f, u.y + v.y, bk[2*jp+1]);
            float un0 = keep[i][2*jp], un1 = keep[i][2*jp+1];
            keep[i][2*jp] = ok0; keep[i][2*jp+1] = ok1;
            ((float*)&vs0)[i] = un0 + ok0; ((float*)&vd0)[i] = un0 - ok0;
            ((float*)&vs1)[i] = un1 + ok1; ((float*)&vd1)[i] = un1 - ok1;
        }
        *(float4*)(sS + (ob+2*jp  )*SST + pb) = vs0;
        *(float4*)(sD + (ob+2*jp  )*SST + pb) = vd0;
        *(float4*)(sS + (ob+2*jp+1)*SST + pb) = vs1;
        *(float4*)(sD + (ob+2*jp+1)*SST + pb) = vd1;
    }
    __syncthreads();

    gemv12(sS, sD, sW0, sW1, pb, ob, aU, aV);
    __syncthreads();
    #pragma unroll
    for (int jp = 0; jp < 6; jp++) {
        float4 vs0, vs1;
        #pragma unroll
        for (int i = 0; i < 4; i++) {
            float2 u = up2(aU[i][jp]), v = up2(aV[i][jp]);
            float o2n0 = fmaf(0.5f, u.x + v.x, bn[2*jp]);
            float o2n1 = fmaf(0.5f, u.y + v.y, bn[2*jp+1]);
            float t0 = keep[i][2*jp]   + o2n0;
            float t1 = keep[i][2*jp+1] + o2n1;
            ((float*)&vs0)[i] = copysignf(fmaxf(fabsf(t0) - 0.01f, 0.f), t0);
            ((float*)&vs1)[i] = copysignf(fmaxf(fabsf(t1) - 0.01f, 0.f), t1);
        }
        *(float4*)(sS + (ob+2*jp  )*SST + pb) = vs0;
        *(float4*)(sS + (ob+2*jp+1)*SST + pb) = vs1;
    }
    __syncthreads();
    float* outp = (float*)g_B;
    for (int e = tid; e < MP*96; e += 256) {
        int p = e / 96, c = e - 96*p;
        outp[(size_t)(p0 + p)*CCH + n*BS + c] = sS[c*SST + p];
    }
}

// ---------------- inverse W-FFT (65 -> 256) + scale + residual : g_B -> out ----------------
__global__ __launch_bounds__(256) void kIW(const float* __restrict__ x, float* __restrict__ out)
{
    __shared__ float2 Ys[256*17];
    __shared__ float2 stw[256];
    const int bh = blockIdx.x, c0 = blockIdx.y * 16, tid = threadIdx.x;
    if (tid < 256) stw[tid] = g_tw256[tid];
    __syncthreads();
    const float2* zp = g_B + (size_t)bh*KWV*CCH + c0;
    for (int e = tid; e < 4096; e += 256) {
        int c = e & 15, n2 = (e >> 4) & 15, k1 = e >> 8;
        float2 acc = make_float2(0.f, 0.f);
        int idx = (k1 * n2) & 255, step = (k1 * 16) & 255;
        int nmax = (n2 == 0) ? 5 : 4;
        for (int n1 = 0; n1 < nmax; n1++) {
            int w = (n1 << 4) + n2;
            float2 z = __ldg(&zp[(size_t)w*CCH + c]);
            cmadd(acc, z, stw[idx]);
            idx = (idx + step) & 255;
        }
        Ys[(k1*16 + n2)*17 + c] = acc;
    }
    __syncthreads();
    const float invN = 1.0f / 50331648.0f;
    {
        const int k1 = tid >> 4, c = tid & 15;
        float2 v[16];
        #pragma unroll
        for (int n2 = 0; n2 < 16; n2++) v[n2] = Ys[(k1*16 + n2)*17 + c];
        fft16r(v);
        #pragma unroll
        for (int k2 = 0; k2 < 16; k2++) {
            float2 acc = v[FFI(k2)];
            size_t a = ((size_t)bh*WW + k1 + 16*k2)*CCH + c0 + c;
            out[a] = fmaf(acc.x + acc.y, invN, x[a]);
        }
    }
}

extern "C" void kernel_launch(void* const* d_in, const int* in_sizes, int n_in,
                              void* d_out, int out_size)
{
    const float* x  = (const float*)d_in[0];
    const float* w1 = (const float*)d_in[1];
    const float* b1 = (const float*)d_in[2];
    const float* w2 = (const float*)d_in[3];
    const float* b2 = (const float*)d_in[4];
    float* out = (float*)d_out;

    cudaFuncSetAttribute(kMLP,   cudaFuncAttributeMaxDynamicSharedMemorySize, 175104);
    cudaFuncSetAttribute(kF1,    cudaFuncAttributeMaxDynamicSharedMemorySize, 54272);
    cudaFuncSetAttribute(kFC<0>, cudaFuncAttributeMaxDynamicSharedMemorySize, 55296);
    cudaFuncSetAttribute(kFC<1>, cudaFuncAttributeMaxDynamicSharedMemorySize, 55296);

    kPrep<<<3, 256>>>();
    kF1 <<<dim3(BB*HH, CCH/16), 256, 54272>>>(x);   // x -> A
    kFC<0><<<NPOS/4, 192, 55296>>>();               // A -> B
    kFHB<0><<<dim3(KWV, CCH/8), 128>>>();           // B -> A
    kMLP<<<dim3(NPOS/MP, NB), 256, 175104>>>(x, w1, b1, w2, b2);  // A,x -> s in B
    kFC<1><<<NPOS/4, 192, 55296>>>();               // B(real) -> A
    kFHB<1><<<dim3(KWV, CCH/8), 128>>>();           // A -> B
    kIW <<<dim3(BB*HH, CCH/16), 256>>>(x, out);     // B -> out
}

// round 9
// speedup vs baseline: 3.6148x; 1.2072x over previous
#include <cuda_runtime.h>
#include <cuda_bf16.h>
#include <math.h>
#include <stdint.h>

#define BB 2
#define HH 128
#define WW 256
#define CCH 768
#define KWV 65
#define NB 8
#define BS 96
#define NPOS (BB*HH*KWV)
#define SLABN (NPOS*CCH)

typedef unsigned long long u64;

__device__ float2 g_A[SLABN];
__device__ float2 g_B[SLABN];
__device__ float2 g_tw256[256];
__device__ float2 g_tw768[768];
__device__ float2 g_tw128[128];

__device__ __forceinline__ void cmadd(float2& acc, float2 z, float2 t) {
    acc.x = fmaf(z.x, t.x, fmaf(-z.y, t.y, acc.x));
    acc.y = fmaf(z.x, t.y, fmaf( z.y, t.x, acc.y));
}
__device__ __forceinline__ float2 cmul(float2 a, float2 b) {
    return make_float2(a.x*b.x - a.y*b.y, a.x*b.y + a.y*b.x);
}

// ---------------- register FFT primitives ----------------
#define FC1 0.92387953251128674f
#define FS1 0.38268343236508977f
#define FR  0.70710678118654752f

__device__ __forceinline__ float2 cadd2(float2 a, float2 b) {
    return make_float2(fmaf(b.x, 1.0f, a.x), fmaf(b.y, 1.0f, a.y));
}
__device__ __forceinline__ float2 csub2(float2 a, float2 b) {
    return make_float2(fmaf(b.x, -1.0f, a.x), fmaf(b.y, -1.0f, a.y));
}
__device__ __forceinline__ float2 cmulK(float2 z, float C, float S) {
    return make_float2(fmaf(z.x, C, -z.y*S), fmaf(z.y, C, z.x*S));
}
__device__ __forceinline__ void dft4(float2& a, float2& b, float2& c, float2& d) {
    float2 apc = cadd2(a, c), amc = csub2(a, c);
    float2 bpd = cadd2(b, d), bmd = csub2(b, d);
    float2 jb = make_float2(bmd.y, -bmd.x);
    a = cadd2(apc, bpd);
    b = cadd2(amc, jb);
    c = csub2(apc, bpd);
    d = csub2(amc, jb);
}
#define FFI(k) (4*((k)&3) + ((k)>>2))
__device__ __forceinline__ void fft16r(float2 v[16]) {
    dft4(v[0], v[4], v[8],  v[12]);
    dft4(v[1], v[5], v[9],  v[13]);
    dft4(v[2], v[6], v[10], v[14]);
    dft4(v[3], v[7], v[11], v[15]);
    v[5]  = cmulK(v[5],  FC1, -FS1);
    v[6]  = cmulK(v[6],  FR,  -FR );
    v[7]  = cmulK(v[7],  FS1, -FC1);
    v[9]  = cmulK(v[9],  FR,  -FR );
    v[10] = make_float2(v[10].y, -v[10].x);
    v[11] = cmulK(v[11], -FR,  -FR );
    v[13] = cmulK(v[13], FS1, -FC1);
    v[14] = cmulK(v[14], -FR,  -FR );
    v[15] = cmulK(v[15], -FC1,  FS1);
    dft4(v[0],  v[1],  v[2],  v[3]);
    dft4(v[4],  v[5],  v[6],  v[7]);
    dft4(v[8],  v[9],  v[10], v[11]);
    dft4(v[12], v[13], v[14], v[15]);
}
__device__ __forceinline__ void fft8r(float2 v[8]) {
    float2 a0 = cadd2(v[0], v[4]), a1 = cadd2(v[1], v[5]);
    float2 a2 = cadd2(v[2], v[6]), a3 = cadd2(v[3], v[7]);
    float2 b0 = csub2(v[0], v[4]);
    float2 t1 = csub2(v[1], v[5]);
    float2 t2 = csub2(v[2], v[6]);
    float2 t3 = csub2(v[3], v[7]);
    float2 b1 = cmulK(t1, FR, -FR);
    float2 b2 = make_float2(t2.y, -t2.x);
    float2 b3 = cmulK(t3, -FR, -FR);
    dft4(a0, a1, a2, a3);
    dft4(b0, b1, b2, b3);
    v[0] = a0; v[2] = a1; v[4] = a2; v[6] = a3;
    v[1] = b0; v[3] = b1; v[5] = b2; v[7] = b3;
}

// ---------------- HMMA helpers (sm_80-era PTX, valid on sm_103) ----------------
__device__ __forceinline__ uint32_t smem_u32(const void* p) {
    uint32_t a;
    asm("{ .reg .u64 t; cvta.to.shared.u64 t, %1; cvt.u32.u64 %0, t; }" : "=r"(a) : "l"(p));
    return a;
}
__device__ __forceinline__ void ldmA(unsigned r[4], uint32_t addr) {
    asm volatile("ldmatrix.sync.aligned.m8n8.x4.shared.b16 {%0,%1,%2,%3}, [%4];"
        : "=r"(r[0]),"=r"(r[1]),"=r"(r[2]),"=r"(r[3]) : "r"(addr));
}
__device__ __forceinline__ void mma16816(float d[4], const unsigned a[4], const unsigned b[2]) {
    asm volatile("mma.sync.aligned.m16n8k16.row.col.f32.bf16.bf16.f32 "
        "{%0,%1,%2,%3}, {%4,%5,%6,%7}, {%8,%9}, {%0,%1,%2,%3};"
        : "+f"(d[0]),"+f"(d[1]),"+f"(d[2]),"+f"(d[3])
        : "r"(a[0]),"r"(a[1]),"r"(a[2]),"r"(a[3]), "r"(b[0]),"r"(b[1]));
}

__global__ void kPrep()
{
    int t = blockIdx.x * blockDim.x + threadIdx.x;
    const double TP = 6.283185307179586476925286766559;
    if (t < 768) {
        double s, c;
        sincos(-TP * (double)t / 768.0, &s, &c);
        g_tw768[t] = make_float2((float)c, (float)s);
        if (t < 256) { sincos(-TP*(double)t/256.0, &s, &c); g_tw256[t] = make_float2((float)c,(float)s); }
        if (t < 128) { sincos(-TP*(double)t/128.0, &s, &c); g_tw128[t] = make_float2((float)c,(float)s); }
    }
}

// ---------------- forward W-FFT (256=16x16) pruned kw<65 : x -> g_A ----------------
__global__ __launch_bounds__(256) void kF1(const float* __restrict__ x)
{
    extern __shared__ float smF1[];
    float*  Xs  = smF1;
    float2* Ys  = (float2*)(smF1 + 4352);
    float2* stw = Ys + 4352;
    const int bh = blockIdx.x, c0 = blockIdx.y * 16, tid = threadIdx.x;
    if (tid < 256) stw[tid] = g_tw256[tid];
    const float* xp = x + (size_t)bh * (WW*CCH) + c0;
    for (int e = tid; e < 4096; e += 256)
        Xs[(e >> 4)*17 + (e & 15)] = xp[(size_t)(e >> 4) * CCH + (e & 15)];
    __syncthreads();
    {
        const int n2 = tid >> 4, c = tid & 15;
        float2 u[16];
        #pragma unroll
        for (int n1 = 0; n1 < 16; n1++) u[n1] = make_float2(Xs[(16*n1 + n2)*17 + c], 0.f);
        fft16r(u);
        #pragma unroll
        for (int k1 = 0; k1 < 16; k1++)
            Ys[(k1*16 + n2)*17 + c] = cmul(u[FFI(k1)], stw[n2*k1]);
    }
    __syncthreads();
    {
        const int k1 = tid >> 4, c = tid & 15;
        float2 v[16];
        #pragma unroll
        for (int n2 = 0; n2 < 16; n2++) v[n2] = Ys[(k1*16 + n2)*17 + c];
        fft16r(v);
        float2* dst = g_A + ((size_t)bh*KWV)*CCH + c0 + c;
        #pragma unroll
        for (int k2 = 0; k2 < 4; k2++)
            dst[(size_t)(k1 + 16*k2)*CCH] = v[FFI(k2)];
        if (k1 == 0)
            dst[(size_t)64*CCH] = v[FFI(4)];
    }
}

// ---------------- C-FFT 768 = 16x16x3 : RIN=0: g_A->g_B; RIN=1: real g_B->g_A ----------------
template<int RIN>
__global__ __launch_bounds__(192) void kFC()
{
    extern __shared__ float2 smC[];
    float2* zb = smC;
    float2* Ab = smC + 3072;
    float2* stw256 = smC + 6144;
    float2* stw768 = smC + 6400;
    const int tid = threadIdx.x;
    const int r = tid / 48, l = tid - r*48;
    const size_t row0 = (size_t)blockIdx.x * 4;
    for (int e = tid; e < 256; e += 192) stw256[e] = g_tw256[e];
    for (int e = tid; e < 512; e += 192) stw768[e] = g_tw768[e];
    if (RIN) {
        const float* sp = (const float*)g_B;
        for (int e = tid; e < 3072; e += 192)
            zb[e] = make_float2(sp[row0*768 + e], 0.f);
    } else {
        for (int e = tid; e < 3072; e += 192)
            zb[e] = g_A[row0*768 + e];
    }
    __syncthreads();
    {
        const int n3 = l >> 4, n2 = l & 15;
        float2 u[16];
        #pragma unroll
        for (int n1 = 0; n1 < 16; n1++) u[n1] = zb[r*768 + n3 + 3*n2 + 48*n1];
        fft16r(u);
        #pragma unroll
        for (int k1 = 0; k1 < 16; k1++)
            Ab[r*768 + (n3*16 + k1)*16 + n2] = cmul(u[FFI(k1)], stw256[n2*k1]);
    }
    __syncthreads();
    {
        const int n3 = l >> 4, k1 = l & 15;
        float2 v[16];
        #pragma unroll
        for (int n2 = 0; n2 < 16; n2++) v[n2] = Ab[r*768 + (n3*16 + k1)*16 + n2];
        fft16r(v);
        #pragma unroll
        for (int k2 = 0; k2 < 16; k2++)
            zb[r*768 + (n3*16 + k1)*16 + k2] = v[FFI(k2)];
    }
    __syncthreads();
    {
        float2* dst = RIN ? g_A : g_B;
        const float s3 = 0.86602540378443865f;
        for (int e = tid; e < 1024; e += 192) {
            const int rr = e >> 8, m = e & 255;
            const int k1 = m & 15, k2 = m >> 4;
            float2 b0 = zb[rr*768 +       k1*16 + k2];
            float2 b1 = cmul(zb[rr*768 + 256 + k1*16 + k2], stw768[m]);
            float2 b2 = cmul(zb[rr*768 + 512 + k1*16 + k2], stw768[2*m]);
            float2 t1 = make_float2(b1.x + b2.x, b1.y + b2.y);
            float2 t2 = make_float2(b1.x - b2.x, b1.y - b2.y);
            dst[(row0+rr)*768 + m] = make_float2(b0.x + t1.x, b0.y + t1.y);
            float xr = fmaf(-0.5f, t1.x, b0.x);
            float xi = fmaf(-0.5f, t1.y, b0.y);
            dst[(row0+rr)*768 + m + 256] = make_float2(fmaf( s3, t2.y, xr), fmaf(-s3, t2.x, xi));
            dst[(row0+rr)*768 + m + 512] = make_float2(fmaf(-s3, t2.y, xr), fmaf( s3, t2.x, xi));
        }
    }
}

// ---------------- H-FFT (128=16x8) + length-2 B-FFT, 16-wide coalesced ----------------
template<int SWAP>
__global__ __launch_bounds__(256) void kFHB()
{
    __shared__ float2 Ys[2][16][8][16];   // [bb][k1][n2][c]  32KB
    __shared__ float2 stw[128];
    const float2* src = SWAP ? g_A : g_B;
    float2* dst = SWAP ? g_B : g_A;
    const int kw = blockIdx.x, c0 = blockIdx.y * 16, tid = threadIdx.x;
    if (tid < 128) stw[tid] = g_tw128[tid];
    {
        const int c = tid & 15, n2 = (tid >> 4) & 7, bb = tid >> 7;
        float2 u[16];
        #pragma unroll
        for (int n1 = 0; n1 < 16; n1++) {
            size_t h = (size_t)(8*n1 + n2);
            float2 a = src[(h*KWV + kw)*CCH + c0 + c];
            float2 b = src[(((size_t)HH + h)*KWV + kw)*CCH + c0 + c];
            u[n1] = bb ? make_float2(a.x - b.x, a.y - b.y)
                       : make_float2(a.x + b.x, a.y + b.y);
        }
        __syncthreads();
        fft16r(u);
        #pragma unroll
        for (int k1 = 0; k1 < 16; k1++)
            Ys[bb][k1][n2][c] = cmul(u[FFI(k1)], stw[k1*n2]);
    }
    __syncthreads();
    #pragma unroll
    for (int r = 0; r < 2; r++) {
        int t = tid + 256*r;
        int c = t & 15, k1 = (t >> 4) & 15, bb = t >> 8;
        float2 v[8];
        #pragma unroll
        for (int n2 = 0; n2 < 8; n2++) v[n2] = Ys[bb][k1][n2][c];
        fft8r(v);
        #pragma unroll
        for (int k2 = 0; k2 < 8; k2++)
            dst[(((size_t)bb*HH + k1 + 16*k2)*KWV + kw)*CCH + c0 + c] = v[k2];
    }
}

// ---------------- HMMA MLP (bf16 tensor-core, Karatsuba): g_A,x -> s in g_B ----------------
// smem (bytes): sAS bf16[128][104] @0 (26624), sAD @26624, sW0 bf16[96][104] @53248 (19968), sW1 @73216. total 93184
#define MO_AS 0
#define MO_AD 26624
#define MO_W0 53248
#define MO_W1 73216
#define MSM   93184
#define ASTR  104
#define WSTR  104
#define SOP   133

__device__ __forceinline__ void mmaGemv(uint32_t aSb, uint32_t aDb,
    const __nv_bfloat16* __restrict__ w0, const __nv_bfloat16* __restrict__ w1v,
    int warpM, int warpN, int lane, int g, int tig,
    float U[2][3][4], float V[2][3][4])
{
    #pragma unroll
    for (int mi = 0; mi < 2; mi++)
        #pragma unroll
        for (int ni = 0; ni < 3; ni++)
            #pragma unroll
            for (int j = 0; j < 4; j++) { U[mi][ni][j] = 0.f; V[mi][ni][j] = 0.f; }
    const uint32_t lrow = (uint32_t)(lane & 15) * (ASTR*2);
    const uint32_t lcol = (uint32_t)((lane >> 4) << 4);   // (lane>>4)*8 cols * 2B
    #pragma unroll
    for (int kb = 0; kb < 6; kb++) {
        const int kc = kb * 16;
        unsigned aS0[4], aS1[4], aD0[4], aD1[4];
        uint32_t base = lrow + lcol + kc*2;
        ldmA(aS0, aSb + (uint32_t)(warpM*32     )*(ASTR*2) + base);
        ldmA(aS1, aSb + (uint32_t)(warpM*32 + 16)*(ASTR*2) + base);
        ldmA(aD0, aDb + (uint32_t)(warpM*32     )*(ASTR*2) + base);
        ldmA(aD1, aDb + (uint32_t)(warpM*32 + 16)*(ASTR*2) + base);
        #pragma unroll
        for (int ni = 0; ni < 3; ni++) {
            const int orow = warpN*24 + ni*8 + g;
            unsigned b0[2], b1[2];
            b0[0] = *(const unsigned*)&w0 [orow*WSTR + kc + 2*tig];
            b0[1] = *(const unsigned*)&w0 [orow*WSTR + kc + 8 + 2*tig];
            b1[0] = *(const unsigned*)&w1v[orow*WSTR + kc + 2*tig];
            b1[1] = *(const unsigned*)&w1v[orow*WSTR + kc + 8 + 2*tig];
            mma16816(U[0][ni], aS0, b0);
            mma16816(U[1][ni], aS1, b0);
            mma16816(V[0][ni], aD0, b1);
            mma16816(V[1][ni], aD1, b1);
        }
    }
}

__global__ __launch_bounds__(512, 1) void kMLP(const float* __restrict__ x,
    const float* __restrict__ w1, const float* __restrict__ b1,
    const float* __restrict__ w2, const float* __restrict__ b2)
{
    extern __shared__ char smc[];
    __nv_bfloat16* aS  = (__nv_bfloat16*)(smc + MO_AS);
    __nv_bfloat16* aD  = (__nv_bfloat16*)(smc + MO_AD);
    __nv_bfloat16* wS0 = (__nv_bfloat16*)(smc + MO_W0);
    __nv_bfloat16* wS1 = (__nv_bfloat16*)(smc + MO_W1);
    const uint32_t aSb = smem_u32(aS), aDb = smem_u32(aD);
    const int n = blockIdx.y, p0 = blockIdx.x * 128, tid = threadIdx.x;
    const int wid = tid >> 5, lane = tid & 31;
    const int warpM = wid >> 2, warpN = wid & 3;
    const int g = lane >> 2, tig = lane & 3;

    // stage weights layer1 (transposed [o][i]) + activations
    for (int e = tid; e < 9216; e += 512) {
        int i = e / 96, o = e - 96*i;
        wS0[o*WSTR + i] = __float2bfloat16(w1[(size_t)n*9216 + e]);
        wS1[o*WSTR + i] = __float2bfloat16(w1[(size_t)(NB+n)*9216 + e]);
    }
    for (int e = tid; e < 12288; e += 512) {
        int p = e / 96, c = e - 96*p;
        int pgl = p0 + p;
        int b = (pgl >= HH*KWV) ? 1 : 0;
        int r = pgl - b*(HH*KWV);
        int h = r / KWV, kw = r - h*KWV;
        float2 z = g_A[(size_t)pgl*CCH + n*BS + c];
        float av = z.x + z.y;
        int hn = (HH - h) & (HH-1), wn = (WW - kw) & (WW-1);
        float an = x[(((size_t)b*HH + hn)*WW + wn)*CCH + n*BS + c];
        aS[p*ASTR + c] = __float2bfloat16(av + an);
        aD[p*ASTR + c] = __float2bfloat16(av - an);
    }
    __syncthreads();

    float U[2][3][4], V[2][3][4], keep[2][3][4];

    // ===== layer 1 =====
    mmaGemv(aSb, aDb, wS0, wS1, warpM, warpN, lane, g, tig, U, V);
    __syncthreads();
    #pragma unroll
    for (int mi = 0; mi < 2; mi++)
        #pragma unroll
        for (int ni = 0; ni < 3; ni++) {
            const int o = warpN*24 + ni*8 + 2*tig;
            const float bk0 = b1[n*BS + o],        bk1 = b1[n*BS + o + 1];
            const float bn0 = b1[(NB+n)*BS + o],   bn1 = b1[(NB+n)*BS + o + 1];
            const int p = warpM*32 + mi*16 + g;
            #pragma unroll
            for (int hh = 0; hh < 2; hh++) {
                float Uu0 = U[mi][ni][2*hh], Uu1 = U[mi][ni][2*hh+1];
                float Vv0 = V[mi][ni][2*hh], Vv1 = V[mi][ni][2*hh+1];
                float k0 = fmaxf(fmaf(0.5f, Uu0 + Vv0, bk0), 0.f);
                float n0 = fmaxf(fmaf(0.5f, Uu0 - Vv0, bn0), 0.f);
                float k1 = fmaxf(fmaf(0.5f, Uu1 + Vv1, bk1), 0.f);
                float n1 = fmaxf(fmaf(0.5f, Uu1 - Vv1, bn1), 0.f);
                keep[mi][ni][2*hh] = n0; keep[mi][ni][2*hh+1] = n1;
                const int pp = p + 8*hh;
                *(__nv_bfloat162*)&aS[pp*ASTR + o] = __floats2bfloat162_rn(k0 + n0, k1 + n1);
                *(__nv_bfloat162*)&aD[pp*ASTR + o] = __floats2bfloat162_rn(k0 - n0, k1 - n1);
            }
        }
    // load layer-2 weights
    for (int e = tid; e < 9216; e += 512) {
        int i = e / 96, o = e - 96*i;
        wS0[o*WSTR + i] = __float2bfloat16(w2[(size_t)n*9216 + e]);
        wS1[o*WSTR + i] = __float2bfloat16(w2[(size_t)(NB+n)*9216 + e]);
    }
    __syncthreads();

    // ===== layer 2 (o2_k) =====
    mmaGemv(aSb, aDb, wS0, wS1, warpM, warpN, lane, g, tig, U, V);
    __syncthreads();
    #pragma unroll
    for (int mi = 0; mi < 2; mi++)
        #pragma unroll
        for (int ni = 0; ni < 3; ni++) {
            const int o = warpN*24 + ni*8 + 2*tig;
            const float bk0 = b2[n*BS + o], bk1 = b2[n*BS + o + 1];
            const int p = warpM*32 + mi*16 + g;
            #pragma unroll
            for (int hh = 0; hh < 2; hh++) {
                float ok0 = fmaf(0.5f, U[mi][ni][2*hh]   + V[mi][ni][2*hh],   bk0);
                float ok1 = fmaf(0.5f, U[mi][ni][2*hh+1] + V[mi][ni][2*hh+1], bk1);
                float un0 = keep[mi][ni][2*hh], un1 = keep[mi][ni][2*hh+1];
                keep[mi][ni][2*hh] = ok0; keep[mi][ni][2*hh+1] = ok1;
                const int pp = p + 8*hh;
                *(__nv_bfloat162*)&aS[pp*ASTR + o] = __floats2bfloat162_rn(un0 + ok0, un1 + ok1);
                *(__nv_bfloat162*)&aD[pp*ASTR + o] = __floats2bfloat162_rn(un0 - ok0, un1 - ok1);  // o2_nk uses o2_k
            }
        }
    __syncthreads();

    // ===== layer 2 (o2_nk) + soft-threshold =====
    mmaGemv(aSb, aDb, wS0, wS1, warpM, warpN, lane, g, tig, U, V);
    __syncthreads();
    float* sOut = (float*)(smc + MO_AS);   // f32 [96][SOP], overlays aS/aD (done with them)
    #pragma unroll
    for (int mi = 0; mi < 2; mi++)
        #pragma unroll
        for (int ni = 0; ni < 3; ni++) {
            const int o = warpN*24 + ni*8 + 2*tig;
            const float bn0 = b2[(NB+n)*BS + o], bn1 = b2[(NB+n)*BS + o + 1];
            const int p = warpM*32 + mi*16 + g;
            #pragma unroll
            for (int hh = 0; hh < 2; hh++) {
                float o2n0 = fmaf(0.5f, U[mi][ni][2*hh]   + V[mi][ni][2*hh],   bn0);
                float o2n1 = fmaf(0.5f, U[mi][ni][2*hh+1] + V[mi][ni][2*hh+1], bn1);
                float t0 = keep[mi][ni][2*hh]   + o2n0;
                float t1 = keep[mi][ni][2*hh+1] + o2n1;
                const int pp = p + 8*hh;
                sOut[o*SOP + pp]     = copysignf(fmaxf(fabsf(t0) - 0.01f, 0.f), t0);
                sOut[(o+1)*SOP + pp] = copysignf(fmaxf(fabsf(t1) - 0.01f, 0.f), t1);
            }
        }
    __syncthreads();
    float* outp = (float*)g_B;
    for (int e = tid; e < 12288; e += 512) {
        int p = e / 96, c = e - 96*p;
        outp[(size_t)(p0 + p)*CCH + n*BS + c] = sOut[c*SOP + p];
    }
}

// ---------------- inverse W-FFT (65 -> 256) + scale + residual : g_B -> out ----------------
__global__ __launch_bounds__(256) void kIW(const float* __restrict__ x, float* __restrict__ out)
{
    __shared__ float2 Ys[256*17];
    __shared__ float2 stw[256];
    const int bh = blockIdx.x, c0 = blockIdx.y * 16, tid = threadIdx.x;
    if (tid < 256) stw[tid] = g_tw256[tid];
    __syncthreads();
    const float2* zp = g_B + (size_t)bh*KWV*CCH + c0;
    for (int e = tid; e < 4096; e += 256) {
        int c = e & 15, n2 = (e >> 4) & 15, k1 = e >> 8;
        float2 acc = make_float2(0.f, 0.f);
        int idx = (k1 * n2) & 255, step = (k1 * 16) & 255;
        int nmax = (n2 == 0) ? 5 : 4;
        for (int n1 = 0; n1 < nmax; n1++) {
            int w = (n1 << 4) + n2;
            float2 z = __ldg(&zp[(size_t)w*CCH + c]);
            cmadd(acc, z, stw[idx]);
            idx = (idx + step) & 255;
        }
        Ys[(k1*16 + n2)*17 + c] = acc;
    }
    __syncthreads();
    const float invN = 1.0f / 50331648.0f;
    {
        const int k1 = tid >> 4, c = tid & 15;
        float2 v[16];
        #pragma unroll
        for (int n2 = 0; n2 < 16; n2++) v[n2] = Ys[(k1*16 + n2)*17 + c];
        fft16r(v);
        #pragma unroll
        for (int k2 = 0; k2 < 16; k2++) {
            float2 acc = v[FFI(k2)];
            size_t a = ((size_t)bh*WW + k1 + 16*k2)*CCH + c0 + c;
            out[a] = fmaf(acc.x + acc.y, invN, x[a]);
        }
    }
}

extern "C" void kernel_launch(void* const* d_in, const int* in_sizes, int n_in,
                              void* d_out, int out_size)
{
    const float* x  = (const float*)d_in[0];
    const float* w1 = (const float*)d_in[1];
    const float* b1 = (const float*)d_in[2];
    const float* w2 = (const float*)d_in[3];
    const float* b2 = (const float*)d_in[4];
    float* out = (float*)d_out;

    cudaFuncSetAttribute(kMLP,   cudaFuncAttributeMaxDynamicSharedMemorySize, MSM);
    cudaFuncSetAttribute(kF1,    cudaFuncAttributeMaxDynamicSharedMemorySize, 54272);
    cudaFuncSetAttribute(kFC<0>, cudaFuncAttributeMaxDynamicSharedMemorySize, 55296);
    cudaFuncSetAttribute(kFC<1>, cudaFuncAttributeMaxDynamicSharedMemorySize, 55296);

    kPrep<<<3, 256>>>();
    kF1 <<<dim3(BB*HH, CCH/16), 256, 54272>>>(x);   // x -> A
    kFC<0><<<NPOS/4, 192, 55296>>>();               // A -> B
    kFHB<0><<<dim3(KWV, CCH/16), 256>>>();          // B -> A
    kMLP<<<dim3(NPOS/128, NB), 512, MSM>>>(x, w1, b1, w2, b2);  // A,x -> s in B
    kFC<1><<<NPOS/4, 192, 55296>>>();               // B(real) -> A
    kFHB<1><<<dim3(KWV, CCH/16), 256>>>();          // A -> B
    kIW <<<dim3(BB*HH, CCH/16), 256>>>(x, out);     // B -> out
}

// round 10
// speedup vs baseline: 3.7509x; 1.0376x over previous
#include <cuda_runtime.h>
#include <cuda_bf16.h>
#include <math.h>
#include <stdint.h>

#define BB 2
#define HH 128
#define WW 256
#define CCH 768
#define KWV 65
#define NB 8
#define BS 96
#define NPOS (BB*HH*KWV)
#define SLABN (NPOS*CCH)

typedef unsigned long long u64;
typedef __nv_bfloat162 cbf;

__device__ cbf g_A[SLABN];     // ~51 MB (complex bf16)
__device__ cbf g_B[SLABN];     // ~51 MB
__device__ float2 g_tw256[256];
__device__ float2 g_tw768[768];
__device__ float2 g_tw128[128];

__device__ __forceinline__ float2 b2f(cbf v) {
    return make_float2(__bfloat162float(v.x), __bfloat162float(v.y));
}
__device__ __forceinline__ cbf f2b(float2 v) {
    return __floats2bfloat162_rn(v.x, v.y);
}
__device__ __forceinline__ void cmadd(float2& acc, float2 z, float2 t) {
    acc.x = fmaf(z.x, t.x, fmaf(-z.y, t.y, acc.x));
    acc.y = fmaf(z.x, t.y, fmaf( z.y, t.x, acc.y));
}
__device__ __forceinline__ float2 cmul(float2 a, float2 b) {
    return make_float2(a.x*b.x - a.y*b.y, a.x*b.y + a.y*b.x);
}

// ---------------- register FFT primitives ----------------
#define FC1 0.92387953251128674f
#define FS1 0.38268343236508977f
#define FR  0.70710678118654752f

__device__ __forceinline__ float2 cadd2(float2 a, float2 b) {
    return make_float2(fmaf(b.x, 1.0f, a.x), fmaf(b.y, 1.0f, a.y));
}
__device__ __forceinline__ float2 csub2(float2 a, float2 b) {
    return make_float2(fmaf(b.x, -1.0f, a.x), fmaf(b.y, -1.0f, a.y));
}
__device__ __forceinline__ float2 cmulK(float2 z, float C, float S) {
    return make_float2(fmaf(z.x, C, -z.y*S), fmaf(z.y, C, z.x*S));
}
__device__ __forceinline__ void dft4(float2& a, float2& b, float2& c, float2& d) {
    float2 apc = cadd2(a, c), amc = csub2(a, c);
    float2 bpd = cadd2(b, d), bmd = csub2(b, d);
    float2 jb = make_float2(bmd.y, -bmd.x);
    a = cadd2(apc, bpd);
    b = cadd2(amc, jb);
    c = csub2(apc, bpd);
    d = csub2(amc, jb);
}
#define FFI(k) (4*((k)&3) + ((k)>>2))
__device__ __forceinline__ void fft16r(float2 v[16]) {
    dft4(v[0], v[4], v[8],  v[12]);
    dft4(v[1], v[5], v[9],  v[13]);
    dft4(v[2], v[6], v[10], v[14]);
    dft4(v[3], v[7], v[11], v[15]);
    v[5]  = cmulK(v[5],  FC1, -FS1);
    v[6]  = cmulK(v[6],  FR,  -FR );
    v[7]  = cmulK(v[7],  FS1, -FC1);
    v[9]  = cmulK(v[9],  FR,  -FR );
    v[10] = make_float2(v[10].y, -v[10].x);
    v[11] = cmulK(v[11], -FR,  -FR );
    v[13] = cmulK(v[13], FS1, -FC1);
    v[14] = cmulK(v[14], -FR,  -FR );
    v[15] = cmulK(v[15], -FC1,  FS1);
    dft4(v[0],  v[1],  v[2],  v[3]);
    dft4(v[4],  v[5],  v[6],  v[7]);
    dft4(v[8],  v[9],  v[10], v[11]);
    dft4(v[12], v[13], v[14], v[15]);
}
__device__ __forceinline__ void fft8r(float2 v[8]) {
    float2 a0 = cadd2(v[0], v[4]), a1 = cadd2(v[1], v[5]);
    float2 a2 = cadd2(v[2], v[6]), a3 = cadd2(v[3], v[7]);
    float2 b0 = csub2(v[0], v[4]);
    float2 t1 = csub2(v[1], v[5]);
    float2 t2 = csub2(v[2], v[6]);
    float2 t3 = csub2(v[3], v[7]);
    float2 b1 = cmulK(t1, FR, -FR);
    float2 b2 = make_float2(t2.y, -t2.x);
    float2 b3 = cmulK(t3, -FR, -FR);
    dft4(a0, a1, a2, a3);
    dft4(b0, b1, b2, b3);
    v[0] = a0; v[2] = a1; v[4] = a2; v[6] = a3;
    v[1] = b0; v[3] = b1; v[5] = b2; v[7] = b3;
}

// ---------------- HMMA helpers ----------------
__device__ __forceinline__ uint32_t smem_u32(const void* p) {
    uint32_t a;
    asm("{ .reg .u64 t; cvta.to.shared.u64 t, %1; cvt.u32.u64 %0, t; }" : "=r"(a) : "l"(p));
    return a;
}
__device__ __forceinline__ void ldmA(unsigned r[4], uint32_t addr) {
    asm volatile("ldmatrix.sync.aligned.m8n8.x4.shared.b16 {%0,%1,%2,%3}, [%4];"
        : "=r"(r[0]),"=r"(r[1]),"=r"(r[2]),"=r"(r[3]) : "r"(addr));
}
__device__ __forceinline__ void mma16816(float d[4], const unsigned a[4], const unsigned b[2]) {
    asm volatile("mma.sync.aligned.m16n8k16.row.col.f32.bf16.bf16.f32 "
        "{%0,%1,%2,%3}, {%4,%5,%6,%7}, {%8,%9}, {%0,%1,%2,%3};"
        : "+f"(d[0]),"+f"(d[1]),"+f"(d[2]),"+f"(d[3])
        : "r"(a[0]),"r"(a[1]),"r"(a[2]),"r"(a[3]), "r"(b[0]),"r"(b[1]));
}

__global__ void kPrep()
{
    int t = blockIdx.x * blockDim.x + threadIdx.x;
    const double TP = 6.283185307179586476925286766559;
    if (t < 768) {
        double s, c;
        sincos(-TP * (double)t / 768.0, &s, &c);
        g_tw768[t] = make_float2((float)c, (float)s);
        if (t < 256) { sincos(-TP*(double)t/256.0, &s, &c); g_tw256[t] = make_float2((float)c,(float)s); }
        if (t < 128) { sincos(-TP*(double)t/128.0, &s, &c); g_tw128[t] = make_float2((float)c,(float)s); }
    }
}

// ---------------- forward W-FFT (256=16x16) pruned kw<65 : x -> g_A ----------------
__global__ __launch_bounds__(256) void kF1(const float* __restrict__ x)
{
    extern __shared__ float smF1[];
    float*  Xs  = smF1;
    float2* Ys  = (float2*)(smF1 + 4352);
    float2* stw = Ys + 4352;
    const int bh = blockIdx.x, c0 = blockIdx.y * 16, tid = threadIdx.x;
    if (tid < 256) stw[tid] = g_tw256[tid];
    const float* xp = x + (size_t)bh * (WW*CCH) + c0;
    for (int e = tid; e < 4096; e += 256)
        Xs[(e >> 4)*17 + (e & 15)] = xp[(size_t)(e >> 4) * CCH + (e & 15)];
    __syncthreads();
    {
        const int n2 = tid >> 4, c = tid & 15;
        float2 u[16];
        #pragma unroll
        for (int n1 = 0; n1 < 16; n1++) u[n1] = make_float2(Xs[(16*n1 + n2)*17 + c], 0.f);
        fft16r(u);
        #pragma unroll
        for (int k1 = 0; k1 < 16; k1++)
            Ys[(k1*16 + n2)*17 + c] = cmul(u[FFI(k1)], stw[n2*k1]);
    }
    __syncthreads();
    {
        const int k1 = tid >> 4, c = tid & 15;
        float2 v[16];
        #pragma unroll
        for (int n2 = 0; n2 < 16; n2++) v[n2] = Ys[(k1*16 + n2)*17 + c];
        fft16r(v);
        cbf* dst = g_A + ((size_t)bh*KWV)*CCH + c0 + c;
        #pragma unroll
        for (int k2 = 0; k2 < 4; k2++)
            dst[(size_t)(k1 + 16*k2)*CCH] = f2b(v[FFI(k2)]);
        if (k1 == 0)
            dst[(size_t)64*CCH] = f2b(v[FFI(4)]);
    }
}

// ---------------- C-FFT 768 = 16x16x3 : RIN=0: g_A->g_B; RIN=1: real(f32) g_B->g_A ----------------
template<int RIN>
__global__ __launch_bounds__(192) void kFC()
{
    extern __shared__ float2 smC[];
    float2* zb = smC;
    float2* Ab = smC + 3072;
    float2* stw256 = smC + 6144;
    float2* stw768 = smC + 6400;
    const int tid = threadIdx.x;
    const int r = tid / 48, l = tid - r*48;
    const size_t row0 = (size_t)blockIdx.x * 4;
    for (int e = tid; e < 256; e += 192) stw256[e] = g_tw256[e];
    for (int e = tid; e < 512; e += 192) stw768[e] = g_tw768[e];
    if (RIN) {
        const float* sp = (const float*)g_B;   // s stored as fp32, same byte size as bf16 slab
        for (int e = tid; e < 3072; e += 192)
            zb[e] = make_float2(sp[row0*768 + e], 0.f);
    } else {
        for (int e = tid; e < 3072; e += 192)
            zb[e] = b2f(g_A[row0*768 + e]);
    }
    __syncthreads();
    {
        const int n3 = l >> 4, n2 = l & 15;
        float2 u[16];
        #pragma unroll
        for (int n1 = 0; n1 < 16; n1++) u[n1] = zb[r*768 + n3 + 3*n2 + 48*n1];
        fft16r(u);
        #pragma unroll
        for (int k1 = 0; k1 < 16; k1++)
            Ab[r*768 + (n3*16 + k1)*16 + n2] = cmul(u[FFI(k1)], stw256[n2*k1]);
    }
    __syncthreads();
    {
        const int n3 = l >> 4, k1 = l & 15;
        float2 v[16];
        #pragma unroll
        for (int n2 = 0; n2 < 16; n2++) v[n2] = Ab[r*768 + (n3*16 + k1)*16 + n2];
        fft16r(v);
        #pragma unroll
        for (int k2 = 0; k2 < 16; k2++)
            zb[r*768 + (n3*16 + k1)*16 + k2] = v[FFI(k2)];
    }
    __syncthreads();
    {
        cbf* dst = RIN ? g_A : g_B;
        const float s3 = 0.86602540378443865f;
        for (int e = tid; e < 1024; e += 192) {
            const int rr = e >> 8, m = e & 255;
            const int k1 = m & 15, k2 = m >> 4;
            float2 b0 = zb[rr*768 +       k1*16 + k2];
            float2 b1 = cmul(zb[rr*768 + 256 + k1*16 + k2], stw768[m]);
            float2 b2 = cmul(zb[rr*768 + 512 + k1*16 + k2], stw768[2*m]);
            float2 t1 = make_float2(b1.x + b2.x, b1.y + b2.y);
            float2 t2 = make_float2(b1.x - b2.x, b1.y - b2.y);
            dst[(row0+rr)*768 + m] = f2b(make_float2(b0.x + t1.x, b0.y + t1.y));
            float xr = fmaf(-0.5f, t1.x, b0.x);
            float xi = fmaf(-0.5f, t1.y, b0.y);
            dst[(row0+rr)*768 + m + 256] = f2b(make_float2(fmaf( s3, t2.y, xr), fmaf(-s3, t2.x, xi)));
            dst[(row0+rr)*768 + m + 512] = f2b(make_float2(fmaf(-s3, t2.y, xr), fmaf( s3, t2.x, xi)));
        }
    }
}

// ---------------- H-FFT (128=16x8) + length-2 B-FFT, 16-wide coalesced ----------------
template<int SWAP>
__global__ __launch_bounds__(256) void kFHB()
{
    __shared__ float2 Ys[2][16][8][16];
    __shared__ float2 stw[128];
    const cbf* __restrict__ src = SWAP ? g_A : g_B;
    cbf* dst = SWAP ? g_B : g_A;
    const int kw = blockIdx.x, c0 = blockIdx.y * 16, tid = threadIdx.x;
    if (tid < 128) stw[tid] = g_tw128[tid];
    {
        const int c = tid & 15, n2 = (tid >> 4) & 7, bb = tid >> 7;
        float2 u[16];
        #pragma unroll
        for (int n1 = 0; n1 < 16; n1++) {
            size_t h = (size_t)(8*n1 + n2);
            float2 a = b2f(src[(h*KWV + kw)*CCH + c0 + c]);
            float2 b = b2f(src[(((size_t)HH + h)*KWV + kw)*CCH + c0 + c]);
            u[n1] = bb ? make_float2(a.x - b.x, a.y - b.y)
                       : make_float2(a.x + b.x, a.y + b.y);
        }
        __syncthreads();
        fft16r(u);
        #pragma unroll
        for (int k1 = 0; k1 < 16; k1++)
            Ys[bb][k1][n2][c] = cmul(u[FFI(k1)], stw[k1*n2]);
    }
    __syncthreads();
    #pragma unroll
    for (int r = 0; r < 2; r++) {
        int t = tid + 256*r;
        int c = t & 15, k1 = (t >> 4) & 15, bb = t >> 8;
        float2 v[8];
        #pragma unroll
        for (int n2 = 0; n2 < 8; n2++) v[n2] = Ys[bb][k1][n2][c];
        fft8r(v);
        #pragma unroll
        for (int k2 = 0; k2 < 8; k2++)
            dst[(((size_t)bb*HH + k1 + 16*k2)*KWV + kw)*CCH + c0 + c] = f2b(v[k2]);
    }
}

// ---------------- HMMA MLP (bf16 tensor-core, Karatsuba): g_A,x -> s (f32) in g_B ----------------
#define MO_AS 0
#define MO_AD 26624
#define MO_W0 53248
#define MO_W1 73216
#define MSM   93184
#define ASTR  104
#define WSTR  104
#define SOP   133

__device__ __forceinline__ void mmaGemv(uint32_t aSb, uint32_t aDb,
    const __nv_bfloat16* __restrict__ w0, const __nv_bfloat16* __restrict__ w1v,
    int warpM, int warpN, int lane, int g, int tig,
    float U[2][3][4], float V[2][3][4])
{
    #pragma unroll
    for (int mi = 0; mi < 2; mi++)
        #pragma unroll
        for (int ni = 0; ni < 3; ni++)
            #pragma unroll
            for (int j = 0; j < 4; j++) { U[mi][ni][j] = 0.f; V[mi][ni][j] = 0.f; }
    const uint32_t lrow = (uint32_t)(lane & 15) * (ASTR*2);
    const uint32_t lcol = (uint32_t)((lane >> 4) << 4);
    #pragma unroll
    for (int kb = 0; kb < 6; kb++) {
        const int kc = kb * 16;
        unsigned aS0[4], aS1[4], aD0[4], aD1[4];
        uint32_t base = lrow + lcol + kc*2;
        ldmA(aS0, aSb + (uint32_t)(warpM*32     )*(ASTR*2) + base);
        ldmA(aS1, aSb + (uint32_t)(warpM*32 + 16)*(ASTR*2) + base);
        ldmA(aD0, aDb + (uint32_t)(warpM*32     )*(ASTR*2) + base);
        ldmA(aD1, aDb + (uint32_t)(warpM*32 + 16)*(ASTR*2) + base);
        #pragma unroll
        for (int ni = 0; ni < 3; ni++) {
            const int orow = warpN*24 + ni*8 + g;
            unsigned b0[2], b1[2];
            b0[0] = *(const unsigned*)&w0 [orow*WSTR + kc + 2*tig];
            b0[1] = *(const unsigned*)&w0 [orow*WSTR + kc + 8 + 2*tig];
            b1[0] = *(const unsigned*)&w1v[orow*WSTR + kc + 2*tig];
            b1[1] = *(const unsigned*)&w1v[orow*WSTR + kc + 8 + 2*tig];
            mma16816(U[0][ni], aS0, b0);
            mma16816(U[1][ni], aS1, b0);
            mma16816(V[0][ni], aD0, b1);
            mma16816(V[1][ni], aD1, b1);
        }
    }
}

__global__ __launch_bounds__(512, 1) void kMLP(const float* __restrict__ x,
    const float* __restrict__ w1, const float* __restrict__ b1,
    const float* __restrict__ w2, const float* __restrict__ b2)
{
    extern __shared__ char smc[];
    __nv_bfloat16* aS  = (__nv_bfloat16*)(smc + MO_AS);
    __nv_bfloat16* aD  = (__nv_bfloat16*)(smc + MO_AD);
    __nv_bfloat16* wS0 = (__nv_bfloat16*)(smc + MO_W0);
    __nv_bfloat16* wS1 = (__nv_bfloat16*)(smc + MO_W1);
    const uint32_t aSb = smem_u32(aS), aDb = smem_u32(aD);
    const int n = blockIdx.y, p0 = blockIdx.x * 128, tid = threadIdx.x;
    const int wid = tid >> 5, lane = tid & 31;
    const int warpM = wid >> 2, warpN = wid & 3;
    const int g = lane >> 2, tig = lane & 3;

    for (int e = tid; e < 9216; e += 512) {
        int i = e / 96, o = e - 96*i;
        wS0[o*WSTR + i] = __float2bfloat16(w1[(size_t)n*9216 + e]);
        wS1[o*WSTR + i] = __float2bfloat16(w1[(size_t)(NB+n)*9216 + e]);
    }
    for (int e = tid; e < 12288; e += 512) {
        int p = e / 96, c = e - 96*p;
        int pgl = p0 + p;
        int b = (pgl >= HH*KWV) ? 1 : 0;
        int r = pgl - b*(HH*KWV);
        int h = r / KWV, kw = r - h*KWV;
        float2 z = b2f(g_A[(size_t)pgl*CCH + n*BS + c]);
        float av = z.x + z.y;
        int hn = (HH - h) & (HH-1), wn = (WW - kw) & (WW-1);
        float an = x[(((size_t)b*HH + hn)*WW + wn)*CCH + n*BS + c];
        aS[p*ASTR + c] = __float2bfloat16(av + an);
        aD[p*ASTR + c] = __float2bfloat16(av - an);
    }
    __syncthreads();

    float U[2][3][4], V[2][3][4], keep[2][3][4];

    // ===== layer 1 =====
    mmaGemv(aSb, aDb, wS0, wS1, warpM, warpN, lane, g, tig, U, V);
    __syncthreads();
    #pragma unroll
    for (int mi = 0; mi < 2; mi++)
        #pragma unroll
        for (int ni = 0; ni < 3; ni++) {
            const int o = warpN*24 + ni*8 + 2*tig;
            const float bk0 = b1[n*BS + o],        bk1 = b1[n*BS + o + 1];
            const float bn0 = b1[(NB+n)*BS + o],   bn1 = b1[(NB+n)*BS + o + 1];
            const int p = warpM*32 + mi*16 + g;
            #pragma unroll
            for (int hh = 0; hh < 2; hh++) {
                float Uu0 = U[mi][ni][2*hh], Uu1 = U[mi][ni][2*hh+1];
                float Vv0 = V[mi][ni][2*hh], Vv1 = V[mi][ni][2*hh+1];
                float k0 = fmaxf(fmaf(0.5f, Uu0 + Vv0, bk0), 0.f);
                float n0 = fmaxf(fmaf(0.5f, Uu0 - Vv0, bn0), 0.f);
                float k1 = fmaxf(fmaf(0.5f, Uu1 + Vv1, bk1), 0.f);
                float n1 = fmaxf(fmaf(0.5f, Uu1 - Vv1, bn1), 0.f);
                keep[mi][ni][2*hh] = n0; keep[mi][ni][2*hh+1] = n1;
                const int pp = p + 8*hh;
                *(__nv_bfloat162*)&aS[pp*ASTR + o] = __floats2bfloat162_rn(k0 + n0, k1 + n1);
                *(__nv_bfloat162*)&aD[pp*ASTR + o] = __floats2bfloat162_rn(k0 - n0, k1 - n1);
            }
        }
    for (int e = tid; e < 9216; e += 512) {
        int i = e / 96, o = e - 96*i;
        wS0[o*WSTR + i] = __float2bfloat16(w2[(size_t)n*9216 + e]);
        wS1[o*WSTR + i] = __float2bfloat16(w2[(size_t)(NB+n)*9216 + e]);
    }
    __syncthreads();

    // ===== layer 2 (o2_k) =====
    mmaGemv(aSb, aDb, wS0, wS1, warpM, warpN, lane, g, tig, U, V);
    __syncthreads();
    #pragma unroll
    for (int mi = 0; mi < 2; mi++)
        #pragma unroll
        for (int ni = 0; ni < 3; ni++) {
            const int o = warpN*24 + ni*8 + 2*tig;
            const float bk0 = b2[n*BS + o], bk1 = b2[n*BS + o + 1];
            const int p = warpM*32 + mi*16 + g;
            #pragma unroll
            for (int hh = 0; hh < 2; hh++) {
                float ok0 = fmaf(0.5f, U[mi][ni][2*hh]   + V[mi][ni][2*hh],   bk0);
                float ok1 = fmaf(0.5f, U[mi][ni][2*hh+1] + V[mi][ni][2*hh+1], bk1);
                float un0 = keep[mi][ni][2*hh], un1 = keep[mi][ni][2*hh+1];
                keep[mi][ni][2*hh] = ok0; keep[mi][ni][2*hh+1] = ok1;
                const int pp = p + 8*hh;
                *(__nv_bfloat162*)&aS[pp*ASTR + o] = __floats2bfloat162_rn(un0 + ok0, un1 + ok1);
                *(__nv_bfloat162*)&aD[pp*ASTR + o] = __floats2bfloat162_rn(un0 - ok0, un1 - ok1);
            }
        }
    __syncthreads();

    // ===== layer 2 (o2_nk) + soft-threshold =====
    mmaGemv(aSb, aDb, wS0, wS1, warpM, warpN, lane, g, tig, U, V);
    __syncthreads();
    float* sOut = (float*)(smc + MO_AS);
    #pragma unroll
    for (int mi = 0; mi < 2; mi++)
        #pragma unroll
        for (int ni = 0; ni < 3; ni++) {
            const int o = warpN*24 + ni*8 + 2*tig;
            const float bn0 = b2[(NB+n)*BS + o], bn1 = b2[(NB+n)*BS + o + 1];
            const int p = warpM*32 + mi*16 + g;
            #pragma unroll
            for (int hh = 0; hh < 2; hh++) {
                float o2n0 = fmaf(0.5f, U[mi][ni][2*hh]   + V[mi][ni][2*hh],   bn0);
                float o2n1 = fmaf(0.5f, U[mi][ni][2*hh+1] + V[mi][ni][2*hh+1], bn1);
                float t0 = keep[mi][ni][2*hh]   + o2n0;
                float t1 = keep[mi][ni][2*hh+1] + o2n1;
                const int pp = p + 8*hh;
                sOut[o*SOP + pp]     = copysignf(fmaxf(fabsf(t0) - 0.01f, 0.f), t0);
                sOut[(o+1)*SOP + pp] = copysignf(fmaxf(fabsf(t1) - 0.01f, 0.f), t1);
            }
        }
    __syncthreads();
    float* outp = (float*)g_B;   // s as fp32, exactly fills the bf16 slab bytes
    for (int e = tid; e < 12288; e += 512) {
        int p = e / 96, c = e - 96*p;
        outp[(size_t)(p0 + p)*CCH + n*BS + c] = sOut[c*SOP + p];
    }
}

// ---------------- inverse W-FFT (65 -> 256) + scale + residual : g_B -> out ----------------
__global__ __launch_bounds__(256) void kIW(const float* __restrict__ x, float* __restrict__ out)
{
    __shared__ float2 Ys[256*17];
    __shared__ float2 stw[256];
    const int bh = blockIdx.x, c0 = blockIdx.y * 16, tid = threadIdx.x;
    if (tid < 256) stw[tid] = g_tw256[tid];
    __syncthreads();
    const cbf* __restrict__ zp = g_B + (size_t)bh*KWV*CCH + c0;
    for (int e = tid; e < 4096; e += 256) {
        int c = e & 15, n2 = (e >> 4) & 15, k1 = e >> 8;
        float2 acc = make_float2(0.f, 0.f);
        int idx = (k1 * n2) & 255, step = (k1 * 16) & 255;
        int nmax = (n2 == 0) ? 5 : 4;
        for (int n1 = 0; n1 < nmax; n1++) {
            int w = (n1 << 4) + n2;
            float2 z = b2f(zp[(size_t)w*CCH + c]);
            cmadd(acc, z, stw[idx]);
            idx = (idx + step) & 255;
        }
        Ys[(k1*16 + n2)*17 + c] = acc;
    }
    __syncthreads();
    const float invN = 1.0f / 50331648.0f;
    {
        const int k1 = tid >> 4, c = tid & 15;
        float2 v[16];
        #pragma unroll
        for (int n2 = 0; n2 < 16; n2++) v[n2] = Ys[(k1*16 + n2)*17 + c];
        fft16r(v);
        #pragma unroll
        for (int k2 = 0; k2 < 16; k2++) {
            float2 acc = v[FFI(k2)];
            size_t a = ((size_t)bh*WW + k1 + 16*k2)*CCH + c0 + c;
            out[a] = fmaf(acc.x + acc.y, invN, x[a]);
        }
    }
}

extern "C" void kernel_launch(void* const* d_in, const int* in_sizes, int n_in,
                              void* d_out, int out_size)
{
    const float* x  = (const float*)d_in[0];
    const float* w1 = (const float*)d_in[1];
    const float* b1 = (const float*)d_in[2];
    const float* w2 = (const float*)d_in[3];
    const float* b2 = (const float*)d_in[4];
    float* out = (float*)d_out;

    cudaFuncSetAttribute(kMLP,   cudaFuncAttributeMaxDynamicSharedMemorySize, MSM);
    cudaFuncSetAttribute(kF1,    cudaFuncAttributeMaxDynamicSharedMemorySize, 54272);
    cudaFuncSetAttribute(kFC<0>, cudaFuncAttributeMaxDynamicSharedMemorySize, 55296);
    cudaFuncSetAttribute(kFC<1>, cudaFuncAttributeMaxDynamicSharedMemorySize, 55296);

    kPrep<<<3, 256>>>();
    kF1 <<<dim3(BB*HH, CCH/16), 256, 54272>>>(x);   // x -> A (bf16 cplx)
    kFC<0><<<NPOS/4, 192, 55296>>>();               // A -> B
    kFHB<0><<<dim3(KWV, CCH/16), 256>>>();          // B -> A
    kMLP<<<dim3(NPOS/128, NB), 512, MSM>>>(x, w1, b1, w2, b2);  // A,x -> s(f32) in B
    kFC<1><<<NPOS/4, 192, 55296>>>();               // B(real f32) -> A
    kFHB<1><<<dim3(KWV, CCH/16), 256>>>();          // A -> B
    kIW <<<dim3(BB*HH, CCH/16), 256>>>(x, out);     // B -> out
}

// round 11
// speedup vs baseline: 4.3445x; 1.1583x over previous
#include <cuda_runtime.h>
#include <cuda_bf16.h>
#include <math.h>
#include <stdint.h>

#define BB 2
#define HH 128
#define WW 256
#define CCH 768
#define KWV 65
#define NB 8
#define BS 96
#define NPOS (BB*HH*KWV)
#define SLABN (NPOS*CCH)

typedef unsigned long long u64;
typedef __nv_bfloat162 cbf;

__device__ cbf g_A[SLABN];     // ~51 MB (complex bf16)
__device__ cbf g_B[SLABN];     // ~51 MB
__device__ float2 g_tw256[256];
__device__ float2 g_tw768[768];
__device__ float2 g_tw128[128];

__device__ __forceinline__ float2 b2f(cbf v) {
    return make_float2(__bfloat162float(v.x), __bfloat162float(v.y));
}
__device__ __forceinline__ cbf f2b(float2 v) {
    return __floats2bfloat162_rn(v.x, v.y);
}
__device__ __forceinline__ void cmadd(float2& acc, float2 z, float2 t) {
    acc.x = fmaf(z.x, t.x, fmaf(-z.y, t.y, acc.x));
    acc.y = fmaf(z.x, t.y, fmaf( z.y, t.x, acc.y));
}
__device__ __forceinline__ float2 cmul(float2 a, float2 b) {
    return make_float2(a.x*b.x - a.y*b.y, a.x*b.y + a.y*b.x);
}

// ---------------- register FFT primitives ----------------
#define FC1 0.92387953251128674f
#define FS1 0.38268343236508977f
#define FR  0.70710678118654752f

__device__ __forceinline__ float2 cadd2(float2 a, float2 b) {
    return make_float2(fmaf(b.x, 1.0f, a.x), fmaf(b.y, 1.0f, a.y));
}
__device__ __forceinline__ float2 csub2(float2 a, float2 b) {
    return make_float2(fmaf(b.x, -1.0f, a.x), fmaf(b.y, -1.0f, a.y));
}
__device__ __forceinline__ float2 cmulK(float2 z, float C, float S) {
    return make_float2(fmaf(z.x, C, -z.y*S), fmaf(z.y, C, z.x*S));
}
__device__ __forceinline__ void dft4(float2& a, float2& b, float2& c, float2& d) {
    float2 apc = cadd2(a, c), amc = csub2(a, c);
    float2 bpd = cadd2(b, d), bmd = csub2(b, d);
    float2 jb = make_float2(bmd.y, -bmd.x);
    a = cadd2(apc, bpd);
    b = cadd2(amc, jb);
    c = csub2(apc, bpd);
    d = csub2(amc, jb);
}
#define FFI(k) (4*((k)&3) + ((k)>>2))
__device__ __forceinline__ void fft16r(float2 v[16]) {
    dft4(v[0], v[4], v[8],  v[12]);
    dft4(v[1], v[5], v[9],  v[13]);
    dft4(v[2], v[6], v[10], v[14]);
    dft4(v[3], v[7], v[11], v[15]);
    v[5]  = cmulK(v[5],  FC1, -FS1);
    v[6]  = cmulK(v[6],  FR,  -FR );
    v[7]  = cmulK(v[7],  FS1, -FC1);
    v[9]  = cmulK(v[9],  FR,  -FR );
    v[10] = make_float2(v[10].y, -v[10].x);
    v[11] = cmulK(v[11], -FR,  -FR );
    v[13] = cmulK(v[13], FS1, -FC1);
    v[14] = cmulK(v[14], -FR,  -FR );
    v[15] = cmulK(v[15], -FC1,  FS1);
    dft4(v[0],  v[1],  v[2],  v[3]);
    dft4(v[4],  v[5],  v[6],  v[7]);
    dft4(v[8],  v[9],  v[10], v[11]);
    dft4(v[12], v[13], v[14], v[15]);
}
__device__ __forceinline__ void fft8r(float2 v[8]) {
    float2 a0 = cadd2(v[0], v[4]), a1 = cadd2(v[1], v[5]);
    float2 a2 = cadd2(v[2], v[6]), a3 = cadd2(v[3], v[7]);
    float2 b0 = csub2(v[0], v[4]);
    float2 t1 = csub2(v[1], v[5]);
    float2 t2 = csub2(v[2], v[6]);
    float2 t3 = csub2(v[3], v[7]);
    float2 b1 = cmulK(t1, FR, -FR);
    float2 b2 = make_float2(t2.y, -t2.x);
    float2 b3 = cmulK(t3, -FR, -FR);
    dft4(a0, a1, a2, a3);
    dft4(b0, b1, b2, b3);
    v[0] = a0; v[2] = a1; v[4] = a2; v[6] = a3;
    v[1] = b0; v[3] = b1; v[5] = b2; v[7] = b3;
}

// ---------------- HMMA helpers ----------------
__device__ __forceinline__ uint32_t smem_u32(const void* p) {
    uint32_t a;
    asm("{ .reg .u64 t; cvta.to.shared.u64 t, %1; cvt.u32.u64 %0, t; }" : "=r"(a) : "l"(p));
    return a;
}
__device__ __forceinline__ void ldmA(unsigned r[4], uint32_t addr) {
    asm volatile("ldmatrix.sync.aligned.m8n8.x4.shared.b16 {%0,%1,%2,%3}, [%4];"
        : "=r"(r[0]),"=r"(r[1]),"=r"(r[2]),"=r"(r[3]) : "r"(addr));
}
__device__ __forceinline__ void mma16816(float d[4], const unsigned a[4], const unsigned b[2]) {
    asm volatile("mma.sync.aligned.m16n8k16.row.col.f32.bf16.bf16.f32 "
        "{%0,%1,%2,%3}, {%4,%5,%6,%7}, {%8,%9}, {%0,%1,%2,%3};"
        : "+f"(d[0]),"+f"(d[1]),"+f"(d[2]),"+f"(d[3])
        : "r"(a[0]),"r"(a[1]),"r"(a[2]),"r"(a[3]), "r"(b[0]),"r"(b[1]));
}

__global__ void kPrep()
{
    int t = blockIdx.x * blockDim.x + threadIdx.x;
    const double TP = 6.283185307179586476925286766559;
    if (t < 768) {
        double s, c;
        sincos(-TP * (double)t / 768.0, &s, &c);
        g_tw768[t] = make_float2((float)c, (float)s);
        if (t < 256) { sincos(-TP*(double)t/256.0, &s, &c); g_tw256[t] = make_float2((float)c,(float)s); }
        if (t < 128) { sincos(-TP*(double)t/128.0, &s, &c); g_tw128[t] = make_float2((float)c,(float)s); }
    }
}

// ---------------- forward W-FFT (256=16x16) pruned kw<65 : x -> g_A ----------------
__global__ __launch_bounds__(256) void kF1(const float* __restrict__ x)
{
    extern __shared__ float smF1[];
    float*  Xs  = smF1;
    float2* Ys  = (float2*)(smF1 + 4352);
    float2* stw = Ys + 4352;
    const int bh = blockIdx.x, c0 = blockIdx.y * 16, tid = threadIdx.x;
    if (tid < 256) stw[tid] = g_tw256[tid];
    const float* xp = x + (size_t)bh * (WW*CCH) + c0;
    for (int e = tid; e < 4096; e += 256)
        Xs[(e >> 4)*17 + (e & 15)] = xp[(size_t)(e >> 4) * CCH + (e & 15)];
    __syncthreads();
    {
        const int n2 = tid >> 4, c = tid & 15;
        float2 u[16];
        #pragma unroll
        for (int n1 = 0; n1 < 16; n1++) u[n1] = make_float2(Xs[(16*n1 + n2)*17 + c], 0.f);
        fft16r(u);
        #pragma unroll
        for (int k1 = 0; k1 < 16; k1++)
            Ys[(k1*16 + n2)*17 + c] = cmul(u[FFI(k1)], stw[n2*k1]);
    }
    __syncthreads();
    {
        const int k1 = tid >> 4, c = tid & 15;
        float2 v[16];
        #pragma unroll
        for (int n2 = 0; n2 < 16; n2++) v[n2] = Ys[(k1*16 + n2)*17 + c];
        fft16r(v);
        cbf* dst = g_A + ((size_t)bh*KWV)*CCH + c0 + c;
        #pragma unroll
        for (int k2 = 0; k2 < 4; k2++)
            dst[(size_t)(k1 + 16*k2)*CCH] = f2b(v[FFI(k2)]);
        if (k1 == 0)
            dst[(size_t)64*CCH] = f2b(v[FFI(4)]);
    }
}

// ---------------- C-FFT 768 = 16x16x3 : RIN=0: g_A->g_B; RIN=1: real(f32) g_B->g_A ----------------
// smem: zb cbf[4*768] (12288B), Ab float2[4*768] (24576B), stw256 (2048B), stw768 (4096B) = 43008B
template<int RIN>
__global__ __launch_bounds__(192) void kFC()
{
    extern __shared__ char smCb[];
    cbf*    zb     = (cbf*)smCb;                   // 4*768 cbf
    float2* Ab     = (float2*)(smCb + 12288);      // 4*768 float2
    float2* stw256 = (float2*)(smCb + 36864);      // 256
    float2* stw768 = (float2*)(smCb + 38912);      // 512
    const int tid = threadIdx.x;
    const int r = tid / 48, l = tid - r*48;
    const size_t row0 = (size_t)blockIdx.x * 4;
    for (int e = tid; e < 256; e += 192) stw256[e] = g_tw256[e];
    for (int e = tid; e < 512; e += 192) stw768[e] = g_tw768[e];
    if (RIN) {
        const float* sp = (const float*)g_B;   // s stored fp32
        for (int e = tid; e < 3072; e += 192)
            zb[e] = f2b(make_float2(sp[row0*768 + e], 0.f));
    } else {
        for (int e = tid; e < 3072; e += 192)
            zb[e] = g_A[row0*768 + e];         // plain bf16 copy, no cvt
    }
    __syncthreads();
    {   // stage1: (r, n3, n2): FFT-16 over n1, then x tw256[n2*k1]
        const int n3 = l >> 4, n2 = l & 15;
        float2 u[16];
        #pragma unroll
        for (int n1 = 0; n1 < 16; n1++) u[n1] = b2f(zb[r*768 + n3 + 3*n2 + 48*n1]);
        fft16r(u);
        #pragma unroll
        for (int k1 = 0; k1 < 16; k1++)
            Ab[r*768 + (n3*16 + k1)*16 + n2] = cmul(u[FFI(k1)], stw256[n2*k1]);
    }
    __syncthreads();
    {   // stage2: (r, n3, k1): FFT-16 over n2, store bf16
        const int n3 = l >> 4, k1 = l & 15;
        float2 v[16];
        #pragma unroll
        for (int n2 = 0; n2 < 16; n2++) v[n2] = Ab[r*768 + (n3*16 + k1)*16 + n2];
        fft16r(v);
        #pragma unroll
        for (int k2 = 0; k2 < 16; k2++)
            zb[r*768 + (n3*16 + k1)*16 + k2] = f2b(v[FFI(k2)]);
    }
    __syncthreads();
    {   // stage3: radix-3 combine
        cbf* dst = RIN ? g_A : g_B;
        const float s3 = 0.86602540378443865f;
        for (int e = tid; e < 1024; e += 192) {
            const int rr = e >> 8, m = e & 255;
            const int k1 = m & 15, k2 = m >> 4;
            float2 b0 = b2f(zb[rr*768 +       k1*16 + k2]);
            float2 b1 = cmul(b2f(zb[rr*768 + 256 + k1*16 + k2]), stw768[m]);
            float2 b2 = cmul(b2f(zb[rr*768 + 512 + k1*16 + k2]), stw768[2*m]);
            float2 t1 = make_float2(b1.x + b2.x, b1.y + b2.y);
            float2 t2 = make_float2(b1.x - b2.x, b1.y - b2.y);
            dst[(row0+rr)*768 + m] = f2b(make_float2(b0.x + t1.x, b0.y + t1.y));
            float xr = fmaf(-0.5f, t1.x, b0.x);
            float xi = fmaf(-0.5f, t1.y, b0.y);
            dst[(row0+rr)*768 + m + 256] = f2b(make_float2(fmaf( s3, t2.y, xr), fmaf(-s3, t2.x, xi)));
            dst[(row0+rr)*768 + m + 512] = f2b(make_float2(fmaf(-s3, t2.y, xr), fmaf( s3, t2.x, xi)));
        }
    }
}

// ---------------- H-FFT (128=16x8) + length-2 B-FFT, pointer-stride loads ----------------
template<int SWAP>
__global__ __launch_bounds__(256) void kFHB()
{
    __shared__ float2 Ys[2][16][8][16];
    __shared__ float2 stw[128];
    const cbf* __restrict__ src = SWAP ? g_A : g_B;
    cbf* dst = SWAP ? g_B : g_A;
    const int kw = blockIdx.x, c0 = blockIdx.y * 16, tid = threadIdx.x;
    if (tid < 128) stw[tid] = g_tw128[tid];
    {
        const int c = tid & 15, n2 = (tid >> 4) & 7, bb = tid >> 7;
        const size_t hstep = (size_t)8 * KWV * CCH;
        const cbf* p0 = src + ((size_t)n2 * KWV + kw)*CCH + c0 + c;
        const cbf* p1 = p0 + (size_t)HH * KWV * CCH;
        float2 u[16];
        #pragma unroll
        for (int n1 = 0; n1 < 16; n1++) {
            float2 a = b2f(*p0), b = b2f(*p1);
            p0 += hstep; p1 += hstep;
            u[n1] = bb ? make_float2(a.x - b.x, a.y - b.y)
                       : make_float2(a.x + b.x, a.y + b.y);
        }
        __syncthreads();
        fft16r(u);
        #pragma unroll
        for (int k1 = 0; k1 < 16; k1++)
            Ys[bb][k1][n2][c] = cmul(u[FFI(k1)], stw[k1*n2]);
    }
    __syncthreads();
    #pragma unroll
    for (int r = 0; r < 2; r++) {
        int t = tid + 256*r;
        int c = t & 15, k1 = (t >> 4) & 15, bb = t >> 8;
        float2 v[8];
        #pragma unroll
        for (int n2 = 0; n2 < 8; n2++) v[n2] = Ys[bb][k1][n2][c];
        fft8r(v);
        const size_t kstep = (size_t)16 * KWV * CCH;
        cbf* q = dst + (((size_t)bb*HH + k1)*KWV + kw)*CCH + c0 + c;
        #pragma unroll
        for (int k2 = 0; k2 < 8; k2++) {
            *q = f2b(v[k2]);
            q += kstep;
        }
    }
}

// ---------------- HMMA MLP (bf16 tensor-core, Karatsuba): g_A,x -> s (f32) in g_B ----------------
#define MO_AS 0
#define MO_AD 26624
#define MO_W0 53248
#define MO_W1 73216
#define MSM   93184
#define ASTR  104
#define WSTR  104
#define SOP   133

__device__ __forceinline__ void mmaGemv(uint32_t aSb, uint32_t aDb,
    const __nv_bfloat16* __restrict__ w0, const __nv_bfloat16* __restrict__ w1v,
    int warpM, int warpN, int lane, int g, int tig,
    float U[2][3][4], float V[2][3][4])
{
    #pragma unroll
    for (int mi = 0; mi < 2; mi++)
        #pragma unroll
        for (int ni = 0; ni < 3; ni++)
            #pragma unroll
            for (int j = 0; j < 4; j++) { U[mi][ni][j] = 0.f; V[mi][ni][j] = 0.f; }
    const uint32_t lrow = (uint32_t)(lane & 15) * (ASTR*2);
    const uint32_t lcol = (uint32_t)((lane >> 4) << 4);
    #pragma unroll
    for (int kb = 0; kb < 6; kb++) {
        const int kc = kb * 16;
        unsigned aS0[4], aS1[4], aD0[4], aD1[4];
        uint32_t base = lrow + lcol + kc*2;
        ldmA(aS0, aSb + (uint32_t)(warpM*32     )*(ASTR*2) + base);
        ldmA(aS1, aSb + (uint32_t)(warpM*32 + 16)*(ASTR*2) + base);
        ldmA(aD0, aDb + (uint32_t)(warpM*32     )*(ASTR*2) + base);
        ldmA(aD1, aDb + (uint32_t)(warpM*32 + 16)*(ASTR*2) + base);
        #pragma unroll
        for (int ni = 0; ni < 3; ni++) {
            const int orow = warpN*24 + ni*8 + g;
            unsigned b0[2], b1[2];
            b0[0] = *(const unsigned*)&w0 [orow*WSTR + kc + 2*tig];
            b0[1] = *(const unsigned*)&w0 [orow*WSTR + kc + 8 + 2*tig];
            b1[0] = *(const unsigned*)&w1v[orow*WSTR + kc + 2*tig];
            b1[1] = *(const unsigned*)&w1v[orow*WSTR + kc + 8 + 2*tig];
            mma16816(U[0][ni], aS0, b0);
            mma16816(U[1][ni], aS1, b0);
            mma16816(V[0][ni], aD0, b1);
            mma16816(V[1][ni], aD1, b1);
        }
    }
}

__global__ __launch_bounds__(512, 1) void kMLP(const float* __restrict__ x,
    const float* __restrict__ w1, const float* __restrict__ b1,
    const float* __restrict__ w2, const float* __restrict__ b2)
{
    extern __shared__ char smc[];
    __nv_bfloat16* aS  = (__nv_bfloat16*)(smc + MO_AS);
    __nv_bfloat16* aD  = (__nv_bfloat16*)(smc + MO_AD);
    __nv_bfloat16* wS0 = (__nv_bfloat16*)(smc + MO_W0);
    __nv_bfloat16* wS1 = (__nv_bfloat16*)(smc + MO_W1);
    const uint32_t aSb = smem_u32(aS), aDb = smem_u32(aD);
    const int n = blockIdx.y, p0 = blockIdx.x * 128, tid = threadIdx.x;
    const int wid = tid >> 5, lane = tid & 31;
    const int warpM = wid >> 2, warpN = wid & 3;
    const int g = lane >> 2, tig = lane & 3;

    for (int e = tid; e < 9216; e += 512) {
        int i = e / 96, o = e - 96*i;
        wS0[o*WSTR + i] = __float2bfloat16(w1[(size_t)n*9216 + e]);
        wS1[o*WSTR + i] = __float2bfloat16(w1[(size_t)(NB+n)*9216 + e]);
    }
    for (int e = tid; e < 12288; e += 512) {
        int p = e / 96, c = e - 96*p;
        int pgl = p0 + p;
        int b = (pgl >= HH*KWV) ? 1 : 0;
        int r = pgl - b*(HH*KWV);
        int h = r / KWV, kw = r - h*KWV;
        float2 z = b2f(g_A[(size_t)pgl*CCH + n*BS + c]);
        float av = z.x + z.y;
        int hn = (HH - h) & (HH-1), wn = (WW - kw) & (WW-1);
        float an = x[(((size_t)b*HH + hn)*WW + wn)*CCH + n*BS + c];
        aS[p*ASTR + c] = __float2bfloat16(av + an);
        aD[p*ASTR + c] = __float2bfloat16(av - an);
    }
    __syncthreads();

    float U[2][3][4], V[2][3][4], keep[2][3][4];

    // ===== layer 1 =====
    mmaGemv(aSb, aDb, wS0, wS1, warpM, warpN, lane, g, tig, U, V);
    __syncthreads();
    #pragma unroll
    for (int mi = 0; mi < 2; mi++)
        #pragma unroll
        for (int ni = 0; ni < 3; ni++) {
            const int o = warpN*24 + ni*8 + 2*tig;
            const float bk0 = b1[n*BS + o],        bk1 = b1[n*BS + o + 1];
            const float bn0 = b1[(NB+n)*BS + o],   bn1 = b1[(NB+n)*BS + o + 1];
            const int p = warpM*32 + mi*16 + g;
            #pragma unroll
            for (int hh = 0; hh < 2; hh++) {
                float Uu0 = U[mi][ni][2*hh], Uu1 = U[mi][ni][2*hh+1];
                float Vv0 = V[mi][ni][2*hh], Vv1 = V[mi][ni][2*hh+1];
                float k0 = fmaxf(fmaf(0.5f, Uu0 + Vv0, bk0), 0.f);
                float n0 = fmaxf(fmaf(0.5f, Uu0 - Vv0, bn0), 0.f);
                float k1 = fmaxf(fmaf(0.5f, Uu1 + Vv1, bk1), 0.f);
                float n1 = fmaxf(fmaf(0.5f, Uu1 - Vv1, bn1), 0.f);
                keep[mi][ni][2*hh] = n0; keep[mi][ni][2*hh+1] = n1;
                const int pp = p + 8*hh;
                *(__nv_bfloat162*)&aS[pp*ASTR + o] = __floats2bfloat162_rn(k0 + n0, k1 + n1);
                *(__nv_bfloat162*)&aD[pp*ASTR + o] = __floats2bfloat162_rn(k0 - n0, k1 - n1);
            }
        }
    for (int e = tid; e < 9216; e += 512) {
        int i = e / 96, o = e - 96*i;
        wS0[o*WSTR + i] = __float2bfloat16(w2[(size_t)n*9216 + e]);
        wS1[o*WSTR + i] = __float2bfloat16(w2[(size_t)(NB+n)*9216 + e]);
    }
    __syncthreads();

    // ===== layer 2 (o2_k) =====
    mmaGemv(aSb, aDb, wS0, wS1, warpM, warpN, lane, g, tig, U, V);
    __syncthreads();
    #pragma unroll
    for (int mi = 0; mi < 2; mi++)
        #pragma unroll
        for (int ni = 0; ni < 3; ni++) {
            const int o = warpN*24 + ni*8 + 2*tig;
            const float bk0 = b2[n*BS + o], bk1 = b2[n*BS + o + 1];
            const int p = warpM*32 + mi*16 + g;
            #pragma unroll
            for (int hh = 0; hh < 2; hh++) {
                float ok0 = fmaf(0.5f, U[mi][ni][2*hh]   + V[mi][ni][2*hh],   bk0);
                float ok1 = fmaf(0.5f, U[mi][ni][2*hh+1] + V[mi][ni][2*hh+1], bk1);
                float un0 = keep[mi][ni][2*hh], un1 = keep[mi][ni][2*hh+1];
                keep[mi][ni][2*hh] = ok0; keep[mi][ni][2*hh+1] = ok1;
                const int pp = p + 8*hh;
                *(__nv_bfloat162*)&aS[pp*ASTR + o] = __floats2bfloat162_rn(un0 + ok0, un1 + ok1);
                *(__nv_bfloat162*)&aD[pp*ASTR + o] = __floats2bfloat162_rn(un0 - ok0, un1 - ok1);
            }
        }
    __syncthreads();

    // ===== layer 2 (o2_nk) + soft-threshold =====
    mmaGemv(aSb, aDb, wS0, wS1, warpM, warpN, lane, g, tig, U, V);
    __syncthreads();
    float* sOut = (float*)(smc + MO_AS);
    #pragma unroll
    for (int mi = 0; mi < 2; mi++)
        #pragma unroll
        for (int ni = 0; ni < 3; ni++) {
            const int o = warpN*24 + ni*8 + 2*tig;
            const float bn0 = b2[(NB+n)*BS + o], bn1 = b2[(NB+n)*BS + o + 1];
            const int p = warpM*32 + mi*16 + g;
            #pragma unroll
            for (int hh = 0; hh < 2; hh++) {
                float o2n0 = fmaf(0.5f, U[mi][ni][2*hh]   + V[mi][ni][2*hh],   bn0);
                float o2n1 = fmaf(0.5f, U[mi][ni][2*hh+1] + V[mi][ni][2*hh+1], bn1);
                float t0 = keep[mi][ni][2*hh]   + o2n0;
                float t1 = keep[mi][ni][2*hh+1] + o2n1;
                const int pp = p + 8*hh;
                sOut[o*SOP + pp]     = copysignf(fmaxf(fabsf(t0) - 0.01f, 0.f), t0);
                sOut[(o+1)*SOP + pp] = copysignf(fmaxf(fabsf(t1) - 0.01f, 0.f), t1);
            }
        }
    __syncthreads();
    float* outp = (float*)g_B;
    for (int e = tid; e < 12288; e += 512) {
        int p = e / 96, c = e - 96*p;
        outp[(size_t)(p0 + p)*CCH + n*BS + c] = sOut[c*SOP + p];
    }
}

// ---------------- inverse W-FFT (65 -> 256) + scale + residual : g_B -> out ----------------
__global__ __launch_bounds__(256) void kIW(const float* __restrict__ x, float* __restrict__ out)
{
    __shared__ float2 Zs[KWV*16];     // staged slab chunk, 8320B
    __shared__ float2 Ys[256*17];     // 34816B
    __shared__ float2 stw[256];       // 2048B
    const int bh = blockIdx.x, c0 = blockIdx.y * 16, tid = threadIdx.x;
    if (tid < 256) stw[tid] = g_tw256[tid];
    const cbf* __restrict__ zp = g_B + (size_t)bh*KWV*CCH + c0;
    for (int e = tid; e < KWV*16; e += 256) {
        int w = e >> 4, c = e & 15;
        Zs[e] = b2f(zp[(size_t)w*CCH + c]);
    }
    __syncthreads();
    for (int e = tid; e < 4096; e += 256) {
        int c = e & 15, n2 = (e >> 4) & 15, k1 = e >> 8;
        float2 acc = make_float2(0.f, 0.f);
        int idx = (k1 * n2) & 255, step = (k1 * 16) & 255;
        int nmax = (n2 == 0) ? 5 : 4;
        for (int n1 = 0; n1 < nmax; n1++) {
            int w = (n1 << 4) + n2;
            cmadd(acc, Zs[w*16 + c], stw[idx]);
            idx = (idx + step) & 255;
        }
        Ys[(k1*16 + n2)*17 + c] = acc;
    }
    __syncthreads();
    const float invN = 1.0f / 50331648.0f;
    {
        const int k1 = tid >> 4, c = tid & 15;
        float2 v[16];
        #pragma unroll
        for (int n2 = 0; n2 < 16; n2++) v[n2] = Ys[(k1*16 + n2)*17 + c];
        fft16r(v);
        #pragma unroll
        for (int k2 = 0; k2 < 16; k2++) {
            float2 acc = v[FFI(k2)];
            size_t a = ((size_t)bh*WW + k1 + 16*k2)*CCH + c0 + c;
            out[a] = fmaf(acc.x + acc.y, invN, x[a]);
        }
    }
}

extern "C" void kernel_launch(void* const* d_in, const int* in_sizes, int n_in,
                              void* d_out, int out_size)
{
    const float* x  = (const float*)d_in[0];
    const float* w1 = (const float*)d_in[1];
    const float* b1 = (const float*)d_in[2];
    const float* w2 = (const float*)d_in[3];
    const float* b2 = (const float*)d_in[4];
    float* out = (float*)d_out;

    cudaFuncSetAttribute(kMLP,   cudaFuncAttributeMaxDynamicSharedMemorySize, MSM);
    cudaFuncSetAttribute(kF1,    cudaFuncAttributeMaxDynamicSharedMemorySize, 54272);
    cudaFuncSetAttribute(kFC<0>, cudaFuncAttributeMaxDynamicSharedMemorySize, 43008);
    cudaFuncSetAttribute(kFC<1>, cudaFuncAttributeMaxDynamicSharedMemorySize, 43008);

    kPrep<<<3, 256>>>();
    kF1 <<<dim3(BB*HH, CCH/16), 256, 54272>>>(x);   // x -> A (bf16 cplx)
    kFC<0><<<NPOS/4, 192, 43008>>>();               // A -> B
    kFHB<0><<<dim3(KWV, CCH/16), 256>>>();          // B -> A
    kMLP<<<dim3(NPOS/128, NB), 512, MSM>>>(x, w1, b1, w2, b2);  // A,x -> s(f32) in B
    kFC<1><<<NPOS/4, 192, 43008>>>();               // B(real f32) -> A
    kFHB<1><<<dim3(KWV, CCH/16), 256>>>();          // A -> B
    kIW <<<dim3(BB*HH, CCH/16), 256>>>(x, out);     // B -> out
}

// round 12
// speedup vs baseline: 4.6443x; 1.0690x over previous
#include <cuda_runtime.h>
#include <cuda_bf16.h>
#include <math.h>
#include <stdint.h>

#define BB 2
#define HH 128
#define WW 256
#define CCH 768
#define KWV 65
#define NB 8
#define BS 96
#define NPOS (BB*HH*KWV)
#define SLABN (NPOS*CCH)

typedef unsigned long long u64;
typedef __nv_bfloat162 cbf;

__device__ cbf g_A[SLABN];     // ~51 MB (complex bf16)
__device__ cbf g_B[SLABN];     // ~51 MB
__device__ float2 g_tw256[256];
__device__ float2 g_tw768[768];
__device__ float2 g_tw128[128];

#define WSTR 104
__device__ __nv_bfloat16 g_Wb[4][NB][BS*WSTR];   // pre-transposed bf16 weights [o][i]

__device__ __forceinline__ float2 b2f(cbf v) {
    return make_float2(__bfloat162float(v.x), __bfloat162float(v.y));
}
__device__ __forceinline__ cbf f2b(float2 v) {
    return __floats2bfloat162_rn(v.x, v.y);
}
__device__ __forceinline__ void cmadd(float2& acc, float2 z, float2 t) {
    acc.x = fmaf(z.x, t.x, fmaf(-z.y, t.y, acc.x));
    acc.y = fmaf(z.x, t.y, fmaf( z.y, t.x, acc.y));
}
__device__ __forceinline__ float2 cmul(float2 a, float2 b) {
    return make_float2(a.x*b.x - a.y*b.y, a.x*b.y + a.y*b.x);
}

// ---------------- register FFT primitives ----------------
#define FC1 0.92387953251128674f
#define FS1 0.38268343236508977f
#define FR  0.70710678118654752f

__device__ __forceinline__ float2 cadd2(float2 a, float2 b) {
    return make_float2(fmaf(b.x, 1.0f, a.x), fmaf(b.y, 1.0f, a.y));
}
__device__ __forceinline__ float2 csub2(float2 a, float2 b) {
    return make_float2(fmaf(b.x, -1.0f, a.x), fmaf(b.y, -1.0f, a.y));
}
__device__ __forceinline__ float2 cmulK(float2 z, float C, float S) {
    return make_float2(fmaf(z.x, C, -z.y*S), fmaf(z.y, C, z.x*S));
}
__device__ __forceinline__ void dft4(float2& a, float2& b, float2& c, float2& d) {
    float2 apc = cadd2(a, c), amc = csub2(a, c);
    float2 bpd = cadd2(b, d), bmd = csub2(b, d);
    float2 jb = make_float2(bmd.y, -bmd.x);
    a = cadd2(apc, bpd);
    b = cadd2(amc, jb);
    c = csub2(apc, bpd);
    d = csub2(amc, jb);
}
#define FFI(k) (4*((k)&3) + ((k)>>2))
__device__ __forceinline__ void fft16r(float2 v[16]) {
    dft4(v[0], v[4], v[8],  v[12]);
    dft4(v[1], v[5], v[9],  v[13]);
    dft4(v[2], v[6], v[10], v[14]);
    dft4(v[3], v[7], v[11], v[15]);
    v[5]  = cmulK(v[5],  FC1, -FS1);
    v[6]  = cmulK(v[6],  FR,  -FR );
    v[7]  = cmulK(v[7],  FS1, -FC1);
    v[9]  = cmulK(v[9],  FR,  -FR );
    v[10] = make_float2(v[10].y, -v[10].x);
    v[11] = cmulK(v[11], -FR,  -FR );
    v[13] = cmulK(v[13], FS1, -FC1);
    v[14] = cmulK(v[14], -FR,  -FR );
    v[15] = cmulK(v[15], -FC1,  FS1);
    dft4(v[0],  v[1],  v[2],  v[3]);
    dft4(v[4],  v[5],  v[6],  v[7]);
    dft4(v[8],  v[9],  v[10], v[11]);
    dft4(v[12], v[13], v[14], v[15]);
}
__device__ __forceinline__ void fft8r(float2 v[8]) {
    float2 a0 = cadd2(v[0], v[4]), a1 = cadd2(v[1], v[5]);
    float2 a2 = cadd2(v[2], v[6]), a3 = cadd2(v[3], v[7]);
    float2 b0 = csub2(v[0], v[4]);
    float2 t1 = csub2(v[1], v[5]);
    float2 t2 = csub2(v[2], v[6]);
    float2 t3 = csub2(v[3], v[7]);
    float2 b1 = cmulK(t1, FR, -FR);
    float2 b2 = make_float2(t2.y, -t2.x);
    float2 b3 = cmulK(t3, -FR, -FR);
    dft4(a0, a1, a2, a3);
    dft4(b0, b1, b2, b3);
    v[0] = a0; v[2] = a1; v[4] = a2; v[6] = a3;
    v[1] = b0; v[3] = b1; v[5] = b2; v[7] = b3;
}

// ---------------- HMMA helpers ----------------
__device__ __forceinline__ uint32_t smem_u32(const void* p) {
    uint32_t a;
    asm("{ .reg .u64 t; cvta.to.shared.u64 t, %1; cvt.u32.u64 %0, t; }" : "=r"(a) : "l"(p));
    return a;
}
__device__ __forceinline__ void ldmA(unsigned r[4], uint32_t addr) {
    asm volatile("ldmatrix.sync.aligned.m8n8.x4.shared.b16 {%0,%1,%2,%3}, [%4];"
        : "=r"(r[0]),"=r"(r[1]),"=r"(r[2]),"=r"(r[3]) : "r"(addr));
}
__device__ __forceinline__ void mma16816(float d[4], const unsigned a[4], const unsigned b[2]) {
    asm volatile("mma.sync.aligned.m16n8k16.row.col.f32.bf16.bf16.f32 "
        "{%0,%1,%2,%3}, {%4,%5,%6,%7}, {%8,%9}, {%0,%1,%2,%3};"
        : "+f"(d[0]),"+f"(d[1]),"+f"(d[2]),"+f"(d[3])
        : "r"(a[0]),"r"(a[1]),"r"(a[2]),"r"(a[3]), "r"(b[0]),"r"(b[1]));
}

// ---------------- prep: twiddles + bf16 weight transposition ----------------
__global__ void kPrep(const float* __restrict__ w1, const float* __restrict__ w2)
{
    int t = blockIdx.x * blockDim.x + threadIdx.x;
    const double TP = 6.283185307179586476925286766559;
    if (t < 768) {
        double s, c;
        sincos(-TP * (double)t / 768.0, &s, &c);
        g_tw768[t] = make_float2((float)c, (float)s);
        if (t < 256) { sincos(-TP*(double)t/256.0, &s, &c); g_tw256[t] = make_float2((float)c,(float)s); }
        if (t < 128) { sincos(-TP*(double)t/128.0, &s, &c); g_tw128[t] = make_float2((float)c,(float)s); }
    }
    // weights: g_Wb[m][n][o*WSTR+i] = bf16(w[m][n][i*96+o])
    int stride = gridDim.x * blockDim.x;
    for (int e = t; e < 4*NB*BS*BS; e += stride) {
        int m = e / (NB*BS*BS);
        int r = e - m*(NB*BS*BS);
        int n = r / (BS*BS);
        int q = r - n*(BS*BS);
        int i = q / BS, o = q - i*BS;
        const float* src = (m < 2) ? (w1 + (size_t)(m*NB + n)*9216)
                                   : (w2 + (size_t)((m-2)*NB + n)*9216);
        g_Wb[m][n][o*WSTR + i] = __float2bfloat16(src[i*96 + o]);
    }
}

// ---------------- forward W-FFT (256=16x16) pruned kw<65 : x -> g_A ----------------
__global__ __launch_bounds__(256) void kF1(const float* __restrict__ x)
{
    extern __shared__ float smF1[];
    float*  Xs  = smF1;
    float2* Ys  = (float2*)(smF1 + 4352);
    float2* stw = Ys + 4352;
    const int bh = blockIdx.x, c0 = blockIdx.y * 16, tid = threadIdx.x;
    if (tid < 256) stw[tid] = g_tw256[tid];
    const float* xp = x + (size_t)bh * (WW*CCH) + c0;
    for (int e = tid; e < 4096; e += 256)
        Xs[(e >> 4)*17 + (e & 15)] = xp[(size_t)(e >> 4) * CCH + (e & 15)];
    __syncthreads();
    {
        const int n2 = tid >> 4, c = tid & 15;
        float2 u[16];
        #pragma unroll
        for (int n1 = 0; n1 < 16; n1++) u[n1] = make_float2(Xs[(16*n1 + n2)*17 + c], 0.f);
        fft16r(u);
        #pragma unroll
        for (int k1 = 0; k1 < 16; k1++)
            Ys[(k1*16 + n2)*17 + c] = cmul(u[FFI(k1)], stw[n2*k1]);
    }
    __syncthreads();
    {
        const int k1 = tid >> 4, c = tid & 15;
        float2 v[16];
        #pragma unroll
        for (int n2 = 0; n2 < 16; n2++) v[n2] = Ys[(k1*16 + n2)*17 + c];
        fft16r(v);
        cbf* dst = g_A + ((size_t)bh*KWV)*CCH + c0 + c;
        #pragma unroll
        for (int k2 = 0; k2 < 4; k2++)
            dst[(size_t)(k1 + 16*k2)*CCH] = f2b(v[FFI(k2)]);
        if (k1 == 0)
            dst[(size_t)64*CCH] = f2b(v[FFI(4)]);
    }
}

// ---------------- C-FFT 768 = 16x16x3 : RIN=0: g_A->g_B; RIN=1: real(bf16) g_B->g_A ----------------
template<int RIN>
__global__ __launch_bounds__(192) void kFC()
{
    extern __shared__ char smCb[];
    cbf*    zb     = (cbf*)smCb;                   // 4*768 cbf
    float2* Ab     = (float2*)(smCb + 12288);      // 4*768 float2
    float2* stw256 = (float2*)(smCb + 36864);      // 256
    float2* stw768 = (float2*)(smCb + 38912);      // 512
    const int tid = threadIdx.x;
    const int r = tid / 48, l = tid - r*48;
    const size_t row0 = (size_t)blockIdx.x * 4;
    for (int e = tid; e < 256; e += 192) stw256[e] = g_tw256[e];
    for (int e = tid; e < 512; e += 192) stw768[e] = g_tw768[e];
    if (RIN) {
        const __nv_bfloat16* sp = (const __nv_bfloat16*)g_B;   // s stored bf16 real
        for (int e = tid; e < 3072; e += 192) {
            cbf z; z.x = sp[row0*768 + e]; z.y = __float2bfloat16(0.f);
            zb[e] = z;
        }
    } else {
        for (int e = tid; e < 3072; e += 192)
            zb[e] = g_A[row0*768 + e];
    }
    __syncthreads();
    {
        const int n3 = l >> 4, n2 = l & 15;
        float2 u[16];
        #pragma unroll
        for (int n1 = 0; n1 < 16; n1++) u[n1] = b2f(zb[r*768 + n3 + 3*n2 + 48*n1]);
        fft16r(u);
        #pragma unroll
        for (int k1 = 0; k1 < 16; k1++)
            Ab[r*768 + (n3*16 + k1)*16 + n2] = cmul(u[FFI(k1)], stw256[n2*k1]);
    }
    __syncthreads();
    {
        const int n3 = l >> 4, k1 = l & 15;
        float2 v[16];
        #pragma unroll
        for (int n2 = 0; n2 < 16; n2++) v[n2] = Ab[r*768 + (n3*16 + k1)*16 + n2];
        fft16r(v);
        #pragma unroll
        for (int k2 = 0; k2 < 16; k2++)
            zb[r*768 + (n3*16 + k1)*16 + k2] = f2b(v[FFI(k2)]);
    }
    __syncthreads();
    {
        cbf* dst = RIN ? g_A : g_B;
        const float s3 = 0.86602540378443865f;
        for (int e = tid; e < 1024; e += 192) {
            const int rr = e >> 8, m = e & 255;
            const int k1 = m & 15, k2 = m >> 4;
            float2 b0 = b2f(zb[rr*768 +       k1*16 + k2]);
            float2 b1 = cmul(b2f(zb[rr*768 + 256 + k1*16 + k2]), stw768[m]);
            float2 b2 = cmul(b2f(zb[rr*768 + 512 + k1*16 + k2]), stw768[2*m]);
            float2 t1 = make_float2(b1.x + b2.x, b1.y + b2.y);
            float2 t2 = make_float2(b1.x - b2.x, b1.y - b2.y);
            dst[(row0+rr)*768 + m] = f2b(make_float2(b0.x + t1.x, b0.y + t1.y));
            float xr = fmaf(-0.5f, t1.x, b0.x);
            float xi = fmaf(-0.5f, t1.y, b0.y);
            dst[(row0+rr)*768 + m + 256] = f2b(make_float2(fmaf( s3, t2.y, xr), fmaf(-s3, t2.x, xi)));
            dst[(row0+rr)*768 + m + 512] = f2b(make_float2(fmaf(-s3, t2.y, xr), fmaf( s3, t2.x, xi)));
        }
    }
}

// ---------------- H-FFT (128=16x8) + length-2 B-FFT, pointer-stride loads ----------------
template<int SWAP>
__global__ __launch_bounds__(256) void kFHB()
{
    __shared__ float2 Ys[2][16][8][16];
    __shared__ float2 stw[128];
    const cbf* __restrict__ src = SWAP ? g_A : g_B;
    cbf* dst = SWAP ? g_B : g_A;
    const int kw = blockIdx.x, c0 = blockIdx.y * 16, tid = threadIdx.x;
    if (tid < 128) stw[tid] = g_tw128[tid];
    {
        const int c = tid & 15, n2 = (tid >> 4) & 7, bb = tid >> 7;
        const size_t hstep = (size_t)8 * KWV * CCH;
        const cbf* p0 = src + ((size_t)n2 * KWV + kw)*CCH + c0 + c;
        const cbf* p1 = p0 + (size_t)HH * KWV * CCH;
        float2 u[16];
        #pragma unroll
        for (int n1 = 0; n1 < 16; n1++) {
            float2 a = b2f(*p0), b = b2f(*p1);
            p0 += hstep; p1 += hstep;
            u[n1] = bb ? make_float2(a.x - b.x, a.y - b.y)
                       : make_float2(a.x + b.x, a.y + b.y);
        }
        __syncthreads();
        fft16r(u);
        #pragma unroll
        for (int k1 = 0; k1 < 16; k1++)
            Ys[bb][k1][n2][c] = cmul(u[FFI(k1)], stw[k1*n2]);
    }
    __syncthreads();
    #pragma unroll
    for (int r = 0; r < 2; r++) {
        int t = tid + 256*r;
        int c = t & 15, k1 = (t >> 4) & 15, bb = t >> 8;
        float2 v[8];
        #pragma unroll
        for (int n2 = 0; n2 < 8; n2++) v[n2] = Ys[bb][k1][n2][c];
        fft8r(v);
        const size_t kstep = (size_t)16 * KWV * CCH;
        cbf* q = dst + (((size_t)bb*HH + k1)*KWV + kw)*CCH + c0 + c;
        #pragma unroll
        for (int k2 = 0; k2 < 8; k2++) {
            *q = f2b(v[k2]);
            q += kstep;
        }
    }
}

// ---------------- HMMA MLP (bf16 tensor-core, Karatsuba): g_A,x -> s (bf16) in g_B ----------------
#define MO_AS 0
#define MO_AD 26624
#define MO_W0 53248
#define MO_W1 73216
#define MSM   93184
#define ASTR  104
#define SOP   133

__device__ __forceinline__ void mmaGemv(uint32_t aSb, uint32_t aDb,
    const __nv_bfloat16* __restrict__ w0, const __nv_bfloat16* __restrict__ w1v,
    int warpM, int warpN, int lane, int g, int tig,
    float U[2][3][4], float V[2][3][4])
{
    #pragma unroll
    for (int mi = 0; mi < 2; mi++)
        #pragma unroll
        for (int ni = 0; ni < 3; ni++)
            #pragma unroll
            for (int j = 0; j < 4; j++) { U[mi][ni][j] = 0.f; V[mi][ni][j] = 0.f; }
    const uint32_t lrow = (uint32_t)(lane & 15) * (ASTR*2);
    const uint32_t lcol = (uint32_t)((lane >> 4) << 4);
    #pragma unroll
    for (int kb = 0; kb < 6; kb++) {
        const int kc = kb * 16;
        unsigned aS0[4], aS1[4], aD0[4], aD1[4];
        uint32_t base = lrow + lcol + kc*2;
        ldmA(aS0, aSb + (uint32_t)(warpM*32     )*(ASTR*2) + base);
        ldmA(aS1, aSb + (uint32_t)(warpM*32 + 16)*(ASTR*2) + base);
        ldmA(aD0, aDb + (uint32_t)(warpM*32     )*(ASTR*2) + base);
        ldmA(aD1, aDb + (uint32_t)(warpM*32 + 16)*(ASTR*2) + base);
        #pragma unroll
        for (int ni = 0; ni < 3; ni++) {
            const int orow = warpN*24 + ni*8 + g;
            unsigned b0[2], b1[2];
            b0[0] = *(const unsigned*)&w0 [orow*WSTR + kc + 2*tig];
            b0[1] = *(const unsigned*)&w0 [orow*WSTR + kc + 8 + 2*tig];
            b1[0] = *(const unsigned*)&w1v[orow*WSTR + kc + 2*tig];
            b1[1] = *(const unsigned*)&w1v[orow*WSTR + kc + 8 + 2*tig];
            mma16816(U[0][ni], aS0, b0);
            mma16816(U[1][ni], aS1, b0);
            mma16816(V[0][ni], aD0, b1);
            mma16816(V[1][ni], aD1, b1);
        }
    }
}

__global__ __launch_bounds__(512, 1) void kMLP(const float* __restrict__ x,
    const float* __restrict__ b1, const float* __restrict__ b2)
{
    extern __shared__ char smc[];
    __nv_bfloat16* aS  = (__nv_bfloat16*)(smc + MO_AS);
    __nv_bfloat16* aD  = (__nv_bfloat16*)(smc + MO_AD);
    __nv_bfloat16* wS0 = (__nv_bfloat16*)(smc + MO_W0);
    __nv_bfloat16* wS1 = (__nv_bfloat16*)(smc + MO_W1);
    const uint32_t aSb = smem_u32(aS), aDb = smem_u32(aD);
    const int n = blockIdx.y, p0 = blockIdx.x * 128, tid = threadIdx.x;
    const int wid = tid >> 5, lane = tid & 31;
    const int warpM = wid >> 2, warpN = wid & 3;
    const int g = lane >> 2, tig = lane & 3;

    // weight staging: straight bf16 memcpy (pre-transposed in kPrep)
    {
        const uint4* s0 = (const uint4*)g_Wb[0][n];
        const uint4* s1 = (const uint4*)g_Wb[1][n];
        for (int e = tid; e < (BS*WSTR)/8; e += 512) {
            ((uint4*)wS0)[e] = s0[e];
            ((uint4*)wS1)[e] = s1[e];
        }
    }
    for (int e = tid; e < 12288; e += 512) {
        int p = e / 96, c = e - 96*p;
        int pgl = p0 + p;
        int b = (pgl >= HH*KWV) ? 1 : 0;
        int r = pgl - b*(HH*KWV);
        int h = r / KWV, kw = r - h*KWV;
        float2 z = b2f(g_A[(size_t)pgl*CCH + n*BS + c]);
        float av = z.x + z.y;
        int hn = (HH - h) & (HH-1), wn = (WW - kw) & (WW-1);
        float an = x[(((size_t)b*HH + hn)*WW + wn)*CCH + n*BS + c];
        aS[p*ASTR + c] = __float2bfloat16(av + an);
        aD[p*ASTR + c] = __float2bfloat16(av - an);
    }
    __syncthreads();

    float U[2][3][4], V[2][3][4], keep[2][3][4];

    // ===== layer 1 =====
    mmaGemv(aSb, aDb, wS0, wS1, warpM, warpN, lane, g, tig, U, V);
    __syncthreads();
    #pragma unroll
    for (int mi = 0; mi < 2; mi++)
        #pragma unroll
        for (int ni = 0; ni < 3; ni++) {
            const int o = warpN*24 + ni*8 + 2*tig;
            const float bk0 = b1[n*BS + o],        bk1 = b1[n*BS + o + 1];
            const float bn0 = b1[(NB+n)*BS + o],   bn1 = b1[(NB+n)*BS + o + 1];
            const int p = warpM*32 + mi*16 + g;
            #pragma unroll
            for (int hh = 0; hh < 2; hh++) {
                float Uu0 = U[mi][ni][2*hh], Uu1 = U[mi][ni][2*hh+1];
                float Vv0 = V[mi][ni][2*hh], Vv1 = V[mi][ni][2*hh+1];
                float k0 = fmaxf(fmaf(0.5f, Uu0 + Vv0, bk0), 0.f);
                float n0 = fmaxf(fmaf(0.5f, Uu0 - Vv0, bn0), 0.f);
                float k1 = fmaxf(fmaf(0.5f, Uu1 + Vv1, bk1), 0.f);
                float n1 = fmaxf(fmaf(0.5f, Uu1 - Vv1, bn1), 0.f);
                keep[mi][ni][2*hh] = n0; keep[mi][ni][2*hh+1] = n1;
                const int pp = p + 8*hh;
                *(__nv_bfloat162*)&aS[pp*ASTR + o] = __floats2bfloat162_rn(k0 + n0, k1 + n1);
                *(__nv_bfloat162*)&aD[pp*ASTR + o] = __floats2bfloat162_rn(k0 - n0, k1 - n1);
            }
        }
    {
        const uint4* s0 = (const uint4*)g_Wb[2][n];
        const uint4* s1 = (const uint4*)g_Wb[3][n];
        for (int e = tid; e < (BS*WSTR)/8; e += 512) {
            ((uint4*)wS0)[e] = s0[e];
            ((uint4*)wS1)[e] = s1[e];
        }
    }
    __syncthreads();

    // ===== layer 2 (o2_k) =====
    mmaGemv(aSb, aDb, wS0, wS1, warpM, warpN, lane, g, tig, U, V);
    __syncthreads();
    #pragma unroll
    for (int mi = 0; mi < 2; mi++)
        #pragma unroll
        for (int ni = 0; ni < 3; ni++) {
            const int o = warpN*24 + ni*8 + 2*tig;
            const float bk0 = b2[n*BS + o], bk1 = b2[n*BS + o + 1];
            const int p = warpM*32 + mi*16 + g;
            #pragma unroll
            for (int hh = 0; hh < 2; hh++) {
                float ok0 = fmaf(0.5f, U[mi][ni][2*hh]   + V[mi][ni][2*hh],   bk0);
                float ok1 = fmaf(0.5f, U[mi][ni][2*hh+1] + V[mi][ni][2*hh+1], bk1);
                float un0 = keep[mi][ni][2*hh], un1 = keep[mi][ni][2*hh+1];
                keep[mi][ni][2*hh] = ok0; keep[mi][ni][2*hh+1] = ok1;
                const int pp = p + 8*hh;
                *(__nv_bfloat162*)&aS[pp*ASTR + o] = __floats2bfloat162_rn(un0 + ok0, un1 + ok1);
                *(__nv_bfloat162*)&aD[pp*ASTR + o] = __floats2bfloat162_rn(un0 - ok0, un1 - ok1);  // o2_nk uses o2_k
            }
        }
    __syncthreads();

    // ===== layer 2 (o2_nk) + soft-threshold =====
    mmaGemv(aSb, aDb, wS0, wS1, warpM, warpN, lane, g, tig, U, V);
    __syncthreads();
    float* sOut = (float*)(smc + MO_AS);
    #pragma unroll
    for (int mi = 0; mi < 2; mi++)
        #pragma unroll
        for (int ni = 0; ni < 3; ni++) {
            const int o = warpN*24 + ni*8 + 2*tig;
            const float bn0 = b2[(NB+n)*BS + o], bn1 = b2[(NB+n)*BS + o + 1];
            const int p = warpM*32 + mi*16 + g;
            #pragma unroll
            for (int hh = 0; hh < 2; hh++) {
                float o2n0 = fmaf(0.5f, U[mi][ni][2*hh]   + V[mi][ni][2*hh],   bn0);
                float o2n1 = fmaf(0.5f, U[mi][ni][2*hh+1] + V[mi][ni][2*hh+1], bn1);
                float t0 = keep[mi][ni][2*hh]   + o2n0;
                float t1 = keep[mi][ni][2*hh+1] + o2n1;
                const int pp = p + 8*hh;
                sOut[o*SOP + pp]     = copysignf(fmaxf(fabsf(t0) - 0.01f, 0.f), t0);
                sOut[(o+1)*SOP + pp] = copysignf(fmaxf(fabsf(t1) - 0.01f, 0.f), t1);
            }
        }
    __syncthreads();
    __nv_bfloat16* outp = (__nv_bfloat16*)g_B;   // s stored bf16
    for (int e = tid; e < 12288; e += 512) {
        int p = e / 96, c = e - 96*p;
        outp[(size_t)(p0 + p)*CCH + n*BS + c] = __float2bfloat16(sOut[c*SOP + p]);
    }
}

// ---------------- inverse W-FFT (65 -> 256) + scale + residual : g_B -> out ----------------
__global__ __launch_bounds__(256) void kIW(const float* __restrict__ x, float* __restrict__ out)
{
    __shared__ float2 Zs[KWV*16];
    __shared__ float2 Ys[256*17];
    __shared__ float2 stw[256];
    const int bh = blockIdx.x, c0 = blockIdx.y * 16, tid = threadIdx.x;
    if (tid < 256) stw[tid] = g_tw256[tid];
    const cbf* __restrict__ zp = g_B + (size_t)bh*KWV*CCH + c0;
    for (int e = tid; e < KWV*16; e += 256) {
        int w = e >> 4, c = e & 15;
        Zs[e] = b2f(zp[(size_t)w*CCH + c]);
    }
    __syncthreads();
    for (int e = tid; e < 4096; e += 256) {
        int c = e & 15, n2 = (e >> 4) & 15, k1 = e >> 8;
        float2 acc = make_float2(0.f, 0.f);
        int idx = (k1 * n2) & 255, step = (k1 * 16) & 255;
        int nmax = (n2 == 0) ? 5 : 4;
        for (int n1 = 0; n1 < nmax; n1++) {
            int w = (n1 << 4) + n2;
            cmadd(acc, Zs[w*16 + c], stw[idx]);
            idx = (idx + step) & 255;
        }
        Ys[(k1*16 + n2)*17 + c] = acc;
    }
    __syncthreads();
    const float invN = 1.0f / 50331648.0f;
    {
        const int k1 = tid >> 4, c = tid & 15;
        float2 v[16];
        #pragma unroll
        for (int n2 = 0; n2 < 16; n2++) v[n2] = Ys[(k1*16 + n2)*17 + c];
        fft16r(v);
        #pragma unroll
        for (int k2 = 0; k2 < 16; k2++) {
            float2 acc = v[FFI(k2)];
            size_t a = ((size_t)bh*WW + k1 + 16*k2)*CCH + c0 + c;
            out[a] = fmaf(acc.x + acc.y, invN, x[a]);
        }
    }
}

extern "C" void kernel_launch(void* const* d_in, const int* in_sizes, int n_in,
                              void* d_out, int out_size)
{
    const float* x  = (const float*)d_in[0];
    const float* w1 = (const float*)d_in[1];
    const float* b1 = (const float*)d_in[2];
    const float* w2 = (const float*)d_in[3];
    const float* b2 = (const float*)d_in[4];
    float* out = (float*)d_out;

    cudaFuncSetAttribute(kMLP,   cudaFuncAttributeMaxDynamicSharedMemorySize, MSM);
    cudaFuncSetAttribute(kF1,    cudaFuncAttributeMaxDynamicSharedMemorySize, 54272);
    cudaFuncSetAttribute(kFC<0>, cudaFuncAttributeMaxDynamicSharedMemorySize, 43008);
    cudaFuncSetAttribute(kFC<1>, cudaFuncAttributeMaxDynamicSharedMemorySize, 43008);

    kPrep<<<290, 1024>>>(w1, w2);
    kF1 <<<dim3(BB*HH, CCH/16), 256, 54272>>>(x);   // x -> A (bf16 cplx)
    kFC<0><<<NPOS/4, 192, 43008>>>();               // A -> B
    kFHB<0><<<dim3(KWV, CCH/16), 256>>>();          // B -> A
    kMLP<<<dim3(NPOS/128, NB), 512, MSM>>>(x, b1, b2);  // A,x -> s(bf16) in B
    kFC<1><<<NPOS/4, 192, 43008>>>();               // B(real bf16) -> A
    kFHB<1><<<dim3(KWV, CCH/16), 256>>>();          // A -> B
    kIW <<<dim3(BB*HH, CCH/16), 256>>>(x, out);     // B -> out
}

// round 13
// speedup vs baseline: 4.9523x; 1.0663x over previous
#include <cuda_runtime.h>
#include <cuda_bf16.h>
#include <math.h>
#include <stdint.h>

#define BB 2
#define HH 128
#define WW 256
#define CCH 768
#define KWV 65
#define NB 8
#define BS 96
#define NPOS (BB*HH*KWV)
#define SLABN (NPOS*CCH)

typedef unsigned long long u64;
typedef __nv_bfloat162 cbf;

__device__ cbf g_A[SLABN];                 // 51 MB: complex slab / (S,D) real slab pair
__device__ cbf g_B[SLABN];                 // 51 MB
__device__ __nv_bfloat16 g_C[SLABN];       // 25.5 MB: an gather slab (real bf16)
__device__ float2 g_tw256[256];
__device__ float2 g_tw768[768];
__device__ float2 g_tw128[128];

#define WSTR 104
__device__ __nv_bfloat16 g_Wb[4][NB][BS*WSTR];   // pre-transposed bf16 weights [o][i]

__device__ __forceinline__ float2 b2f(cbf v) {
    return make_float2(__bfloat162float(v.x), __bfloat162float(v.y));
}
__device__ __forceinline__ cbf f2b(float2 v) {
    return __floats2bfloat162_rn(v.x, v.y);
}
__device__ __forceinline__ void cmadd(float2& acc, float2 z, float2 t) {
    acc.x = fmaf(z.x, t.x, fmaf(-z.y, t.y, acc.x));
    acc.y = fmaf(z.x, t.y, fmaf( z.y, t.x, acc.y));
}
__device__ __forceinline__ float2 cmul(float2 a, float2 b) {
    return make_float2(a.x*b.x - a.y*b.y, a.x*b.y + a.y*b.x);
}

// ---------------- register FFT primitives ----------------
#define FC1 0.92387953251128674f
#define FS1 0.38268343236508977f
#define FR  0.70710678118654752f

__device__ __forceinline__ float2 cadd2(float2 a, float2 b) {
    return make_float2(fmaf(b.x, 1.0f, a.x), fmaf(b.y, 1.0f, a.y));
}
__device__ __forceinline__ float2 csub2(float2 a, float2 b) {
    return make_float2(fmaf(b.x, -1.0f, a.x), fmaf(b.y, -1.0f, a.y));
}
__device__ __forceinline__ float2 cmulK(float2 z, float C, float S) {
    return make_float2(fmaf(z.x, C, -z.y*S), fmaf(z.y, C, z.x*S));
}
__device__ __forceinline__ void dft4(float2& a, float2& b, float2& c, float2& d) {
    float2 apc = cadd2(a, c), amc = csub2(a, c);
    float2 bpd = cadd2(b, d), bmd = csub2(b, d);
    float2 jb = make_float2(bmd.y, -bmd.x);
    a = cadd2(apc, bpd);
    b = cadd2(amc, jb);
    c = csub2(apc, bpd);
    d = csub2(amc, jb);
}
#define FFI(k) (4*((k)&3) + ((k)>>2))
__device__ __forceinline__ void fft16r(float2 v[16]) {
    dft4(v[0], v[4], v[8],  v[12]);
    dft4(v[1], v[5], v[9],  v[13]);
    dft4(v[2], v[6], v[10], v[14]);
    dft4(v[3], v[7], v[11], v[15]);
    v[5]  = cmulK(v[5],  FC1, -FS1);
    v[6]  = cmulK(v[6],  FR,  -FR );
    v[7]  = cmulK(v[7],  FS1, -FC1);
    v[9]  = cmulK(v[9],  FR,  -FR );
    v[10] = make_float2(v[10].y, -v[10].x);
    v[11] = cmulK(v[11], -FR,  -FR );
    v[13] = cmulK(v[13], FS1, -FC1);
    v[14] = cmulK(v[14], -FR,  -FR );
    v[15] = cmulK(v[15], -FC1,  FS1);
    dft4(v[0],  v[1],  v[2],  v[3]);
    dft4(v[4],  v[5],  v[6],  v[7]);
    dft4(v[8],  v[9],  v[10], v[11]);
    dft4(v[12], v[13], v[14], v[15]);
}
__device__ __forceinline__ void fft8r(float2 v[8]) {
    float2 a0 = cadd2(v[0], v[4]), a1 = cadd2(v[1], v[5]);
    float2 a2 = cadd2(v[2], v[6]), a3 = cadd2(v[3], v[7]);
    float2 b0 = csub2(v[0], v[4]);
    float2 t1 = csub2(v[1], v[5]);
    float2 t2 = csub2(v[2], v[6]);
    float2 t3 = csub2(v[3], v[7]);
    float2 b1 = cmulK(t1, FR, -FR);
    float2 b2 = make_float2(t2.y, -t2.x);
    float2 b3 = cmulK(t3, -FR, -FR);
    dft4(a0, a1, a2, a3);
    dft4(b0, b1, b2, b3);
    v[0] = a0; v[2] = a1; v[4] = a2; v[6] = a3;
    v[1] = b0; v[3] = b1; v[5] = b2; v[7] = b3;
}

// ---------------- HMMA helpers ----------------
__device__ __forceinline__ uint32_t smem_u32(const void* p) {
    uint32_t a;
    asm("{ .reg .u64 t; cvta.to.shared.u64 t, %1; cvt.u32.u64 %0, t; }" : "=r"(a) : "l"(p));
    return a;
}
__device__ __forceinline__ void ldmA(unsigned r[4], uint32_t addr) {
    asm volatile("ldmatrix.sync.aligned.m8n8.x4.shared.b16 {%0,%1,%2,%3}, [%4];"
        : "=r"(r[0]),"=r"(r[1]),"=r"(r[2]),"=r"(r[3]) : "r"(addr));
}
__device__ __forceinline__ void mma16816(float d[4], const unsigned a[4], const unsigned b[2]) {
    asm volatile("mma.sync.aligned.m16n8k16.row.col.f32.bf16.bf16.f32 "
        "{%0,%1,%2,%3}, {%4,%5,%6,%7}, {%8,%9}, {%0,%1,%2,%3};"
        : "+f"(d[0]),"+f"(d[1]),"+f"(d[2]),"+f"(d[3])
        : "r"(a[0]),"r"(a[1]),"r"(a[2]),"r"(a[3]), "r"(b[0]),"r"(b[1]));
}

// ---------------- prep: twiddles + bf16 weight transposition ----------------
__global__ void kPrep(const float* __restrict__ w1, const float* __restrict__ w2)
{
    int t = blockIdx.x * blockDim.x + threadIdx.x;
    const double TP = 6.283185307179586476925286766559;
    if (t < 768) {
        double s, c;
        sincos(-TP * (double)t / 768.0, &s, &c);
        g_tw768[t] = make_float2((float)c, (float)s);
        if (t < 256) { sincos(-TP*(double)t/256.0, &s, &c); g_tw256[t] = make_float2((float)c,(float)s); }
        if (t < 128) { sincos(-TP*(double)t/128.0, &s, &c); g_tw128[t] = make_float2((float)c,(float)s); }
    }
    int stride = gridDim.x * blockDim.x;
    for (int e = t; e < 4*NB*BS*BS; e += stride) {
        int m = e / (NB*BS*BS);
        int r = e - m*(NB*BS*BS);
        int n = r / (BS*BS);
        int q = r - n*(BS*BS);
        int i = q / BS, o = q - i*BS;
        const float* src = (m < 2) ? (w1 + (size_t)(m*NB + n)*9216)
                                   : (w2 + (size_t)((m-2)*NB + n)*9216);
        g_Wb[m][n][o*WSTR + i] = __float2bfloat16(src[i*96 + o]);
    }
}

// ---------------- forward W-FFT (256=16x16) pruned kw<65 + an emit : x -> g_A, g_C ----------------
__global__ __launch_bounds__(256) void kF1(const float* __restrict__ x)
{
    extern __shared__ float smF1[];
    float*  Xs  = smF1;
    float2* Ys  = (float2*)(smF1 + 4352);
    float2* stw = Ys + 4352;
    const int bh = blockIdx.x, c0 = blockIdx.y * 16, tid = threadIdx.x;
    if (tid < 256) stw[tid] = g_tw256[tid];
    const float* xp = x + (size_t)bh * (WW*CCH) + c0;
    for (int e = tid; e < 4096; e += 256)
        Xs[(e >> 4)*17 + (e & 15)] = xp[(size_t)(e >> 4) * CCH + (e & 15)];
    __syncthreads();
    // an gather emit: g_C[(b, (H-h)%H, kw)][c] = x[bh][(W-kw)%W][c]
    {
        const int b = bh >> 7, h = bh & 127;
        const int hn = (HH - h) & (HH - 1);
        __nv_bfloat16* cp = g_C + (((size_t)b*HH + hn)*KWV)*CCH + c0;
        for (int e = tid; e < KWV*16; e += 256) {
            int kw = e >> 4, c = e & 15;
            int wn = (WW - kw) & (WW - 1);
            cp[(size_t)kw*CCH + c] = __float2bfloat16(Xs[wn*17 + c]);
        }
    }
    {
        const int n2 = tid >> 4, c = tid & 15;
        float2 u[16];
        #pragma unroll
        for (int n1 = 0; n1 < 16; n1++) u[n1] = make_float2(Xs[(16*n1 + n2)*17 + c], 0.f);
        fft16r(u);
        #pragma unroll
        for (int k1 = 0; k1 < 16; k1++)
            Ys[(k1*16 + n2)*17 + c] = cmul(u[FFI(k1)], stw[n2*k1]);
    }
    __syncthreads();
    {
        const int k1 = tid >> 4, c = tid & 15;
        float2 v[16];
        #pragma unroll
        for (int n2 = 0; n2 < 16; n2++) v[n2] = Ys[(k1*16 + n2)*17 + c];
        fft16r(v);
        cbf* dst = g_A + ((size_t)bh*KWV)*CCH + c0 + c;
        #pragma unroll
        for (int k2 = 0; k2 < 4; k2++)
            dst[(size_t)(k1 + 16*k2)*CCH] = f2b(v[FFI(k2)]);
        if (k1 == 0)
            dst[(size_t)64*CCH] = f2b(v[FFI(4)]);
    }
}

// ---------------- C-FFT 768 = 16x16x3 : RIN=0: g_A->g_B; RIN=1: real(bf16) g_B->g_A ----------------
template<int RIN>
__global__ __launch_bounds__(192) void kFC()
{
    extern __shared__ char smCb[];
    cbf*    zb     = (cbf*)smCb;
    float2* Ab     = (float2*)(smCb + 12288);
    float2* stw256 = (float2*)(smCb + 36864);
    float2* stw768 = (float2*)(smCb + 38912);
    const int tid = threadIdx.x;
    const int r = tid / 48, l = tid - r*48;
    const size_t row0 = (size_t)blockIdx.x * 4;
    for (int e = tid; e < 256; e += 192) stw256[e] = g_tw256[e];
    for (int e = tid; e < 512; e += 192) stw768[e] = g_tw768[e];
    if (RIN) {
        const __nv_bfloat16* sp = (const __nv_bfloat16*)g_B;
        for (int e = tid; e < 3072; e += 192) {
            cbf z; z.x = sp[row0*768 + e]; z.y = __float2bfloat16(0.f);
            zb[e] = z;
        }
    } else {
        const uint4* sp = (const uint4*)(g_A + row0*768);
        uint4* dp = (uint4*)zb;
        for (int e = tid; e < 768; e += 192)
            dp[e] = sp[e];
    }
    __syncthreads();
    {
        const int n3 = l >> 4, n2 = l & 15;
        float2 u[16];
        #pragma unroll
        for (int n1 = 0; n1 < 16; n1++) u[n1] = b2f(zb[r*768 + n3 + 3*n2 + 48*n1]);
        fft16r(u);
        #pragma unroll
        for (int k1 = 0; k1 < 16; k1++)
            Ab[r*768 + (n3*16 + k1)*16 + n2] = cmul(u[FFI(k1)], stw256[n2*k1]);
    }
    __syncthreads();
    {
        const int n3 = l >> 4, k1 = l & 15;
        float2 v[16];
        #pragma unroll
        for (int n2 = 0; n2 < 16; n2++) v[n2] = Ab[r*768 + (n3*16 + k1)*16 + n2];
        fft16r(v);
        #pragma unroll
        for (int k2 = 0; k2 < 16; k2++)
            zb[r*768 + (n3*16 + k1)*16 + k2] = f2b(v[FFI(k2)]);
    }
    __syncthreads();
    {
        cbf* dst = RIN ? g_A : g_B;
        const float s3 = 0.86602540378443865f;
        for (int e = tid; e < 1024; e += 192) {
            const int rr = e >> 8, m = e & 255;
            const int k1 = m & 15, k2 = m >> 4;
            float2 b0 = b2f(zb[rr*768 +       k1*16 + k2]);
            float2 b1 = cmul(b2f(zb[rr*768 + 256 + k1*16 + k2]), stw768[m]);
            float2 b2 = cmul(b2f(zb[rr*768 + 512 + k1*16 + k2]), stw768[2*m]);
            float2 t1 = make_float2(b1.x + b2.x, b1.y + b2.y);
            float2 t2 = make_float2(b1.x - b2.x, b1.y - b2.y);
            dst[(row0+rr)*768 + m] = f2b(make_float2(b0.x + t1.x, b0.y + t1.y));
            float xr = fmaf(-0.5f, t1.x, b0.x);
            float xi = fmaf(-0.5f, t1.y, b0.y);
            dst[(row0+rr)*768 + m + 256] = f2b(make_float2(fmaf( s3, t2.y, xr), fmaf(-s3, t2.x, xi)));
            dst[(row0+rr)*768 + m + 512] = f2b(make_float2(fmaf(-s3, t2.y, xr), fmaf( s3, t2.x, xi)));
        }
    }
}

// ---------------- H-FFT (128=16x8) + B-FFT.  FWD=1: g_B(+g_C an) -> S/D in g_A ; FWD=0: g_A -> g_B ----------------
template<int FWD>
__global__ __launch_bounds__(256) void kFHB()
{
    __shared__ float2 Ys[2][16][8][16];
    __shared__ float2 stw[128];
    const cbf* __restrict__ src = FWD ? g_B : g_A;
    const int kw = blockIdx.x, c0 = blockIdx.y * 16, tid = threadIdx.x;
    if (tid < 128) stw[tid] = g_tw128[tid];
    {
        const int c = tid & 15, n2 = (tid >> 4) & 7, bb = tid >> 7;
        const size_t hstep = (size_t)8 * KWV * CCH;
        const cbf* p0 = src + ((size_t)n2 * KWV + kw)*CCH + c0 + c;
        const cbf* p1 = p0 + (size_t)HH * KWV * CCH;
        float2 u[16];
        #pragma unroll
        for (int n1 = 0; n1 < 16; n1++) {
            float2 a = b2f(*p0), b = b2f(*p1);
            p0 += hstep; p1 += hstep;
            u[n1] = bb ? make_float2(a.x - b.x, a.y - b.y)
                       : make_float2(a.x + b.x, a.y + b.y);
        }
        __syncthreads();
        fft16r(u);
        #pragma unroll
        for (int k1 = 0; k1 < 16; k1++)
            Ys[bb][k1][n2][c] = cmul(u[FFI(k1)], stw[k1*n2]);
    }
    __syncthreads();
    #pragma unroll
    for (int r = 0; r < 2; r++) {
        int t = tid + 256*r;
        int c = t & 15, k1 = (t >> 4) & 15, bb = t >> 8;
        float2 v[8];
        #pragma unroll
        for (int n2 = 0; n2 < 8; n2++) v[n2] = Ys[bb][k1][n2][c];
        fft8r(v);
        const size_t kstep = (size_t)16 * KWV * CCH;
        const size_t base = (((size_t)bb*HH + k1)*KWV + kw)*CCH + c0 + c;
        if (FWD) {
            // emit S = DHT+an, D = DHT-an as two real bf16 slabs packed in g_A
            __nv_bfloat16* qs = (__nv_bfloat16*)g_A + base;
            __nv_bfloat16* qd = qs + (size_t)SLABN;
            const __nv_bfloat16* qa = g_C + base;
            #pragma unroll
            for (int k2 = 0; k2 < 8; k2++) {
                float av = v[k2].x + v[k2].y;
                float an = __bfloat162float(*qa);
                *qs = __float2bfloat16(av + an);
                *qd = __float2bfloat16(av - an);
                qs += kstep; qd += kstep; qa += kstep;
            }
        } else {
            cbf* q = g_B + base;
            #pragma unroll
            for (int k2 = 0; k2 < 8; k2++) {
                *q = f2b(v[k2]);
                q += kstep;
            }
        }
    }
}

// ---------------- HMMA MLP: g_A(S/D) -> s (bf16) in g_B ----------------
#define MO_AS 0
#define MO_AD 26624
#define MO_W0 53248
#define MO_W1 73216
#define MSM   93184
#define ASTR  104
#define SOP   133

__device__ __forceinline__ void mmaGemv(uint32_t aSb, uint32_t aDb,
    const __nv_bfloat16* __restrict__ w0, const __nv_bfloat16* __restrict__ w1v,
    int warpM, int warpN, int lane, int g, int tig,
    float U[2][3][4], float V[2][3][4])
{
    #pragma unroll
    for (int mi = 0; mi < 2; mi++)
        #pragma unroll
        for (int ni = 0; ni < 3; ni++)
            #pragma unroll
            for (int j = 0; j < 4; j++) { U[mi][ni][j] = 0.f; V[mi][ni][j] = 0.f; }
    const uint32_t lrow = (uint32_t)(lane & 15) * (ASTR*2);
    const uint32_t lcol = (uint32_t)((lane >> 4) << 4);
    #pragma unroll
    for (int kb = 0; kb < 6; kb++) {
        const int kc = kb * 16;
        unsigned aS0[4], aS1[4], aD0[4], aD1[4];
        uint32_t base = lrow + lcol + kc*2;
        ldmA(aS0, aSb + (uint32_t)(warpM*32     )*(ASTR*2) + base);
        ldmA(aS1, aSb + (uint32_t)(warpM*32 + 16)*(ASTR*2) + base);
        ldmA(aD0, aDb + (uint32_t)(warpM*32     )*(ASTR*2) + base);
        ldmA(aD1, aDb + (uint32_t)(warpM*32 + 16)*(ASTR*2) + base);
        #pragma unroll
        for (int ni = 0; ni < 3; ni++) {
            const int orow = warpN*24 + ni*8 + g;
            unsigned b0[2], b1[2];
            b0[0] = *(const unsigned*)&w0 [orow*WSTR + kc + 2*tig];
            b0[1] = *(const unsigned*)&w0 [orow*WSTR + kc + 8 + 2*tig];
            b1[0] = *(const unsigned*)&w1v[orow*WSTR + kc + 2*tig];
            b1[1] = *(const unsigned*)&w1v[orow*WSTR + kc + 8 + 2*tig];
            mma16816(U[0][ni], aS0, b0);
            mma16816(U[1][ni], aS1, b0);
            mma16816(V[0][ni], aD0, b1);
            mma16816(V[1][ni], aD1, b1);
        }
    }
}

__global__ __launch_bounds__(512, 1) void kMLP(const float* __restrict__ b1,
                                               const float* __restrict__ b2)
{
    extern __shared__ char smc[];
    __nv_bfloat16* aS  = (__nv_bfloat16*)(smc + MO_AS);
    __nv_bfloat16* aD  = (__nv_bfloat16*)(smc + MO_AD);
    __nv_bfloat16* wS0 = (__nv_bfloat16*)(smc + MO_W0);
    __nv_bfloat16* wS1 = (__nv_bfloat16*)(smc + MO_W1);
    const uint32_t aSb = smem_u32(aS), aDb = smem_u32(aD);
    const int n = blockIdx.y, p0 = blockIdx.x * 128, tid = threadIdx.x;
    const int wid = tid >> 5, lane = tid & 31;
    const int warpM = wid >> 2, warpN = wid & 3;
    const int g = lane >> 2, tig = lane & 3;

    // weight staging: bf16 memcpy
    {
        const uint4* s0 = (const uint4*)g_Wb[0][n];
        const uint4* s1 = (const uint4*)g_Wb[1][n];
        for (int e = tid; e < (BS*WSTR)/8; e += 512) {
            ((uint4*)wS0)[e] = s0[e];
            ((uint4*)wS1)[e] = s1[e];
        }
    }
    // activation staging: pure copies of S/D rows (96 bf16 = 12 uint4 per row)
    {
        const __nv_bfloat16* gS = (const __nv_bfloat16*)g_A + (size_t)p0*CCH + n*BS;
        const __nv_bfloat16* gD = gS + (size_t)SLABN;
        for (int e = tid; e < 128*12; e += 512) {
            int p = e / 12, q = e - 12*p;
            *(uint4*)&aS[p*ASTR + q*8] = *(const uint4*)&gS[(size_t)p*CCH + q*8];
            *(uint4*)&aD[p*ASTR + q*8] = *(const uint4*)&gD[(size_t)p*CCH + q*8];
        }
    }
    __syncthreads();

    float U[2][3][4], V[2][3][4], keep[2][3][4];

    // ===== layer 1 =====
    mmaGemv(aSb, aDb, wS0, wS1, warpM, warpN, lane, g, tig, U, V);
    __syncthreads();
    #pragma unroll
    for (int mi = 0; mi < 2; mi++)
        #pragma unroll
        for (int ni = 0; ni < 3; ni++) {
            const int o = warpN*24 + ni*8 + 2*tig;
            const float bk0 = b1[n*BS + o],        bk1 = b1[n*BS + o + 1];
            const float bn0 = b1[(NB+n)*BS + o],   bn1 = b1[(NB+n)*BS + o + 1];
            const int p = warpM*32 + mi*16 + g;
            #pragma unroll
            for (int hh = 0; hh < 2; hh++) {
                float Uu0 = U[mi][ni][2*hh], Uu1 = U[mi][ni][2*hh+1];
                float Vv0 = V[mi][ni][2*hh], Vv1 = V[mi][ni][2*hh+1];
                float k0 = fmaxf(fmaf(0.5f, Uu0 + Vv0, bk0), 0.f);
                float n0 = fmaxf(fmaf(0.5f, Uu0 - Vv0, bn0), 0.f);
                float k1 = fmaxf(fmaf(0.5f, Uu1 + Vv1, bk1), 0.f);
                float n1 = fmaxf(fmaf(0.5f, Uu1 - Vv1, bn1), 0.f);
                keep[mi][ni][2*hh] = n0; keep[mi][ni][2*hh+1] = n1;
                const int pp = p + 8*hh;
                *(__nv_bfloat162*)&aS[pp*ASTR + o] = __floats2bfloat162_rn(k0 + n0, k1 + n1);
                *(__nv_bfloat162*)&aD[pp*ASTR + o] = __floats2bfloat162_rn(k0 - n0, k1 - n1);
            }
        }
    {
        const uint4* s0 = (const uint4*)g_Wb[2][n];
        const uint4* s1 = (const uint4*)g_Wb[3][n];
        for (int e = tid; e < (BS*WSTR)/8; e += 512) {
            ((uint4*)wS0)[e] = s0[e];
            ((uint4*)wS1)[e] = s1[e];
        }
    }
    __syncthreads();

    // ===== layer 2 (o2_k) =====
    mmaGemv(aSb, aDb, wS0, wS1, warpM, warpN, lane, g, tig, U, V);
    __syncthreads();
    #pragma unroll
    for (int mi = 0; mi < 2; mi++)
        #pragma unroll
        for (int ni = 0; ni < 3; ni++) {
            const int o = warpN*24 + ni*8 + 2*tig;
            const float bk0 = b2[n*BS + o], bk1 = b2[n*BS + o + 1];
            const int p = warpM*32 + mi*16 + g;
            #pragma unroll
            for (int hh = 0; hh < 2; hh++) {
                float ok0 = fmaf(0.5f, U[mi][ni][2*hh]   + V[mi][ni][2*hh],   bk0);
                float ok1 = fmaf(0.5f, U[mi][ni][2*hh+1] + V[mi][ni][2*hh+1], bk1);
                float un0 = keep[mi][ni][2*hh], un1 = keep[mi][ni][2*hh+1];
                keep[mi][ni][2*hh] = ok0; keep[mi][ni][2*hh+1] = ok1;
                const int pp = p + 8*hh;
                *(__nv_bfloat162*)&aS[pp*ASTR + o] = __floats2bfloat162_rn(un0 + ok0, un1 + ok1);
                *(__nv_bfloat162*)&aD[pp*ASTR + o] = __floats2bfloat162_rn(un0 - ok0, un1 - ok1);  // o2_nk uses o2_k
            }
        }
    __syncthreads();

    // ===== layer 2 (o2_nk) + soft-threshold =====
    mmaGemv(aSb, aDb, wS0, wS1, warpM, warpN, lane, g, tig, U, V);
    __syncthreads();
    float* sOut = (float*)(smc + MO_AS);
    #pragma unroll
    for (int mi = 0; mi < 2; mi++)
        #pragma unroll
        for (int ni = 0; ni < 3; ni++) {
            const int o = warpN*24 + ni*8 + 2*tig;
            const float bn0 = b2[(NB+n)*BS + o], bn1 = b2[(NB+n)*BS + o + 1];
            const int p = warpM*32 + mi*16 + g;
            #pragma unroll
            for (int hh = 0; hh < 2; hh++) {
                float o2n0 = fmaf(0.5f, U[mi][ni][2*hh]   + V[mi][ni][2*hh],   bn0);
                float o2n1 = fmaf(0.5f, U[mi][ni][2*hh+1] + V[mi][ni][2*hh+1], bn1);
                float t0 = keep[mi][ni][2*hh]   + o2n0;
                float t1 = keep[mi][ni][2*hh+1] + o2n1;
                const int pp = p + 8*hh;
                sOut[o*SOP + pp]     = copysignf(fmaxf(fabsf(t0) - 0.01f, 0.f), t0);
                sOut[(o+1)*SOP + pp] = copysignf(fmaxf(fabsf(t1) - 0.01f, 0.f), t1);
            }
        }
    __syncthreads();
    __nv_bfloat16* outp = (__nv_bfloat16*)g_B;
    for (int e = tid; e < 12288; e += 512) {
        int p = e / 96, c = e - 96*p;
        outp[(size_t)(p0 + p)*CCH + n*BS + c] = __float2bfloat16(sOut[c*SOP + p]);
    }
}

// ---------------- inverse W-FFT (65 -> 256) + scale + residual : g_B -> out ----------------
__global__ __launch_bounds__(256) void kIW(const float* __restrict__ x, float* __restrict__ out)
{
    __shared__ float2 Zs[KWV*16];
    __shared__ float2 Ys[256*17];
    __shared__ float2 stw[256];
    const int bh = blockIdx.x, c0 = blockIdx.y * 16, tid = threadIdx.x;
    if (tid < 256) stw[tid] = g_tw256[tid];
    const cbf* __restrict__ zp = g_B + (size_t)bh*KWV*CCH + c0;
    for (int e = tid; e < KWV*16; e += 256) {
        int w = e >> 4, c = e & 15;
        Zs[e] = b2f(zp[(size_t)w*CCH + c]);
    }
    __syncthreads();
    for (int e = tid; e < 4096; e += 256) {
        int c = e & 15, n2 = (e >> 4) & 15, k1 = e >> 8;
        float2 acc = make_float2(0.f, 0.f);
        int idx = (k1 * n2) & 255, step = (k1 * 16) & 255;
        int nmax = (n2 == 0) ? 5 : 4;
        for (int n1 = 0; n1 < nmax; n1++) {
            int w = (n1 << 4) + n2;
            cmadd(acc, Zs[w*16 + c], stw[idx]);
            idx = (idx + step) & 255;
        }
        Ys[(k1*16 + n2)*17 + c] = acc;
    }
    __syncthreads();
    const float invN = 1.0f / 50331648.0f;
    {
        const int k1 = tid >> 4, c = tid & 15;
        float2 v[16];
        #pragma unroll
        for (int n2 = 0; n2 < 16; n2++) v[n2] = Ys[(k1*16 + n2)*17 + c];
        fft16r(v);
        #pragma unroll
        for (int k2 = 0; k2 < 16; k2++) {
            float2 acc = v[FFI(k2)];
            size_t a = ((size_t)bh*WW + k1 + 16*k2)*CCH + c0 + c;
            out[a] = fmaf(acc.x + acc.y, invN, x[a]);
        }
    }
}

extern "C" void kernel_launch(void* const* d_in, const int* in_sizes, int n_in,
                              void* d_out, int out_size)
{
    const float* x  = (const float*)d_in[0];
    const float* w1 = (const float*)d_in[1];
    const float* b1 = (const float*)d_in[2];
    const float* w2 = (const float*)d_in[3];
    const float* b2 = (const float*)d_in[4];
    float* out = (float*)d_out;

    cudaFuncSetAttribute(kMLP,   cudaFuncAttributeMaxDynamicSharedMemorySize, MSM);
    cudaFuncSetAttribute(kF1,    cudaFuncAttributeMaxDynamicSharedMemorySize, 54272);
    cudaFuncSetAttribute(kFC<0>, cudaFuncAttributeMaxDynamicSharedMemorySize, 43008);
    cudaFuncSetAttribute(kFC<1>, cudaFuncAttributeMaxDynamicSharedMemorySize, 43008);

    kPrep<<<290, 1024>>>(w1, w2);
    kF1 <<<dim3(BB*HH, CCH/16), 256, 54272>>>(x);   // x -> A (cplx) + C (an)
    kFC<0><<<NPOS/4, 192, 43008>>>();               // A -> B
    kFHB<1><<<dim3(KWV, CCH/16), 256>>>();          // B (+C) -> S/D in A
    kMLP<<<dim3(NPOS/128, NB), 512, MSM>>>(b1, b2); // A(S/D) -> s(bf16) in B
    kFC<1><<<NPOS/4, 192, 43008>>>();               // B(real bf16) -> A
    kFHB<0><<<dim3(KWV, CCH/16), 256>>>();          // A -> B
    kIW <<<dim3(BB*HH, CCH/16), 256>>>(x, out);     // B -> out
}